// round 6
// baseline (speedup 1.0000x reference)
#include <cuda_runtime.h>
#include <math.h>
#include <stdint.h>

// ---------------- problem constants ----------------
#define Bc   2
#define Sc   1024
#define Hc   1024
#define Ic   2048
#define Nst  16
#define Rc   64
#define Kcv  4
#define NHc  16
#define NKVc 4
#define HDc  64
#define WATT 512
#define WSSM 128
#define IMc  2816
#define Mrows (Bc*Sc)        // 2048
#define EPSc  1e-6f
#define PROJW (Rc + 2*Nst)   // 96
#define FUSN  5632           // xz(4096)|q(1024)|katt(256)|vatt(256)
#define KVSLD 512            // kssm(256)|vssm(256)
#define GATEN 5632           // interleaved gate|val pairs

// ---------------- scratch ----------------
__device__ float g_hs[Mrows*Hc];
__device__ float g_xzq[Mrows*FUSN];
__device__ float g_xs[Mrows*Ic];
__device__ float g_xst[Mrows*Ic];
__device__ float g_proj[Mrows*PROJW];
__device__ float g_dt[Mrows*Ic];
__device__ float g_y[Mrows*Ic];
__device__ float g_tmp[Mrows*Hc];
__device__ float g_ssmres[Mrows*Hc];
__device__ float g_ssmst[Mrows*Hc];
__device__ float g_kvssm[Mrows*KVSLD];
__device__ float g_o[Mrows*NHc*HDc];
__device__ float g_mlpres[Mrows*Hc];
__device__ float g_x2[Mrows*Hc];
__device__ float g_hm[Mrows*IMc];
// tf32-rounded weights
__device__ float g_wbig[FUSN*Hc];
__device__ float g_wxp[PROJW*Ic];
__device__ float g_wdt[Ic*Rc];
__device__ float g_wop[Hc*Ic];
__device__ float g_wkv[KVSLD*Hc];
__device__ float g_wo[Hc*NHc*HDc];
__device__ float g_wg[GATEN*Hc];   // interleaved
__device__ float g_wd[Hc*IMc];

__device__ __forceinline__ float sigmoidf_(float x) { return 1.f / (1.f + expf(-x)); }
__device__ __forceinline__ uint32_t f2tf32(float x) {
    uint32_t u; asm("cvt.rna.tf32.f32 %0, %1;" : "=r"(u) : "f"(x)); return u;
}
__device__ __forceinline__ float roundtf(float x) { return __uint_as_float(f2tf32(x)); }

// ---------------- tf32 MMA GEMM, 5-stage cp.async pipeline ----------------
// C[m,n] = sum_k A[m,k]*B[n,k];  BM=128, BNT in {128,64}, BK=16, 256 threads.
#define BM 128
#define BK 16
#define PADK 20
#define STAGES 5

// epilogue ops
#define OP_NONE   0
#define OP_ROUND  1
#define OP_SPLUS  2   // softplus(acc + aux[col])
#define OP_SWIGLU 3   // paired cols -> silu(g)*v, rounded, ld=IMc
#define OP_ADDC   4   // acc + aux[r*Ndim+c]

__device__ __forceinline__ void cp16(uint32_t dst, const float* src, int ssize) {
    asm volatile("cp.async.cg.shared.global [%0], [%1], 16, %2;\n"
                 :: "r"(dst), "l"(src), "r"(ssize));
}
__device__ __forceinline__ void mma_tf32(float* c, const uint32_t* a, uint32_t b0, uint32_t b1) {
    asm volatile("mma.sync.aligned.m16n8k8.row.col.f32.tf32.tf32.f32 "
                 "{%0,%1,%2,%3}, {%4,%5,%6,%7}, {%8,%9}, {%0,%1,%2,%3};\n"
                 : "+f"(c[0]), "+f"(c[1]), "+f"(c[2]), "+f"(c[3])
                 : "r"(a[0]), "r"(a[1]), "r"(a[2]), "r"(a[3]), "r"(b0), "r"(b1));
}

template<int BNT, int OP, bool NG>
__global__ __launch_bounds__(256, 2)
void gemm_t(const float* __restrict__ A, const float* __restrict__ Bw,
            float* __restrict__ C, const float* __restrict__ aux,
            int Ndim, int Kdim, int lda, int ldb) {
    constexpr int NI  = BNT / 16;
    constexpr int ASZ = BM * PADK;          // 2560 floats
    constexpr int BSZ = BNT * PADK;
    constexpr int STG = ASZ + BSZ;
    extern __shared__ float sm[];
    const int t    = threadIdx.x;
    const int bm   = blockIdx.y * BM;
    const int bn   = blockIdx.x * BNT;
    const int warp = t >> 5, lane = t & 31;
    const int wm   = (warp & 3) * 32;
    const int wn   = (warp >> 2) * (BNT / 2);
    const int gid  = lane >> 2;
    const int tig  = lane & 3;
    const uint32_t smem_base = (uint32_t)__cvta_generic_to_shared(sm);

    float acc[2][NI][4];
#pragma unroll
    for (int mi = 0; mi < 2; mi++)
#pragma unroll
        for (int ni = 0; ni < NI; ni++)
#pragma unroll
            for (int j = 0; j < 4; j++) acc[mi][ni][j] = 0.f;

    const int niters = Kdim / BK;

    auto load_tile = [&](int slot, int k0) {
        uint32_t aOff = smem_base + slot * STG * 4;
        uint32_t bOff = aOff + ASZ * 4;
        // A: 128 rows x 4 float4 = 512 -> 2 per thread
#pragma unroll
        for (int i = 0; i < 2; i++) {
            int id = t + i * 256;
            int r  = id >> 2;
            int kq = (id & 3) * 4;
            cp16(aOff + (r * PADK + kq) * 4, A + (size_t)(bm + r) * lda + k0 + kq, 16);
        }
        // B: BNT rows x 4 float4
#pragma unroll
        for (int i = 0; i < BNT / 64; i++) {
            int id = t + i * 256;
            int r  = id >> 2;
            int kq = (id & 3) * 4;
            int ok = 1;
            int br = bn + r;
            if (NG) ok = (br < Ndim);
            cp16(bOff + (r * PADK + kq) * 4,
                 Bw + (size_t)(NG ? (ok ? br : 0) : br) * ldb + k0 + kq, ok ? 16 : 0);
        }
    };

    // prologue: stages 0..STAGES-2
#pragma unroll
    for (int s = 0; s < STAGES - 1; s++) {
        if (s < niters) load_tile(s, s * BK);
        asm volatile("cp.async.commit_group;\n");
    }

    int cslot = 0, nslot = STAGES - 1;
    for (int it = 0; it < niters; it++) {
        asm volatile("cp.async.wait_group %0;\n" :: "n"(STAGES - 2));
        __syncthreads();
        int nk = it + STAGES - 1;
        if (nk < niters) load_tile(nslot, nk * BK);
        asm volatile("cp.async.commit_group;\n");
        if (++nslot == STAGES) nslot = 0;

        const float* Ab = sm + cslot * STG;
        const float* Bb = Ab + ASZ;
        if (++cslot == STAGES) cslot = 0;
#pragma unroll
        for (int kk = 0; kk < 2; kk++) {
            int kb = kk * 8;
            uint32_t afr[2][4];
#pragma unroll
            for (int mi = 0; mi < 2; mi++) {
                const float* ab = Ab + (wm + mi * 16 + gid) * PADK + kb + tig;
                afr[mi][0] = __float_as_uint(ab[0]);
                afr[mi][1] = __float_as_uint(ab[8 * PADK]);
                afr[mi][2] = __float_as_uint(ab[4]);
                afr[mi][3] = __float_as_uint(ab[8 * PADK + 4]);
            }
#pragma unroll
            for (int ni = 0; ni < NI; ni++) {
                const float* bb = Bb + (wn + ni * 8 + gid) * PADK + kb + tig;
                uint32_t b0 = __float_as_uint(bb[0]);
                uint32_t b1 = __float_as_uint(bb[4]);
#pragma unroll
                for (int mi = 0; mi < 2; mi++)
                    mma_tf32(acc[mi][ni], afr[mi], b0, b1);
            }
        }
    }

    // ---------------- epilogue ----------------
#pragma unroll
    for (int mi = 0; mi < 2; mi++) {
        int rbase = bm + wm + mi * 16 + gid;
#pragma unroll
        for (int ni = 0; ni < NI; ni++) {
            int c0 = bn + wn + ni * 8 + tig * 2;
            if (NG && c0 >= Ndim) continue;
#pragma unroll
            for (int half = 0; half < 2; half++) {
                int r0 = rbase + half * 8;
                float a0 = acc[mi][ni][half * 2 + 0];
                float a1 = acc[mi][ni][half * 2 + 1];
                if (OP == OP_NONE) {
                    *(float2*)(C + (size_t)r0 * Ndim + c0) = make_float2(a0, a1);
                } else if (OP == OP_ROUND) {
                    *(float2*)(C + (size_t)r0 * Ndim + c0) =
                        make_float2(roundtf(a0), roundtf(a1));
                } else if (OP == OP_SPLUS) {
                    float x0 = a0 + aux[c0], x1 = a1 + aux[c0 + 1];
                    x0 = (x0 > 20.f) ? x0 : log1pf(expf(x0));
                    x1 = (x1 > 20.f) ? x1 : log1pf(expf(x1));
                    *(float2*)(C + (size_t)r0 * Ndim + c0) = make_float2(x0, x1);
                } else if (OP == OP_SWIGLU) {
                    // a0 = gate, a1 = val for feature c0/2
                    float sv = a0 * sigmoidf_(a0) * a1;
                    C[(size_t)r0 * IMc + (c0 >> 1)] = roundtf(sv);
                } else if (OP == OP_ADDC) {
                    float2 r = *(const float2*)(aux + (size_t)r0 * Ndim + c0);
                    *(float2*)(C + (size_t)r0 * Ndim + c0) =
                        make_float2(a0 + r.x, a1 + r.y);
                }
            }
        }
    }
}

// ---------------- weight prep ----------------
__global__ void round_copy(float* __restrict__ dst, const float* __restrict__ src, int n) {
    int idx = blockIdx.x * 256 + threadIdx.x;
    if (idx < n) dst[idx] = roundtf(src[idx]);
}
__global__ void round_concat_big(const float* __restrict__ ipw, const float* __restrict__ qw,
                                 const float* __restrict__ kw, const float* __restrict__ vw) {
    int idx = blockIdx.x * 256 + threadIdx.x;
    if (idx >= FUSN * Hc) return;
    int row = idx >> 10, col = idx & 1023;
    float v;
    if (row < 4096)      v = ipw[idx];
    else if (row < 5120) v = qw[(row - 4096) * Hc + col];
    else if (row < 5376) v = kw[(row - 5120) * Hc + col];
    else                 v = vw[(row - 5376) * Hc + col];
    g_wbig[idx] = roundtf(v);
}
__global__ void round_concat_kv(const float* __restrict__ kw, const float* __restrict__ vw) {
    int idx = blockIdx.x * 256 + threadIdx.x;
    if (idx >= KVSLD * Hc) return;
    int row = idx >> 10, col = idx & 1023;
    float v = (row < 256) ? kw[row * Hc + col] : vw[(row - 256) * Hc + col];
    g_wkv[idx] = roundtf(v);
}
// interleave gate_w rows: out row 2f = gate feature f, 2f+1 = val feature f
__global__ void round_permute_gate(const float* __restrict__ gw) {
    int idx = blockIdx.x * 256 + threadIdx.x;
    if (idx >= GATEN * Hc) return;
    int row = idx >> 10, col = idx & 1023;
    int f = row >> 1;
    int src = (row & 1) ? (IMc + f) : f;
    g_wg[idx] = roundtf(gw[src * Hc + col]);
}

// ---------------- RMSNorm (+optional residual); nrm output tf32-rounded ----------------
__global__ void resid_rms(const float* __restrict__ a, const float* __restrict__ r,
                          const float* __restrict__ w, float* __restrict__ res_out,
                          float* __restrict__ nrm_out) {
    int row = blockIdx.x;
    int t   = threadIdx.x;
    const float* ap = a + (size_t)row * Hc;
    const float* rp = r ? r + (size_t)row * Hc : nullptr;
    float v[4];
    float ss = 0.f;
#pragma unroll
    for (int i = 0; i < 4; i++) {
        int c = t + i * 256;
        float x = ap[c] + (rp ? rp[c] : 0.f);
        v[i] = x;
        ss += x * x;
    }
#pragma unroll
    for (int off = 16; off; off >>= 1) ss += __shfl_xor_sync(0xffffffffu, ss, off);
    __shared__ float sred[8];
    __shared__ float sscale;
    if ((t & 31) == 0) sred[t >> 5] = ss;
    __syncthreads();
    if (t == 0) {
        float tot = 0.f;
        for (int i = 0; i < 8; i++) tot += sred[i];
        sscale = rsqrtf(tot * (1.f / Hc) + EPSc);
    }
    __syncthreads();
    float scale = sscale;
    float* ro = res_out ? res_out + (size_t)row * Hc : nullptr;
    float* no = nrm_out + (size_t)row * Hc;
#pragma unroll
    for (int i = 0; i < 4; i++) {
        int c = t + i * 256;
        if (ro) ro[c] = v[i];
        no[c] = roundtf(v[i] * scale * w[c]);
    }
}

// ---------------- causal depthwise conv (K=4) + SiLU ----------------
__global__ void conv_silu(const float* __restrict__ cw, const float* __restrict__ cb) {
    int idx = blockIdx.x * blockDim.x + threadIdx.x;
    if (idx >= Mrows * Ic) return;
    int row = idx / Ic;
    int i   = idx - row * Ic;
    int b   = row / Sc;
    int s   = row - b * Sc;
    float acc = cb[i];
#pragma unroll
    for (int k = 0; k < Kcv; k++) {
        int sp = s + k - (Kcv - 1);
        if (sp >= 0)
            acc += cw[i * Kcv + k] * g_xzq[(size_t)(b * Sc + sp) * FUSN + i];
    }
    float r = acc * sigmoidf_(acc);
    g_xs[idx]  = r;
    g_xst[idx] = roundtf(r);
}

// ---------------- selective scan (y output tf32-rounded) ----------------
__global__ void scan_kernel(const float* __restrict__ A_log, const float* __restrict__ Dp) {
    int t  = threadIdx.x;
    int c  = t >> 4;
    int n  = t & 15;
    int gi = blockIdx.x * 16 + c;
    int b  = gi / Ic;
    int i  = gi - b * Ic;
    float An = -expf(A_log[i * Nst + n]);
    float Dv = Dp[i];
    float h  = 0.f;
    for (int s = 0; s < Sc; s++) {
        int row = b * Sc + s;
        float dt = g_dt[(size_t)row * Ic + i];
        float xs = g_xs[(size_t)row * Ic + i];
        float Bn = g_proj[row * PROJW + Rc + n];
        float Cn = g_proj[row * PROJW + Rc + Nst + n];
        h = h * expf(dt * An) + dt * Bn * xs;
        float v = h * Cn;
        v += __shfl_xor_sync(0xffffffffu, v, 8);
        v += __shfl_xor_sync(0xffffffffu, v, 4);
        v += __shfl_xor_sync(0xffffffffu, v, 2);
        v += __shfl_xor_sync(0xffffffffu, v, 1);
        if (n == 0) {
            float z  = g_xzq[(size_t)row * FUSN + Ic + i];
            float yv = (v + Dv * xs) * (z * sigmoidf_(z));
            g_y[(size_t)row * Ic + i] = roundtf(yv);
        }
    }
}

// ---------------- rotary (in-place, strided view) ----------------
__global__ void rotary_kernel(float* __restrict__ p, int ld, int coloff, int nheads) {
    int idx = blockIdx.x * blockDim.x + threadIdx.x;
    int tot = Mrows * nheads * 32;
    if (idx >= tot) return;
    int r    = idx / (nheads * 32);
    int rem  = idx - r * (nheads * 32);
    int head = rem >> 5;
    int j    = rem & 31;
    int s    = r % Sc;
    float inv = expf(-((float)(2 * j) / (float)HDc) * logf(10000.0f));
    float f = (float)s * inv;
    float sn, cs;
    sincosf(f, &sn, &cs);
    float* base = p + (size_t)r * ld + coloff + head * HDc;
    float x1 = base[j], x2 = base[j + 32];
    base[j]      = x1 * cs - x2 * sn;
    base[j + 32] = x2 * cs + x1 * sn;
}

// ---------------- dual-window attention: smem key/value tiles ----------------
__global__ __launch_bounds__(256) void attn2() {
    __shared__ float sc[8][WATT + WSSM];
    __shared__ float tile[64][65];
    __shared__ float qs[8][64];
    int t    = threadIdx.x;
    int w    = t >> 5;
    int lane = t & 31;
    int q0   = blockIdx.x * 8;
    int h    = blockIdx.y;
    int b    = blockIdx.z;
    int rowb = b * Sc;
    int qi   = q0 + w;
    int hk   = h >> 2;

    const float* qp = g_xzq + (size_t)(rowb + qi) * FUSN + 4096 + h * HDc;
    qs[w][lane]      = qp[lane];
    qs[w][lane + 32] = qp[lane + 32];

    int ka = max(0, qi - (WATT - 1)), na = qi - ka + 1;
    int ks = max(0, qi - (WSSM - 1)), ns = qi - ks + 1;
    int caStart = max(0, q0 - (WATT - 1)) & ~63;
    int csStart = max(0, q0 - (WSSM - 1)) & ~63;

    for (int c = caStart; c <= q0 + 7; c += 64) {
        __syncthreads();
#pragma unroll
        for (int i = 0; i < 4; i++) {
            int id = t + i * 256;
            int r  = id >> 4;
            int d4 = (id & 15) * 4;
            int key = c + r;
            float4 v = make_float4(0.f, 0.f, 0.f, 0.f);
            if (key < Sc)
                v = *(const float4*)(g_xzq + (size_t)(rowb + key) * FUSN + 5120 + hk * HDc + d4);
            tile[d4][r] = v.x; tile[d4 + 1][r] = v.y;
            tile[d4 + 2][r] = v.z; tile[d4 + 3][r] = v.w;
        }
        __syncthreads();
        float a0 = 0.f, a1 = 0.f;
#pragma unroll 8
        for (int d = 0; d < 64; d++) {
            float qd = qs[w][d];
            a0 = fmaf(qd, tile[d][lane], a0);
            a1 = fmaf(qd, tile[d][lane + 32], a1);
        }
        int k0 = c + lane, k1 = c + lane + 32;
        if (k0 >= ka && k0 <= qi) sc[w][k0 - ka] = a0 * 0.125f;
        if (k1 >= ka && k1 <= qi) sc[w][k1 - ka] = a1 * 0.125f;
    }
    for (int c = csStart; c <= q0 + 7; c += 64) {
        __syncthreads();
#pragma unroll
        for (int i = 0; i < 4; i++) {
            int id = t + i * 256;
            int r  = id >> 4;
            int d4 = (id & 15) * 4;
            int key = c + r;
            float4 v = make_float4(0.f, 0.f, 0.f, 0.f);
            if (key < Sc)
                v = *(const float4*)(g_kvssm + (size_t)(rowb + key) * KVSLD + hk * HDc + d4);
            tile[d4][r] = v.x; tile[d4 + 1][r] = v.y;
            tile[d4 + 2][r] = v.z; tile[d4 + 3][r] = v.w;
        }
        __syncthreads();
        float a0 = 0.f, a1 = 0.f;
#pragma unroll 8
        for (int d = 0; d < 64; d++) {
            float qd = qs[w][d];
            a0 = fmaf(qd, tile[d][lane], a0);
            a1 = fmaf(qd, tile[d][lane + 32], a1);
        }
        int k0 = c + lane, k1 = c + lane + 32;
        if (k0 >= ks && k0 <= qi) sc[w][WATT + k0 - ks] = a0 * 0.125f;
        if (k1 >= ks && k1 <= qi) sc[w][WATT + k1 - ks] = a1 * 0.125f;
    }
    __syncwarp();

    float mx = -1e30f;
    for (int j = lane; j < na; j += 32) mx = fmaxf(mx, sc[w][j]);
    for (int j = lane; j < ns; j += 32) mx = fmaxf(mx, sc[w][WATT + j]);
#pragma unroll
    for (int off = 16; off; off >>= 1) mx = fmaxf(mx, __shfl_xor_sync(0xffffffffu, mx, off));
    float sum = 0.f;
    for (int j = lane; j < na; j += 32) { float e = expf(sc[w][j] - mx); sc[w][j] = e; sum += e; }
    for (int j = lane; j < ns; j += 32) { float e = expf(sc[w][WATT + j] - mx); sc[w][WATT + j] = e; sum += e; }
#pragma unroll
    for (int off = 16; off; off >>= 1) sum += __shfl_xor_sync(0xffffffffu, sum, off);
    float invs = 1.f / sum;
    __syncwarp();

    float o0 = 0.f, o1 = 0.f;
    for (int c = caStart; c <= q0 + 7; c += 64) {
        __syncthreads();
#pragma unroll
        for (int i = 0; i < 4; i++) {
            int id = t + i * 256;
            int r  = id >> 4;
            int d4 = (id & 15) * 4;
            int key = c + r;
            float4 v = make_float4(0.f, 0.f, 0.f, 0.f);
            if (key < Sc)
                v = *(const float4*)(g_xzq + (size_t)(rowb + key) * FUSN + 5376 + hk * HDc + d4);
            tile[r][d4] = v.x; tile[r][d4 + 1] = v.y;
            tile[r][d4 + 2] = v.z; tile[r][d4 + 3] = v.w;
        }
        __syncthreads();
#pragma unroll 4
        for (int j = 0; j < 64; j++) {
            int key = c + j;
            float p = (key >= ka && key <= qi) ? sc[w][key - ka] : 0.f;
            o0 = fmaf(p, tile[j][lane], o0);
            o1 = fmaf(p, tile[j][lane + 32], o1);
        }
    }
    for (int c = csStart; c <= q0 + 7; c += 64) {
        __syncthreads();
#pragma unroll
        for (int i = 0; i < 4; i++) {
            int id = t + i * 256;
            int r  = id >> 4;
            int d4 = (id & 15) * 4;
            int key = c + r;
            float4 v = make_float4(0.f, 0.f, 0.f, 0.f);
            if (key < Sc)
                v = *(const float4*)(g_kvssm + (size_t)(rowb + key) * KVSLD + 256 + hk * HDc + d4);
            tile[r][d4] = v.x; tile[r][d4 + 1] = v.y;
            tile[r][d4 + 2] = v.z; tile[r][d4 + 3] = v.w;
        }
        __syncthreads();
#pragma unroll 4
        for (int j = 0; j < 64; j++) {
            int key = c + j;
            float p = (key >= ks && key <= qi) ? sc[w][WATT + key - ks] : 0.f;
            o0 = fmaf(p, tile[j][lane], o0);
            o1 = fmaf(p, tile[j][lane + 32], o1);
        }
    }

    float* op = g_o + (size_t)(rowb + qi) * NHc * HDc + h * HDc;
    op[lane]      = roundtf(o0 * invs);
    op[lane + 32] = roundtf(o1 * invs);
}

// ---------------- host launcher ----------------
extern "C" void kernel_launch(void* const* d_in, const int* in_sizes, int n_in,
                              void* d_out, int out_size) {
    const float* hidden      = (const float*)d_in[0];
    const float* pre_norm_w  = (const float*)d_in[1];
    const float* in_proj_w   = (const float*)d_in[2];
    const float* conv_w      = (const float*)d_in[3];
    const float* conv_b      = (const float*)d_in[4];
    const float* x_proj_w    = (const float*)d_in[5];
    const float* dt_proj_w   = (const float*)d_in[6];
    const float* dt_proj_b   = (const float*)d_in[7];
    const float* A_log       = (const float*)d_in[8];
    const float* Dp          = (const float*)d_in[9];
    const float* out_proj_w  = (const float*)d_in[10];
    const float* ssm_norm_w  = (const float*)d_in[11];
    const float* q_w         = (const float*)d_in[12];
    const float* k_w         = (const float*)d_in[13];
    const float* v_w         = (const float*)d_in[14];
    const float* o_w         = (const float*)d_in[15];
    const float* mlp_norm_w  = (const float*)d_in[16];
    const float* gate_w      = (const float*)d_in[17];
    const float* down_w      = (const float*)d_in[18];
    float* out = (float*)d_out;

    const int smem128 = (BM * PADK + 128 * PADK) * STAGES * 4;  // 102400
    const int smem64  = (BM * PADK + 64 * PADK) * STAGES * 4;   // 76800
    cudaFuncSetAttribute(gemm_t<128, OP_NONE,  false>, cudaFuncAttributeMaxDynamicSharedMemorySize, smem128);
    cudaFuncSetAttribute(gemm_t<128, OP_SPLUS, false>, cudaFuncAttributeMaxDynamicSharedMemorySize, smem128);
    cudaFuncSetAttribute(gemm_t<128, OP_SWIGLU,false>, cudaFuncAttributeMaxDynamicSharedMemorySize, smem128);
    cudaFuncSetAttribute(gemm_t<64,  OP_ROUND, true >, cudaFuncAttributeMaxDynamicSharedMemorySize, smem64);
    cudaFuncSetAttribute(gemm_t<64,  OP_NONE,  false>, cudaFuncAttributeMaxDynamicSharedMemorySize, smem64);
    cudaFuncSetAttribute(gemm_t<64,  OP_ADDC,  false>, cudaFuncAttributeMaxDynamicSharedMemorySize, smem64);

    float *hs, *xzq, *xst, *proj, *dt, *y, *tmp, *ssmres, *ssmst;
    float *kvssm, *o, *mlpres, *x2, *hm;
    float *wbig, *wxp, *wdt, *wop, *wkv, *wo, *wg, *wd;
    cudaGetSymbolAddress((void**)&hs, g_hs);
    cudaGetSymbolAddress((void**)&xzq, g_xzq);
    cudaGetSymbolAddress((void**)&xst, g_xst);
    cudaGetSymbolAddress((void**)&proj, g_proj);
    cudaGetSymbolAddress((void**)&dt, g_dt);
    cudaGetSymbolAddress((void**)&y, g_y);
    cudaGetSymbolAddress((void**)&tmp, g_tmp);
    cudaGetSymbolAddress((void**)&ssmres, g_ssmres);
    cudaGetSymbolAddress((void**)&ssmst, g_ssmst);
    cudaGetSymbolAddress((void**)&kvssm, g_kvssm);
    cudaGetSymbolAddress((void**)&o, g_o);
    cudaGetSymbolAddress((void**)&mlpres, g_mlpres);
    cudaGetSymbolAddress((void**)&x2, g_x2);
    cudaGetSymbolAddress((void**)&hm, g_hm);
    cudaGetSymbolAddress((void**)&wbig, g_wbig);
    cudaGetSymbolAddress((void**)&wxp, g_wxp);
    cudaGetSymbolAddress((void**)&wdt, g_wdt);
    cudaGetSymbolAddress((void**)&wop, g_wop);
    cudaGetSymbolAddress((void**)&wkv, g_wkv);
    cudaGetSymbolAddress((void**)&wo, g_wo);
    cudaGetSymbolAddress((void**)&wg, g_wg);
    cudaGetSymbolAddress((void**)&wd, g_wd);

    // 0. weight prep
    round_concat_big<<<(FUSN * Hc + 255) / 256, 256>>>(in_proj_w, q_w, k_w, v_w);
    round_concat_kv<<<(KVSLD * Hc + 255) / 256, 256>>>(k_w, v_w);
    round_permute_gate<<<(GATEN * Hc + 255) / 256, 256>>>(gate_w);
    round_copy<<<(PROJW * Ic + 255) / 256, 256>>>(wxp, x_proj_w, PROJW * Ic);
    round_copy<<<(Ic * Rc + 255) / 256, 256>>>(wdt, dt_proj_w, Ic * Rc);
    round_copy<<<(Hc * Ic + 255) / 256, 256>>>(wop, out_proj_w, Hc * Ic);
    round_copy<<<(Hc * NHc * HDc + 255) / 256, 256>>>(wo, o_w, Hc * NHc * HDc);
    round_copy<<<(Hc * IMc + 255) / 256, 256>>>(wd, down_w, Hc * IMc);

    // 1. pre-norm
    resid_rms<<<Mrows, 256>>>(hidden, nullptr, pre_norm_w, nullptr, hs);
    // 2. fused xz|q|k|v (2048 x 5632, K=1024)
    gemm_t<128, OP_NONE, false><<<dim3(FUSN / 128, Mrows / BM), 256, smem128>>>(
        hs, wbig, xzq, nullptr, FUSN, Hc, Hc, Hc);
    // 3. conv + silu
    conv_silu<<<(Mrows * Ic) / 256, 256>>>(conv_w, conv_b);
    // 4. x_proj (2048 x 96, K=2048), rounded output
    gemm_t<64, OP_ROUND, true><<<dim3(2, Mrows / BM), 256, smem64>>>(
        xst, wxp, proj, nullptr, PROJW, Ic, Ic, Ic);
    // 5. dt = softplus(proj[:, :64] @ dt_w^T + bias)  (2048 x 2048, K=64)
    gemm_t<128, OP_SPLUS, false><<<dim3(Ic / 128, Mrows / BM), 256, smem128>>>(
        proj, wdt, dt, dt_proj_b, Ic, Rc, PROJW, Rc);
    // 6. selective scan
    scan_kernel<<<(Bc * Ic) / 16, 256>>>(A_log, Dp);
    // 7. out_proj (2048 x 1024, K=2048); residual + norm
    gemm_t<64, OP_NONE, false><<<dim3(Hc / 64, Mrows / BM), 256, smem64>>>(
        y, wop, tmp, nullptr, Hc, Ic, Ic, Ic);
    resid_rms<<<Mrows, 256>>>(tmp, hidden, ssm_norm_w, ssmres, ssmst);
    // 8. kv_ssm (2048 x 512, K=1024)
    gemm_t<64, OP_NONE, false><<<dim3(KVSLD / 64, Mrows / BM), 256, smem64>>>(
        ssmst, wkv, kvssm, nullptr, KVSLD, Hc, Hc, Hc);
    // 9. rotary
    rotary_kernel<<<(Mrows * NHc * 32) / 256, 256>>>(xzq, FUSN, 4096, NHc);
    rotary_kernel<<<(Mrows * NKVc * 32) / 256, 256>>>(xzq, FUSN, 5120, NKVc);
    rotary_kernel<<<(Mrows * NKVc * 32) / 256, 256>>>(kvssm, KVSLD, 0, NKVc);
    // 10. attention
    attn2<<<dim3(Sc / 8, NHc, Bc), 256>>>();
    // 11. o proj (2048 x 1024, K=1024); residual + norm
    gemm_t<64, OP_NONE, false><<<dim3(Hc / 64, Mrows / BM), 256, smem64>>>(
        o, wo, tmp, nullptr, Hc, NHc * HDc, NHc * HDc, NHc * HDc);
    resid_rms<<<Mrows, 256>>>(tmp, ssmres, mlp_norm_w, mlpres, x2);
    // 12. MLP: gate GEMM with fused swiglu -> hm; down GEMM with fused residual -> out
    gemm_t<128, OP_SWIGLU, false><<<dim3(GATEN / 128, Mrows / BM), 256, smem128>>>(
        x2, wg, hm, nullptr, GATEN, Hc, Hc, Hc);
    gemm_t<64, OP_ADDC, false><<<dim3(Hc / 64, Mrows / BM), 256, smem64>>>(
        hm, wd, out, mlpres, Hc, IMc, IMc, IMc);
}

// round 7
// speedup vs baseline: 1.0434x; 1.0434x over previous
#include <cuda_runtime.h>
#include <math.h>
#include <stdint.h>

// ---------------- problem constants ----------------
#define Bc   2
#define Sc   1024
#define Hc   1024
#define Ic   2048
#define Nst  16
#define Rc   64
#define Kcv  4
#define NHc  16
#define NKVc 4
#define HDc  64
#define WATT 512
#define WSSM 128
#define IMc  2816
#define Mrows (Bc*Sc)        // 2048
#define EPSc  1e-6f
#define PROJW (Rc + 2*Nst)   // 96
#define FUSN  5632           // xz(4096)|q(1024)|katt(256)|vatt(256)
#define KVSLD 512            // kssm(256)|vssm(256)
#define GATEN 5632           // interleaved gate|val pairs

// ---------------- scratch ----------------
__device__ float g_hs[Mrows*Hc];
__device__ float g_xzq[Mrows*FUSN];
__device__ float g_xs[Mrows*Ic];
__device__ float g_xst[Mrows*Ic];
__device__ float g_proj[Mrows*PROJW];
__device__ float g_dt[Mrows*Ic];
__device__ float g_y[Mrows*Ic];
__device__ float g_tmp[Mrows*Hc];
__device__ float g_ssmres[Mrows*Hc];
__device__ float g_ssmst[Mrows*Hc];
__device__ float g_kvssm[Mrows*KVSLD];
__device__ float g_o[Mrows*NHc*HDc];
__device__ float g_mlpres[Mrows*Hc];
__device__ float g_x2[Mrows*Hc];
__device__ float g_hm[Mrows*IMc];
// tf32-rounded weights
__device__ float g_wbig[FUSN*Hc];
__device__ float g_wxp[PROJW*Ic];
__device__ float g_wdt[Ic*Rc];
__device__ float g_wop[Hc*Ic];
__device__ float g_wkv[KVSLD*Hc];
__device__ float g_wo[Hc*NHc*HDc];
__device__ float g_wg[GATEN*Hc];   // interleaved
__device__ float g_wd[Hc*IMc];

__device__ __forceinline__ float sigmoidf_(float x) { return 1.f / (1.f + expf(-x)); }
__device__ __forceinline__ uint32_t f2tf32(float x) {
    uint32_t u; asm("cvt.rna.tf32.f32 %0, %1;" : "=r"(u) : "f"(x)); return u;
}
__device__ __forceinline__ float roundtf(float x) { return __uint_as_float(f2tf32(x)); }

// ---------------- tf32 MMA GEMM ----------------
// 128 threads, warp grid 2(M)x2(N), warp tile 64x64 (BNT=128) / 64x32 (BNT=64).
// BK=32, 3-stage cp.async ring.
#define BM 128
#define BK 32
#define PADS 36
#define STAGES 3

// epilogue ops
#define OP_NONE   0
#define OP_ROUND  1
#define OP_SPLUS  2   // softplus(acc + aux[col])
#define OP_SWIGLU 3   // paired cols -> silu(g)*v, rounded, ld=IMc
#define OP_ADDC   4   // acc + aux[r*Ndim+c]

__device__ __forceinline__ void cp16(uint32_t dst, const float* src, int ssize) {
    asm volatile("cp.async.cg.shared.global [%0], [%1], 16, %2;\n"
                 :: "r"(dst), "l"(src), "r"(ssize));
}
__device__ __forceinline__ void mma_tf32(float* c, const uint32_t* a, uint32_t b0, uint32_t b1) {
    asm volatile("mma.sync.aligned.m16n8k8.row.col.f32.tf32.tf32.f32 "
                 "{%0,%1,%2,%3}, {%4,%5,%6,%7}, {%8,%9}, {%0,%1,%2,%3};\n"
                 : "+f"(c[0]), "+f"(c[1]), "+f"(c[2]), "+f"(c[3])
                 : "r"(a[0]), "r"(a[1]), "r"(a[2]), "r"(a[3]), "r"(b0), "r"(b1));
}

template<int BNT, int OP, bool NG>
__global__ __launch_bounds__(128, 2)
void gemm_t(const float* __restrict__ A, const float* __restrict__ Bw,
            float* __restrict__ C, const float* __restrict__ aux,
            int Ndim, int Kdim, int lda, int ldb) {
    constexpr int NI  = BNT / 16;            // 8 or 4 n-tiles per warp
    constexpr int ASZ = BM * PADS;
    constexpr int BSZ = BNT * PADS;
    constexpr int STG = ASZ + BSZ;
    extern __shared__ float sm[];
    const int t    = threadIdx.x;
    const int bm   = blockIdx.y * BM;
    const int bn   = blockIdx.x * BNT;
    const int warp = t >> 5, lane = t & 31;
    const int wm   = (warp & 1) * 64;
    const int wn   = (warp >> 1) * (BNT / 2);
    const int gid  = lane >> 2;
    const int tig  = lane & 3;
    const uint32_t smem_base = (uint32_t)__cvta_generic_to_shared(sm);

    float acc[4][NI][4];
#pragma unroll
    for (int mi = 0; mi < 4; mi++)
#pragma unroll
        for (int ni = 0; ni < NI; ni++)
#pragma unroll
            for (int j = 0; j < 4; j++) acc[mi][ni][j] = 0.f;

    const int niters = Kdim / BK;

    auto load_tile = [&](int slot, int k0) {
        uint32_t aOff = smem_base + slot * STG * 4;
        uint32_t bOff = aOff + ASZ * 4;
        // A: 128 rows x 8 float4 = 1024 chunks -> 8 per thread
#pragma unroll
        for (int i = 0; i < 8; i++) {
            int id = t + i * 128;
            int r  = id >> 3;
            int kq = (id & 7) * 4;
            cp16(aOff + (r * PADS + kq) * 4, A + (size_t)(bm + r) * lda + k0 + kq, 16);
        }
        // B: BNT rows x 8 float4
#pragma unroll
        for (int i = 0; i < BNT / 16; i++) {
            int id = t + i * 128;
            int r  = id >> 3;
            int kq = (id & 7) * 4;
            int ok = 1;
            int br = bn + r;
            if (NG) ok = (br < Ndim);
            cp16(bOff + (r * PADS + kq) * 4,
                 Bw + (size_t)(NG ? (ok ? br : 0) : br) * ldb + k0 + kq, ok ? 16 : 0);
        }
    };

    // prologue: 2 stages
#pragma unroll
    for (int s = 0; s < STAGES - 1; s++) {
        if (s < niters) load_tile(s, s * BK);
        asm volatile("cp.async.commit_group;\n");
    }

    int cslot = 0, nslot = STAGES - 1;
    for (int it = 0; it < niters; it++) {
        asm volatile("cp.async.wait_group %0;\n" :: "n"(STAGES - 2));
        __syncthreads();          // stage `it` ready; all warps done with stage it-1
        int nk = it + STAGES - 1;
        if (nk < niters) load_tile(nslot, nk * BK);
        asm volatile("cp.async.commit_group;\n");
        if (++nslot == STAGES) nslot = 0;

        const float* Ab = sm + cslot * STG;
        const float* Bb = Ab + ASZ;
        if (++cslot == STAGES) cslot = 0;
#pragma unroll
        for (int kk = 0; kk < 4; kk++) {
            int kb = kk * 8;
            uint32_t afr[4][4];
#pragma unroll
            for (int mi = 0; mi < 4; mi++) {
                const float* ab = Ab + (wm + mi * 16 + gid) * PADS + kb + tig;
                afr[mi][0] = __float_as_uint(ab[0]);
                afr[mi][1] = __float_as_uint(ab[8 * PADS]);
                afr[mi][2] = __float_as_uint(ab[4]);
                afr[mi][3] = __float_as_uint(ab[8 * PADS + 4]);
            }
#pragma unroll
            for (int ni = 0; ni < NI; ni++) {
                const float* bb = Bb + (wn + ni * 8 + gid) * PADS + kb + tig;
                uint32_t b0 = __float_as_uint(bb[0]);
                uint32_t b1 = __float_as_uint(bb[4]);
#pragma unroll
                for (int mi = 0; mi < 4; mi++)
                    mma_tf32(acc[mi][ni], afr[mi], b0, b1);
            }
        }
    }

    // ---------------- epilogue ----------------
#pragma unroll
    for (int mi = 0; mi < 4; mi++) {
        int rbase = bm + wm + mi * 16 + gid;
#pragma unroll
        for (int ni = 0; ni < NI; ni++) {
            int c0 = bn + wn + ni * 8 + tig * 2;
            if (NG && c0 >= Ndim) continue;
#pragma unroll
            for (int half = 0; half < 2; half++) {
                int r0 = rbase + half * 8;
                float a0 = acc[mi][ni][half * 2 + 0];
                float a1 = acc[mi][ni][half * 2 + 1];
                if (OP == OP_NONE) {
                    *(float2*)(C + (size_t)r0 * Ndim + c0) = make_float2(a0, a1);
                } else if (OP == OP_ROUND) {
                    *(float2*)(C + (size_t)r0 * Ndim + c0) =
                        make_float2(roundtf(a0), roundtf(a1));
                } else if (OP == OP_SPLUS) {
                    float x0 = a0 + aux[c0], x1 = a1 + aux[c0 + 1];
                    x0 = (x0 > 20.f) ? x0 : log1pf(expf(x0));
                    x1 = (x1 > 20.f) ? x1 : log1pf(expf(x1));
                    *(float2*)(C + (size_t)r0 * Ndim + c0) = make_float2(x0, x1);
                } else if (OP == OP_SWIGLU) {
                    float sv = a0 * sigmoidf_(a0) * a1;
                    C[(size_t)r0 * IMc + (c0 >> 1)] = roundtf(sv);
                } else if (OP == OP_ADDC) {
                    float2 r = *(const float2*)(aux + (size_t)r0 * Ndim + c0);
                    *(float2*)(C + (size_t)r0 * Ndim + c0) =
                        make_float2(a0 + r.x, a1 + r.y);
                }
            }
        }
    }
}

// ---------------- weight prep ----------------
__global__ void round_copy(float* __restrict__ dst, const float* __restrict__ src, int n) {
    int idx = blockIdx.x * 256 + threadIdx.x;
    if (idx < n) dst[idx] = roundtf(src[idx]);
}
__global__ void round_concat_big(const float* __restrict__ ipw, const float* __restrict__ qw,
                                 const float* __restrict__ kw, const float* __restrict__ vw) {
    int idx = blockIdx.x * 256 + threadIdx.x;
    if (idx >= FUSN * Hc) return;
    int row = idx >> 10, col = idx & 1023;
    float v;
    if (row < 4096)      v = ipw[idx];
    else if (row < 5120) v = qw[(row - 4096) * Hc + col];
    else if (row < 5376) v = kw[(row - 5120) * Hc + col];
    else                 v = vw[(row - 5376) * Hc + col];
    g_wbig[idx] = roundtf(v);
}
__global__ void round_concat_kv(const float* __restrict__ kw, const float* __restrict__ vw) {
    int idx = blockIdx.x * 256 + threadIdx.x;
    if (idx >= KVSLD * Hc) return;
    int row = idx >> 10, col = idx & 1023;
    float v = (row < 256) ? kw[row * Hc + col] : vw[(row - 256) * Hc + col];
    g_wkv[idx] = roundtf(v);
}
__global__ void round_permute_gate(const float* __restrict__ gw) {
    int idx = blockIdx.x * 256 + threadIdx.x;
    if (idx >= GATEN * Hc) return;
    int row = idx >> 10, col = idx & 1023;
    int f = row >> 1;
    int src = (row & 1) ? (IMc + f) : f;
    g_wg[idx] = roundtf(gw[src * Hc + col]);
}

// ---------------- RMSNorm (+optional residual); nrm output tf32-rounded ----------------
__global__ void resid_rms(const float* __restrict__ a, const float* __restrict__ r,
                          const float* __restrict__ w, float* __restrict__ res_out,
                          float* __restrict__ nrm_out) {
    int row = blockIdx.x;
    int t   = threadIdx.x;
    const float* ap = a + (size_t)row * Hc;
    const float* rp = r ? r + (size_t)row * Hc : nullptr;
    float v[4];
    float ss = 0.f;
#pragma unroll
    for (int i = 0; i < 4; i++) {
        int c = t + i * 256;
        float x = ap[c] + (rp ? rp[c] : 0.f);
        v[i] = x;
        ss += x * x;
    }
#pragma unroll
    for (int off = 16; off; off >>= 1) ss += __shfl_xor_sync(0xffffffffu, ss, off);
    __shared__ float sred[8];
    __shared__ float sscale;
    if ((t & 31) == 0) sred[t >> 5] = ss;
    __syncthreads();
    if (t == 0) {
        float tot = 0.f;
        for (int i = 0; i < 8; i++) tot += sred[i];
        sscale = rsqrtf(tot * (1.f / Hc) + EPSc);
    }
    __syncthreads();
    float scale = sscale;
    float* ro = res_out ? res_out + (size_t)row * Hc : nullptr;
    float* no = nrm_out + (size_t)row * Hc;
#pragma unroll
    for (int i = 0; i < 4; i++) {
        int c = t + i * 256;
        if (ro) ro[c] = v[i];
        no[c] = roundtf(v[i] * scale * w[c]);
    }
}

// ---------------- causal depthwise conv (K=4) + SiLU ----------------
__global__ void conv_silu(const float* __restrict__ cw, const float* __restrict__ cb) {
    int idx = blockIdx.x * blockDim.x + threadIdx.x;
    if (idx >= Mrows * Ic) return;
    int row = idx / Ic;
    int i   = idx - row * Ic;
    int b   = row / Sc;
    int s   = row - b * Sc;
    float acc = cb[i];
#pragma unroll
    for (int k = 0; k < Kcv; k++) {
        int sp = s + k - (Kcv - 1);
        if (sp >= 0)
            acc += cw[i * Kcv + k] * g_xzq[(size_t)(b * Sc + sp) * FUSN + i];
    }
    float r = acc * sigmoidf_(acc);
    g_xs[idx]  = r;
    g_xst[idx] = roundtf(r);
}

// ---------------- selective scan (y output tf32-rounded) ----------------
__global__ void scan_kernel(const float* __restrict__ A_log, const float* __restrict__ Dp) {
    int t  = threadIdx.x;
    int c  = t >> 4;
    int n  = t & 15;
    int gi = blockIdx.x * 16 + c;
    int b  = gi / Ic;
    int i  = gi - b * Ic;
    float An = -expf(A_log[i * Nst + n]);
    float Dv = Dp[i];
    float h  = 0.f;
    for (int s = 0; s < Sc; s++) {
        int row = b * Sc + s;
        float dt = g_dt[(size_t)row * Ic + i];
        float xs = g_xs[(size_t)row * Ic + i];
        float Bn = g_proj[row * PROJW + Rc + n];
        float Cn = g_proj[row * PROJW + Rc + Nst + n];
        h = h * expf(dt * An) + dt * Bn * xs;
        float v = h * Cn;
        v += __shfl_xor_sync(0xffffffffu, v, 8);
        v += __shfl_xor_sync(0xffffffffu, v, 4);
        v += __shfl_xor_sync(0xffffffffu, v, 2);
        v += __shfl_xor_sync(0xffffffffu, v, 1);
        if (n == 0) {
            float z  = g_xzq[(size_t)row * FUSN + Ic + i];
            float yv = (v + Dv * xs) * (z * sigmoidf_(z));
            g_y[(size_t)row * Ic + i] = roundtf(yv);
        }
    }
}

// ---------------- rotary (in-place, strided view) ----------------
__global__ void rotary_kernel(float* __restrict__ p, int ld, int coloff, int nheads) {
    int idx = blockIdx.x * blockDim.x + threadIdx.x;
    int tot = Mrows * nheads * 32;
    if (idx >= tot) return;
    int r    = idx / (nheads * 32);
    int rem  = idx - r * (nheads * 32);
    int head = rem >> 5;
    int j    = rem & 31;
    int s    = r % Sc;
    float inv = expf(-((float)(2 * j) / (float)HDc) * logf(10000.0f));
    float f = (float)s * inv;
    float sn, cs;
    sincosf(f, &sn, &cs);
    float* base = p + (size_t)r * ld + coloff + head * HDc;
    float x1 = base[j], x2 = base[j + 32];
    base[j]      = x1 * cs - x2 * sn;
    base[j + 32] = x2 * cs + x1 * sn;
}

// ---------------- dual-window attention: smem key/value tiles ----------------
__global__ __launch_bounds__(256) void attn2() {
    __shared__ float sc[8][WATT + WSSM];
    __shared__ float tile[64][65];
    __shared__ float qs[8][64];
    int t    = threadIdx.x;
    int w    = t >> 5;
    int lane = t & 31;
    int q0   = blockIdx.x * 8;
    int h    = blockIdx.y;
    int b    = blockIdx.z;
    int rowb = b * Sc;
    int qi   = q0 + w;
    int hk   = h >> 2;

    const float* qp = g_xzq + (size_t)(rowb + qi) * FUSN + 4096 + h * HDc;
    qs[w][lane]      = qp[lane];
    qs[w][lane + 32] = qp[lane + 32];

    int ka = max(0, qi - (WATT - 1)), na = qi - ka + 1;
    int ks = max(0, qi - (WSSM - 1)), ns = qi - ks + 1;
    int caStart = max(0, q0 - (WATT - 1)) & ~63;
    int csStart = max(0, q0 - (WSSM - 1)) & ~63;

    for (int c = caStart; c <= q0 + 7; c += 64) {
        __syncthreads();
#pragma unroll
        for (int i = 0; i < 4; i++) {
            int id = t + i * 256;
            int r  = id >> 4;
            int d4 = (id & 15) * 4;
            int key = c + r;
            float4 v = make_float4(0.f, 0.f, 0.f, 0.f);
            if (key < Sc)
                v = *(const float4*)(g_xzq + (size_t)(rowb + key) * FUSN + 5120 + hk * HDc + d4);
            tile[d4][r] = v.x; tile[d4 + 1][r] = v.y;
            tile[d4 + 2][r] = v.z; tile[d4 + 3][r] = v.w;
        }
        __syncthreads();
        float a0 = 0.f, a1 = 0.f;
#pragma unroll 8
        for (int d = 0; d < 64; d++) {
            float qd = qs[w][d];
            a0 = fmaf(qd, tile[d][lane], a0);
            a1 = fmaf(qd, tile[d][lane + 32], a1);
        }
        int k0 = c + lane, k1 = c + lane + 32;
        if (k0 >= ka && k0 <= qi) sc[w][k0 - ka] = a0 * 0.125f;
        if (k1 >= ka && k1 <= qi) sc[w][k1 - ka] = a1 * 0.125f;
    }
    for (int c = csStart; c <= q0 + 7; c += 64) {
        __syncthreads();
#pragma unroll
        for (int i = 0; i < 4; i++) {
            int id = t + i * 256;
            int r  = id >> 4;
            int d4 = (id & 15) * 4;
            int key = c + r;
            float4 v = make_float4(0.f, 0.f, 0.f, 0.f);
            if (key < Sc)
                v = *(const float4*)(g_kvssm + (size_t)(rowb + key) * KVSLD + hk * HDc + d4);
            tile[d4][r] = v.x; tile[d4 + 1][r] = v.y;
            tile[d4 + 2][r] = v.z; tile[d4 + 3][r] = v.w;
        }
        __syncthreads();
        float a0 = 0.f, a1 = 0.f;
#pragma unroll 8
        for (int d = 0; d < 64; d++) {
            float qd = qs[w][d];
            a0 = fmaf(qd, tile[d][lane], a0);
            a1 = fmaf(qd, tile[d][lane + 32], a1);
        }
        int k0 = c + lane, k1 = c + lane + 32;
        if (k0 >= ks && k0 <= qi) sc[w][WATT + k0 - ks] = a0 * 0.125f;
        if (k1 >= ks && k1 <= qi) sc[w][WATT + k1 - ks] = a1 * 0.125f;
    }
    __syncwarp();

    float mx = -1e30f;
    for (int j = lane; j < na; j += 32) mx = fmaxf(mx, sc[w][j]);
    for (int j = lane; j < ns; j += 32) mx = fmaxf(mx, sc[w][WATT + j]);
#pragma unroll
    for (int off = 16; off; off >>= 1) mx = fmaxf(mx, __shfl_xor_sync(0xffffffffu, mx, off));
    float sum = 0.f;
    for (int j = lane; j < na; j += 32) { float e = expf(sc[w][j] - mx); sc[w][j] = e; sum += e; }
    for (int j = lane; j < ns; j += 32) { float e = expf(sc[w][WATT + j] - mx); sc[w][WATT + j] = e; sum += e; }
#pragma unroll
    for (int off = 16; off; off >>= 1) sum += __shfl_xor_sync(0xffffffffu, sum, off);
    float invs = 1.f / sum;
    __syncwarp();

    float o0 = 0.f, o1 = 0.f;
    for (int c = caStart; c <= q0 + 7; c += 64) {
        __syncthreads();
#pragma unroll
        for (int i = 0; i < 4; i++) {
            int id = t + i * 256;
            int r  = id >> 4;
            int d4 = (id & 15) * 4;
            int key = c + r;
            float4 v = make_float4(0.f, 0.f, 0.f, 0.f);
            if (key < Sc)
                v = *(const float4*)(g_xzq + (size_t)(rowb + key) * FUSN + 5376 + hk * HDc + d4);
            tile[r][d4] = v.x; tile[r][d4 + 1] = v.y;
            tile[r][d4 + 2] = v.z; tile[r][d4 + 3] = v.w;
        }
        __syncthreads();
#pragma unroll 4
        for (int j = 0; j < 64; j++) {
            int key = c + j;
            float p = (key >= ka && key <= qi) ? sc[w][key - ka] : 0.f;
            o0 = fmaf(p, tile[j][lane], o0);
            o1 = fmaf(p, tile[j][lane + 32], o1);
        }
    }
    for (int c = csStart; c <= q0 + 7; c += 64) {
        __syncthreads();
#pragma unroll
        for (int i = 0; i < 4; i++) {
            int id = t + i * 256;
            int r  = id >> 4;
            int d4 = (id & 15) * 4;
            int key = c + r;
            float4 v = make_float4(0.f, 0.f, 0.f, 0.f);
            if (key < Sc)
                v = *(const float4*)(g_kvssm + (size_t)(rowb + key) * KVSLD + 256 + hk * HDc + d4);
            tile[r][d4] = v.x; tile[r][d4 + 1] = v.y;
            tile[r][d4 + 2] = v.z; tile[r][d4 + 3] = v.w;
        }
        __syncthreads();
#pragma unroll 4
        for (int j = 0; j < 64; j++) {
            int key = c + j;
            float p = (key >= ks && key <= qi) ? sc[w][WATT + key - ks] : 0.f;
            o0 = fmaf(p, tile[j][lane], o0);
            o1 = fmaf(p, tile[j][lane + 32], o1);
        }
    }

    float* op = g_o + (size_t)(rowb + qi) * NHc * HDc + h * HDc;
    op[lane]      = roundtf(o0 * invs);
    op[lane + 32] = roundtf(o1 * invs);
}

// ---------------- host launcher ----------------
extern "C" void kernel_launch(void* const* d_in, const int* in_sizes, int n_in,
                              void* d_out, int out_size) {
    const float* hidden      = (const float*)d_in[0];
    const float* pre_norm_w  = (const float*)d_in[1];
    const float* in_proj_w   = (const float*)d_in[2];
    const float* conv_w      = (const float*)d_in[3];
    const float* conv_b      = (const float*)d_in[4];
    const float* x_proj_w    = (const float*)d_in[5];
    const float* dt_proj_w   = (const float*)d_in[6];
    const float* dt_proj_b   = (const float*)d_in[7];
    const float* A_log       = (const float*)d_in[8];
    const float* Dp          = (const float*)d_in[9];
    const float* out_proj_w  = (const float*)d_in[10];
    const float* ssm_norm_w  = (const float*)d_in[11];
    const float* q_w         = (const float*)d_in[12];
    const float* k_w         = (const float*)d_in[13];
    const float* v_w         = (const float*)d_in[14];
    const float* o_w         = (const float*)d_in[15];
    const float* mlp_norm_w  = (const float*)d_in[16];
    const float* gate_w      = (const float*)d_in[17];
    const float* down_w      = (const float*)d_in[18];
    float* out = (float*)d_out;

    const int smem128 = (BM * PADS + 128 * PADS) * STAGES * 4;  // 110592
    const int smem64  = (BM * PADS + 64 * PADS) * STAGES * 4;   // 82944
    cudaFuncSetAttribute(gemm_t<128, OP_NONE,  false>, cudaFuncAttributeMaxDynamicSharedMemorySize, smem128);
    cudaFuncSetAttribute(gemm_t<128, OP_SPLUS, false>, cudaFuncAttributeMaxDynamicSharedMemorySize, smem128);
    cudaFuncSetAttribute(gemm_t<128, OP_SWIGLU,false>, cudaFuncAttributeMaxDynamicSharedMemorySize, smem128);
    cudaFuncSetAttribute(gemm_t<64,  OP_ROUND, true >, cudaFuncAttributeMaxDynamicSharedMemorySize, smem64);
    cudaFuncSetAttribute(gemm_t<64,  OP_NONE,  false>, cudaFuncAttributeMaxDynamicSharedMemorySize, smem64);
    cudaFuncSetAttribute(gemm_t<64,  OP_ADDC,  false>, cudaFuncAttributeMaxDynamicSharedMemorySize, smem64);

    float *hs, *xzq, *xst, *proj, *dt, *y, *tmp, *ssmres, *ssmst;
    float *kvssm, *o, *mlpres, *x2, *hm;
    float *wbig, *wxp, *wdt, *wop, *wkv, *wo, *wg, *wd;
    cudaGetSymbolAddress((void**)&hs, g_hs);
    cudaGetSymbolAddress((void**)&xzq, g_xzq);
    cudaGetSymbolAddress((void**)&xst, g_xst);
    cudaGetSymbolAddress((void**)&proj, g_proj);
    cudaGetSymbolAddress((void**)&dt, g_dt);
    cudaGetSymbolAddress((void**)&y, g_y);
    cudaGetSymbolAddress((void**)&tmp, g_tmp);
    cudaGetSymbolAddress((void**)&ssmres, g_ssmres);
    cudaGetSymbolAddress((void**)&ssmst, g_ssmst);
    cudaGetSymbolAddress((void**)&kvssm, g_kvssm);
    cudaGetSymbolAddress((void**)&o, g_o);
    cudaGetSymbolAddress((void**)&mlpres, g_mlpres);
    cudaGetSymbolAddress((void**)&x2, g_x2);
    cudaGetSymbolAddress((void**)&hm, g_hm);
    cudaGetSymbolAddress((void**)&wbig, g_wbig);
    cudaGetSymbolAddress((void**)&wxp, g_wxp);
    cudaGetSymbolAddress((void**)&wdt, g_wdt);
    cudaGetSymbolAddress((void**)&wop, g_wop);
    cudaGetSymbolAddress((void**)&wkv, g_wkv);
    cudaGetSymbolAddress((void**)&wo, g_wo);
    cudaGetSymbolAddress((void**)&wg, g_wg);
    cudaGetSymbolAddress((void**)&wd, g_wd);

    // 0. weight prep
    round_concat_big<<<(FUSN * Hc + 255) / 256, 256>>>(in_proj_w, q_w, k_w, v_w);
    round_concat_kv<<<(KVSLD * Hc + 255) / 256, 256>>>(k_w, v_w);
    round_permute_gate<<<(GATEN * Hc + 255) / 256, 256>>>(gate_w);
    round_copy<<<(PROJW * Ic + 255) / 256, 256>>>(wxp, x_proj_w, PROJW * Ic);
    round_copy<<<(Ic * Rc + 255) / 256, 256>>>(wdt, dt_proj_w, Ic * Rc);
    round_copy<<<(Hc * Ic + 255) / 256, 256>>>(wop, out_proj_w, Hc * Ic);
    round_copy<<<(Hc * NHc * HDc + 255) / 256, 256>>>(wo, o_w, Hc * NHc * HDc);
    round_copy<<<(Hc * IMc + 255) / 256, 256>>>(wd, down_w, Hc * IMc);

    // 1. pre-norm
    resid_rms<<<Mrows, 256>>>(hidden, nullptr, pre_norm_w, nullptr, hs);
    // 2. fused xz|q|k|v (2048 x 5632, K=1024)
    gemm_t<128, OP_NONE, false><<<dim3(FUSN / 128, Mrows / BM), 128, smem128>>>(
        hs, wbig, xzq, nullptr, FUSN, Hc, Hc, Hc);
    // 3. conv + silu
    conv_silu<<<(Mrows * Ic) / 256, 256>>>(conv_w, conv_b);
    // 4. x_proj (2048 x 96, K=2048), rounded output
    gemm_t<64, OP_ROUND, true><<<dim3(2, Mrows / BM), 128, smem64>>>(
        xst, wxp, proj, nullptr, PROJW, Ic, Ic, Ic);
    // 5. dt = softplus(proj[:, :64] @ dt_w^T + bias)  (2048 x 2048, K=64)
    gemm_t<128, OP_SPLUS, false><<<dim3(Ic / 128, Mrows / BM), 128, smem128>>>(
        proj, wdt, dt, dt_proj_b, Ic, Rc, PROJW, Rc);
    // 6. selective scan
    scan_kernel<<<(Bc * Ic) / 16, 256>>>(A_log, Dp);
    // 7. out_proj (2048 x 1024, K=2048); residual + norm
    gemm_t<64, OP_NONE, false><<<dim3(Hc / 64, Mrows / BM), 128, smem64>>>(
        y, wop, tmp, nullptr, Hc, Ic, Ic, Ic);
    resid_rms<<<Mrows, 256>>>(tmp, hidden, ssm_norm_w, ssmres, ssmst);
    // 8. kv_ssm (2048 x 512, K=1024)
    gemm_t<64, OP_NONE, false><<<dim3(KVSLD / 64, Mrows / BM), 128, smem64>>>(
        ssmst, wkv, kvssm, nullptr, KVSLD, Hc, Hc, Hc);
    // 9. rotary
    rotary_kernel<<<(Mrows * NHc * 32) / 256, 256>>>(xzq, FUSN, 4096, NHc);
    rotary_kernel<<<(Mrows * NKVc * 32) / 256, 256>>>(xzq, FUSN, 5120, NKVc);
    rotary_kernel<<<(Mrows * NKVc * 32) / 256, 256>>>(kvssm, KVSLD, 0, NKVc);
    // 10. attention
    attn2<<<dim3(Sc / 8, NHc, Bc), 256>>>();
    // 11. o proj (2048 x 1024, K=1024); residual + norm
    gemm_t<64, OP_NONE, false><<<dim3(Hc / 64, Mrows / BM), 128, smem64>>>(
        o, wo, tmp, nullptr, Hc, NHc * HDc, NHc * HDc, NHc * HDc);
    resid_rms<<<Mrows, 256>>>(tmp, ssmres, mlp_norm_w, mlpres, x2);
    // 12. MLP: gate GEMM with fused swiglu -> hm; down GEMM with fused residual -> out
    gemm_t<128, OP_SWIGLU, false><<<dim3(GATEN / 128, Mrows / BM), 128, smem128>>>(
        x2, wg, hm, nullptr, GATEN, Hc, Hc, Hc);
    gemm_t<64, OP_ADDC, false><<<dim3(Hc / 64, Mrows / BM), 128, smem64>>>(
        hm, wd, out, mlpres, Hc, IMc, IMc, IMc);
}

// round 8
// speedup vs baseline: 1.2177x; 1.1670x over previous
#include <cuda_runtime.h>
#include <cuda_fp16.h>
#include <math.h>
#include <stdint.h>

// ---------------- problem constants ----------------
#define Bc   2
#define Sc   1024
#define Hc   1024
#define Ic   2048
#define Nst  16
#define Rc   64
#define Kcv  4
#define NHc  16
#define NKVc 4
#define HDc  64
#define WATT 512
#define WSSM 128
#define IMc  2816
#define Mrows (Bc*Sc)        // 2048
#define EPSc  1e-6f
#define PROJW (Rc + 2*Nst)   // 96
#define FUSN  5632           // xz(4096)|q(1024)|katt(256)|vatt(256)
#define KVSLD 512            // kssm(256)|vssm(256)
#define GATEN 5632           // interleaved gate|val pairs

// ---------------- scratch ----------------
__device__ __half g_hs[Mrows*Hc];           // rms out (GEMM A)
__device__ float  g_xzq[Mrows*FUSN];        // big GEMM out
__device__ float  g_xs[Mrows*Ic];           // conv out fp32 (scan)
__device__ __half g_xsh[Mrows*Ic];          // conv out half (x_proj A)
__device__ __half g_proj_h[Mrows*PROJW];    // x_proj out (dt A + scan B/C)
__device__ float  g_dt[Mrows*Ic];
__device__ __half g_y[Mrows*Ic];            // scan out (out_proj A)
__device__ float  g_tmp[Mrows*Hc];
__device__ float  g_ssmres[Mrows*Hc];
__device__ __half g_ssmst[Mrows*Hc];        // rms out (kv A)
__device__ float  g_kvssm[Mrows*KVSLD];
__device__ __half g_oh[Mrows*NHc*HDc];      // attn out (o_proj A)
__device__ float  g_mlpres[Mrows*Hc];
__device__ __half g_x2[Mrows*Hc];           // rms out (gate A)
__device__ __half g_hm[Mrows*IMc];          // swiglu out (down A)
// half weights
__device__ __half g_wbig[FUSN*Hc];
__device__ __half g_wxp[PROJW*Ic];
__device__ __half g_wdt[Ic*Rc];
__device__ __half g_wop[Hc*Ic];
__device__ __half g_wkv[KVSLD*Hc];
__device__ __half g_wo[Hc*NHc*HDc];
__device__ __half g_wg[GATEN*Hc];           // interleaved gate|val
__device__ __half g_wd[Hc*IMc];

__device__ __forceinline__ float sigmoidf_(float x) { return 1.f / (1.f + expf(-x)); }

// ---------------- fp16 MMA GEMM: C[m,n] = sum_k A[m,k]*B[n,k] ----------------
// 128 threads, warp grid 2(M)x2(N), warp tile 64x64 (BNT=128) / 64x32 (BNT=64).
// BK=32 (2 x k16), 4-stage cp.async ring, operands half, accum fp32.
#define BM 128
#define BK 32
#define PADH 40     // half units per smem row (32 + 8 pad) -> conflict-free
#define STAGES 4

// epilogue ops
#define OP_NONE   0   // float C
#define OP_HALF   1   // half C
#define OP_SPLUS  2   // float C = softplus(acc + aux[col])
#define OP_SWIGLU 3   // half C: paired cols -> silu(g)*v, ld=IMc
#define OP_ADDC   4   // float C = acc + aux[r*Ndim+c]

__device__ __forceinline__ void cp16(uint32_t dst, const void* src, int ssize) {
    asm volatile("cp.async.cg.shared.global [%0], [%1], 16, %2;\n"
                 :: "r"(dst), "l"(src), "r"(ssize));
}
__device__ __forceinline__ void mma_f16(float* c, const uint32_t* a, uint32_t b0, uint32_t b1) {
    asm volatile("mma.sync.aligned.m16n8k16.row.col.f32.f16.f16.f32 "
                 "{%0,%1,%2,%3}, {%4,%5,%6,%7}, {%8,%9}, {%0,%1,%2,%3};\n"
                 : "+f"(c[0]), "+f"(c[1]), "+f"(c[2]), "+f"(c[3])
                 : "r"(a[0]), "r"(a[1]), "r"(a[2]), "r"(a[3]), "r"(b0), "r"(b1));
}

template<int BNT, int OP, bool NG>
__global__ __launch_bounds__(128, 2)
void gemm_h(const __half* __restrict__ A, const __half* __restrict__ Bw,
            void* __restrict__ Cv, const float* __restrict__ aux,
            int Ndim, int Kdim, int lda, int ldb) {
    constexpr int NI  = BNT / 16;
    constexpr int ASZ = BM * PADH;           // halves
    constexpr int BSZ = BNT * PADH;
    constexpr int STG = ASZ + BSZ;
    extern __shared__ __half smh[];
    const int t    = threadIdx.x;
    const int bm   = blockIdx.y * BM;
    const int bn   = blockIdx.x * BNT;
    const int warp = t >> 5, lane = t & 31;
    const int wm   = (warp & 1) * 64;
    const int wn   = (warp >> 1) * (BNT / 2);
    const int gid  = lane >> 2;
    const int tig  = lane & 3;
    const uint32_t smem_base = (uint32_t)__cvta_generic_to_shared(smh);

    float acc[4][NI][4];
#pragma unroll
    for (int mi = 0; mi < 4; mi++)
#pragma unroll
        for (int ni = 0; ni < NI; ni++)
#pragma unroll
            for (int j = 0; j < 4; j++) acc[mi][ni][j] = 0.f;

    const int niters = Kdim / BK;

    auto load_tile = [&](int slot, int k0) {
        uint32_t aOff = smem_base + slot * STG * 2;
        uint32_t bOff = aOff + ASZ * 2;
        // A: 128 rows x 4 chunks(8 halves) = 512 -> 4 per thread
#pragma unroll
        for (int i = 0; i < 4; i++) {
            int id = t + i * 128;
            int r  = id >> 2;
            int kq = (id & 3) * 8;
            cp16(aOff + (r * PADH + kq) * 2, A + (size_t)(bm + r) * lda + k0 + kq, 16);
        }
        // B: BNT rows x 4 chunks
#pragma unroll
        for (int i = 0; i < BNT / 32; i++) {
            int id = t + i * 128;
            int r  = id >> 2;
            int kq = (id & 3) * 8;
            int ok = 1;
            int br = bn + r;
            if (NG) ok = (br < Ndim);
            cp16(bOff + (r * PADH + kq) * 2,
                 Bw + (size_t)(NG ? (ok ? br : 0) : br) * ldb + k0 + kq, ok ? 16 : 0);
        }
    };

#pragma unroll
    for (int s = 0; s < STAGES - 1; s++) {
        if (s < niters) load_tile(s, s * BK);
        asm volatile("cp.async.commit_group;\n");
    }

    int cslot = 0, nslot = STAGES - 1;
    for (int it = 0; it < niters; it++) {
        asm volatile("cp.async.wait_group %0;\n" :: "n"(STAGES - 2));
        __syncthreads();
        int nk = it + STAGES - 1;
        if (nk < niters) load_tile(nslot, nk * BK);
        asm volatile("cp.async.commit_group;\n");
        if (++nslot == STAGES) nslot = 0;

        const __half* Ab = smh + cslot * STG;
        const __half* Bb = Ab + ASZ;
        if (++cslot == STAGES) cslot = 0;
#pragma unroll
        for (int kk = 0; kk < 2; kk++) {
            int kb = kk * 16;
            uint32_t afr[4][4];
#pragma unroll
            for (int mi = 0; mi < 4; mi++) {
                const __half* ab = Ab + (wm + mi * 16 + gid) * PADH + kb + tig * 2;
                afr[mi][0] = *(const uint32_t*)(ab);
                afr[mi][1] = *(const uint32_t*)(ab + 8 * PADH);
                afr[mi][2] = *(const uint32_t*)(ab + 8);
                afr[mi][3] = *(const uint32_t*)(ab + 8 * PADH + 8);
            }
#pragma unroll
            for (int ni = 0; ni < NI; ni++) {
                const __half* bb = Bb + (wn + ni * 8 + gid) * PADH + kb + tig * 2;
                uint32_t b0 = *(const uint32_t*)(bb);
                uint32_t b1 = *(const uint32_t*)(bb + 8);
#pragma unroll
                for (int mi = 0; mi < 4; mi++)
                    mma_f16(acc[mi][ni], afr[mi], b0, b1);
            }
        }
    }

    // ---------------- epilogue ----------------
    float*  Cf = (float*)Cv;
    __half* Ch = (__half*)Cv;
#pragma unroll
    for (int mi = 0; mi < 4; mi++) {
        int rbase = bm + wm + mi * 16 + gid;
#pragma unroll
        for (int ni = 0; ni < NI; ni++) {
            int c0 = bn + wn + ni * 8 + tig * 2;
            if (NG && c0 >= Ndim) continue;
#pragma unroll
            for (int half_ = 0; half_ < 2; half_++) {
                int r0 = rbase + half_ * 8;
                float a0 = acc[mi][ni][half_ * 2 + 0];
                float a1 = acc[mi][ni][half_ * 2 + 1];
                if (OP == OP_NONE) {
                    *(float2*)(Cf + (size_t)r0 * Ndim + c0) = make_float2(a0, a1);
                } else if (OP == OP_HALF) {
                    __half2 hv = __floats2half2_rn(a0, a1);
                    *(__half2*)(Ch + (size_t)r0 * Ndim + c0) = hv;
                } else if (OP == OP_SPLUS) {
                    float x0 = a0 + aux[c0], x1 = a1 + aux[c0 + 1];
                    x0 = (x0 > 20.f) ? x0 : log1pf(expf(x0));
                    x1 = (x1 > 20.f) ? x1 : log1pf(expf(x1));
                    *(float2*)(Cf + (size_t)r0 * Ndim + c0) = make_float2(x0, x1);
                } else if (OP == OP_SWIGLU) {
                    float sv = a0 * sigmoidf_(a0) * a1;
                    Ch[(size_t)r0 * IMc + (c0 >> 1)] = __float2half_rn(sv);
                } else if (OP == OP_ADDC) {
                    float2 r = *(const float2*)(aux + (size_t)r0 * Ndim + c0);
                    *(float2*)(Cf + (size_t)r0 * Ndim + c0) =
                        make_float2(a0 + r.x, a1 + r.y);
                }
            }
        }
    }
}

// ---------------- weight prep (fp32 -> half) ----------------
__global__ void half_copy(__half* __restrict__ dst, const float* __restrict__ src, int n) {
    int idx = blockIdx.x * 256 + threadIdx.x;
    if (idx < n) dst[idx] = __float2half_rn(src[idx]);
}
__global__ void half_concat_big(const float* __restrict__ ipw, const float* __restrict__ qw,
                                const float* __restrict__ kw, const float* __restrict__ vw) {
    int idx = blockIdx.x * 256 + threadIdx.x;
    if (idx >= FUSN * Hc) return;
    int row = idx >> 10, col = idx & 1023;
    float v;
    if (row < 4096)      v = ipw[idx];
    else if (row < 5120) v = qw[(row - 4096) * Hc + col];
    else if (row < 5376) v = kw[(row - 5120) * Hc + col];
    else                 v = vw[(row - 5376) * Hc + col];
    g_wbig[idx] = __float2half_rn(v);
}
__global__ void half_concat_kv(const float* __restrict__ kw, const float* __restrict__ vw) {
    int idx = blockIdx.x * 256 + threadIdx.x;
    if (idx >= KVSLD * Hc) return;
    int row = idx >> 10, col = idx & 1023;
    float v = (row < 256) ? kw[row * Hc + col] : vw[(row - 256) * Hc + col];
    g_wkv[idx] = __float2half_rn(v);
}
__global__ void half_permute_gate(const float* __restrict__ gw) {
    int idx = blockIdx.x * 256 + threadIdx.x;
    if (idx >= GATEN * Hc) return;
    int row = idx >> 10, col = idx & 1023;
    int f = row >> 1;
    int src = (row & 1) ? (IMc + f) : f;
    g_wg[idx] = __float2half_rn(gw[src * Hc + col]);
}

// ---------------- RMSNorm (+optional residual); nrm output half ----------------
__global__ void resid_rms(const float* __restrict__ a, const float* __restrict__ r,
                          const float* __restrict__ w, float* __restrict__ res_out,
                          __half* __restrict__ nrm_out) {
    int row = blockIdx.x;
    int t   = threadIdx.x;
    const float* ap = a + (size_t)row * Hc;
    const float* rp = r ? r + (size_t)row * Hc : nullptr;
    float v[4];
    float ss = 0.f;
#pragma unroll
    for (int i = 0; i < 4; i++) {
        int c = t + i * 256;
        float x = ap[c] + (rp ? rp[c] : 0.f);
        v[i] = x;
        ss += x * x;
    }
#pragma unroll
    for (int off = 16; off; off >>= 1) ss += __shfl_xor_sync(0xffffffffu, ss, off);
    __shared__ float sred[8];
    __shared__ float sscale;
    if ((t & 31) == 0) sred[t >> 5] = ss;
    __syncthreads();
    if (t == 0) {
        float tot = 0.f;
        for (int i = 0; i < 8; i++) tot += sred[i];
        sscale = rsqrtf(tot * (1.f / Hc) + EPSc);
    }
    __syncthreads();
    float scale = sscale;
    float* ro = res_out ? res_out + (size_t)row * Hc : nullptr;
    __half* no = nrm_out + (size_t)row * Hc;
#pragma unroll
    for (int i = 0; i < 4; i++) {
        int c = t + i * 256;
        if (ro) ro[c] = v[i];
        no[c] = __float2half_rn(v[i] * scale * w[c]);
    }
}

// ---------------- causal depthwise conv (K=4) + SiLU ----------------
__global__ void conv_silu(const float* __restrict__ cw, const float* __restrict__ cb) {
    int idx = blockIdx.x * blockDim.x + threadIdx.x;
    if (idx >= Mrows * Ic) return;
    int row = idx / Ic;
    int i   = idx - row * Ic;
    int b   = row / Sc;
    int s   = row - b * Sc;
    float acc = cb[i];
#pragma unroll
    for (int k = 0; k < Kcv; k++) {
        int sp = s + k - (Kcv - 1);
        if (sp >= 0)
            acc += cw[i * Kcv + k] * g_xzq[(size_t)(b * Sc + sp) * FUSN + i];
    }
    float r = acc * sigmoidf_(acc);
    g_xs[idx]  = r;
    g_xsh[idx] = __float2half_rn(r);
}

// ---------------- selective scan ----------------
__global__ void scan_kernel(const float* __restrict__ A_log, const float* __restrict__ Dp) {
    int t  = threadIdx.x;
    int c  = t >> 4;
    int n  = t & 15;
    int gi = blockIdx.x * 16 + c;
    int b  = gi / Ic;
    int i  = gi - b * Ic;
    float An = -expf(A_log[i * Nst + n]);
    float Dv = Dp[i];
    float h  = 0.f;
    for (int s = 0; s < Sc; s++) {
        int row = b * Sc + s;
        float dt = g_dt[(size_t)row * Ic + i];
        float xs = g_xs[(size_t)row * Ic + i];
        float Bn = __half2float(g_proj_h[row * PROJW + Rc + n]);
        float Cn = __half2float(g_proj_h[row * PROJW + Rc + Nst + n]);
        h = h * expf(dt * An) + dt * Bn * xs;
        float v = h * Cn;
        v += __shfl_xor_sync(0xffffffffu, v, 8);
        v += __shfl_xor_sync(0xffffffffu, v, 4);
        v += __shfl_xor_sync(0xffffffffu, v, 2);
        v += __shfl_xor_sync(0xffffffffu, v, 1);
        if (n == 0) {
            float z  = g_xzq[(size_t)row * FUSN + Ic + i];
            float yv = (v + Dv * xs) * (z * sigmoidf_(z));
            g_y[(size_t)row * Ic + i] = __float2half_rn(yv);
        }
    }
}

// ---------------- rotary (in-place, strided view, fp32) ----------------
__global__ void rotary_kernel(float* __restrict__ p, int ld, int coloff, int nheads) {
    int idx = blockIdx.x * blockDim.x + threadIdx.x;
    int tot = Mrows * nheads * 32;
    if (idx >= tot) return;
    int r    = idx / (nheads * 32);
    int rem  = idx - r * (nheads * 32);
    int head = rem >> 5;
    int j    = rem & 31;
    int s    = r % Sc;
    float inv = expf(-((float)(2 * j) / (float)HDc) * logf(10000.0f));
    float f = (float)s * inv;
    float sn, cs;
    sincosf(f, &sn, &cs);
    float* base = p + (size_t)r * ld + coloff + head * HDc;
    float x1 = base[j], x2 = base[j + 32];
    base[j]      = x1 * cs - x2 * sn;
    base[j + 32] = x2 * cs + x1 * sn;
}

// ---------------- dual-window attention: smem key/value tiles ----------------
__global__ __launch_bounds__(256) void attn2() {
    __shared__ float sc[8][WATT + WSSM];
    __shared__ float tile[64][65];
    __shared__ float qs[8][64];
    int t    = threadIdx.x;
    int w    = t >> 5;
    int lane = t & 31;
    int q0   = blockIdx.x * 8;
    int h    = blockIdx.y;
    int b    = blockIdx.z;
    int rowb = b * Sc;
    int qi   = q0 + w;
    int hk   = h >> 2;

    const float* qp = g_xzq + (size_t)(rowb + qi) * FUSN + 4096 + h * HDc;
    qs[w][lane]      = qp[lane];
    qs[w][lane + 32] = qp[lane + 32];

    int ka = max(0, qi - (WATT - 1)), na = qi - ka + 1;
    int ks = max(0, qi - (WSSM - 1)), ns = qi - ks + 1;
    int caStart = max(0, q0 - (WATT - 1)) & ~63;
    int csStart = max(0, q0 - (WSSM - 1)) & ~63;

    for (int c = caStart; c <= q0 + 7; c += 64) {
        __syncthreads();
#pragma unroll
        for (int i = 0; i < 4; i++) {
            int id = t + i * 256;
            int r  = id >> 4;
            int d4 = (id & 15) * 4;
            int key = c + r;
            float4 v = make_float4(0.f, 0.f, 0.f, 0.f);
            if (key < Sc)
                v = *(const float4*)(g_xzq + (size_t)(rowb + key) * FUSN + 5120 + hk * HDc + d4);
            tile[d4][r] = v.x; tile[d4 + 1][r] = v.y;
            tile[d4 + 2][r] = v.z; tile[d4 + 3][r] = v.w;
        }
        __syncthreads();
        float a0 = 0.f, a1 = 0.f;
#pragma unroll 8
        for (int d = 0; d < 64; d++) {
            float qd = qs[w][d];
            a0 = fmaf(qd, tile[d][lane], a0);
            a1 = fmaf(qd, tile[d][lane + 32], a1);
        }
        int k0 = c + lane, k1 = c + lane + 32;
        if (k0 >= ka && k0 <= qi) sc[w][k0 - ka] = a0 * 0.125f;
        if (k1 >= ka && k1 <= qi) sc[w][k1 - ka] = a1 * 0.125f;
    }
    for (int c = csStart; c <= q0 + 7; c += 64) {
        __syncthreads();
#pragma unroll
        for (int i = 0; i < 4; i++) {
            int id = t + i * 256;
            int r  = id >> 4;
            int d4 = (id & 15) * 4;
            int key = c + r;
            float4 v = make_float4(0.f, 0.f, 0.f, 0.f);
            if (key < Sc)
                v = *(const float4*)(g_kvssm + (size_t)(rowb + key) * KVSLD + hk * HDc + d4);
            tile[d4][r] = v.x; tile[d4 + 1][r] = v.y;
            tile[d4 + 2][r] = v.z; tile[d4 + 3][r] = v.w;
        }
        __syncthreads();
        float a0 = 0.f, a1 = 0.f;
#pragma unroll 8
        for (int d = 0; d < 64; d++) {
            float qd = qs[w][d];
            a0 = fmaf(qd, tile[d][lane], a0);
            a1 = fmaf(qd, tile[d][lane + 32], a1);
        }
        int k0 = c + lane, k1 = c + lane + 32;
        if (k0 >= ks && k0 <= qi) sc[w][WATT + k0 - ks] = a0 * 0.125f;
        if (k1 >= ks && k1 <= qi) sc[w][WATT + k1 - ks] = a1 * 0.125f;
    }
    __syncwarp();

    float mx = -1e30f;
    for (int j = lane; j < na; j += 32) mx = fmaxf(mx, sc[w][j]);
    for (int j = lane; j < ns; j += 32) mx = fmaxf(mx, sc[w][WATT + j]);
#pragma unroll
    for (int off = 16; off; off >>= 1) mx = fmaxf(mx, __shfl_xor_sync(0xffffffffu, mx, off));
    float sum = 0.f;
    for (int j = lane; j < na; j += 32) { float e = expf(sc[w][j] - mx); sc[w][j] = e; sum += e; }
    for (int j = lane; j < ns; j += 32) { float e = expf(sc[w][WATT + j] - mx); sc[w][WATT + j] = e; sum += e; }
#pragma unroll
    for (int off = 16; off; off >>= 1) sum += __shfl_xor_sync(0xffffffffu, sum, off);
    float invs = 1.f / sum;
    __syncwarp();

    float o0 = 0.f, o1 = 0.f;
    for (int c = caStart; c <= q0 + 7; c += 64) {
        __syncthreads();
#pragma unroll
        for (int i = 0; i < 4; i++) {
            int id = t + i * 256;
            int r  = id >> 4;
            int d4 = (id & 15) * 4;
            int key = c + r;
            float4 v = make_float4(0.f, 0.f, 0.f, 0.f);
            if (key < Sc)
                v = *(const float4*)(g_xzq + (size_t)(rowb + key) * FUSN + 5376 + hk * HDc + d4);
            tile[r][d4] = v.x; tile[r][d4 + 1] = v.y;
            tile[r][d4 + 2] = v.z; tile[r][d4 + 3] = v.w;
        }
        __syncthreads();
#pragma unroll 4
        for (int j = 0; j < 64; j++) {
            int key = c + j;
            float p = (key >= ka && key <= qi) ? sc[w][key - ka] : 0.f;
            o0 = fmaf(p, tile[j][lane], o0);
            o1 = fmaf(p, tile[j][lane + 32], o1);
        }
    }
    for (int c = csStart; c <= q0 + 7; c += 64) {
        __syncthreads();
#pragma unroll
        for (int i = 0; i < 4; i++) {
            int id = t + i * 256;
            int r  = id >> 4;
            int d4 = (id & 15) * 4;
            int key = c + r;
            float4 v = make_float4(0.f, 0.f, 0.f, 0.f);
            if (key < Sc)
                v = *(const float4*)(g_kvssm + (size_t)(rowb + key) * KVSLD + 256 + hk * HDc + d4);
            tile[r][d4] = v.x; tile[r][d4 + 1] = v.y;
            tile[r][d4 + 2] = v.z; tile[r][d4 + 3] = v.w;
        }
        __syncthreads();
#pragma unroll 4
        for (int j = 0; j < 64; j++) {
            int key = c + j;
            float p = (key >= ks && key <= qi) ? sc[w][WATT + key - ks] : 0.f;
            o0 = fmaf(p, tile[j][lane], o0);
            o1 = fmaf(p, tile[j][lane + 32], o1);
        }
    }

    __half* op = g_oh + (size_t)(rowb + qi) * NHc * HDc + h * HDc;
    op[lane]      = __float2half_rn(o0 * invs);
    op[lane + 32] = __float2half_rn(o1 * invs);
}

// ---------------- host launcher ----------------
extern "C" void kernel_launch(void* const* d_in, const int* in_sizes, int n_in,
                              void* d_out, int out_size) {
    const float* hidden      = (const float*)d_in[0];
    const float* pre_norm_w  = (const float*)d_in[1];
    const float* in_proj_w   = (const float*)d_in[2];
    const float* conv_w      = (const float*)d_in[3];
    const float* conv_b      = (const float*)d_in[4];
    const float* x_proj_w    = (const float*)d_in[5];
    const float* dt_proj_w   = (const float*)d_in[6];
    const float* dt_proj_b   = (const float*)d_in[7];
    const float* A_log       = (const float*)d_in[8];
    const float* Dp          = (const float*)d_in[9];
    const float* out_proj_w  = (const float*)d_in[10];
    const float* ssm_norm_w  = (const float*)d_in[11];
    const float* q_w         = (const float*)d_in[12];
    const float* k_w         = (const float*)d_in[13];
    const float* v_w         = (const float*)d_in[14];
    const float* o_w         = (const float*)d_in[15];
    const float* mlp_norm_w  = (const float*)d_in[16];
    const float* gate_w      = (const float*)d_in[17];
    const float* down_w      = (const float*)d_in[18];
    float* out = (float*)d_out;

    const int smem128 = (BM * PADH + 128 * PADH) * STAGES * 2;  // 81920
    const int smem64  = (BM * PADH + 64 * PADH) * STAGES * 2;   // 61440
    cudaFuncSetAttribute(gemm_h<128, OP_NONE,  false>, cudaFuncAttributeMaxDynamicSharedMemorySize, smem128);
    cudaFuncSetAttribute(gemm_h<128, OP_SPLUS, false>, cudaFuncAttributeMaxDynamicSharedMemorySize, smem128);
    cudaFuncSetAttribute(gemm_h<128, OP_SWIGLU,false>, cudaFuncAttributeMaxDynamicSharedMemorySize, smem128);
    cudaFuncSetAttribute(gemm_h<64,  OP_HALF,  true >, cudaFuncAttributeMaxDynamicSharedMemorySize, smem64);
    cudaFuncSetAttribute(gemm_h<64,  OP_NONE,  false>, cudaFuncAttributeMaxDynamicSharedMemorySize, smem64);
    cudaFuncSetAttribute(gemm_h<64,  OP_ADDC,  false>, cudaFuncAttributeMaxDynamicSharedMemorySize, smem64);

    __half *hs, *xsh, *proj_h, *y, *ssmst, *oh, *x2, *hm;
    __half *wbig, *wxp, *wdt, *wop, *wkv, *wo, *wg, *wd;
    float *xzq, *xs, *dt, *tmp, *ssmres, *kvssm, *mlpres;
    cudaGetSymbolAddress((void**)&hs, g_hs);
    cudaGetSymbolAddress((void**)&xzq, g_xzq);
    cudaGetSymbolAddress((void**)&xs, g_xs);
    cudaGetSymbolAddress((void**)&xsh, g_xsh);
    cudaGetSymbolAddress((void**)&proj_h, g_proj_h);
    cudaGetSymbolAddress((void**)&dt, g_dt);
    cudaGetSymbolAddress((void**)&y, g_y);
    cudaGetSymbolAddress((void**)&tmp, g_tmp);
    cudaGetSymbolAddress((void**)&ssmres, g_ssmres);
    cudaGetSymbolAddress((void**)&ssmst, g_ssmst);
    cudaGetSymbolAddress((void**)&kvssm, g_kvssm);
    cudaGetSymbolAddress((void**)&oh, g_oh);
    cudaGetSymbolAddress((void**)&mlpres, g_mlpres);
    cudaGetSymbolAddress((void**)&x2, g_x2);
    cudaGetSymbolAddress((void**)&hm, g_hm);
    cudaGetSymbolAddress((void**)&wbig, g_wbig);
    cudaGetSymbolAddress((void**)&wxp, g_wxp);
    cudaGetSymbolAddress((void**)&wdt, g_wdt);
    cudaGetSymbolAddress((void**)&wop, g_wop);
    cudaGetSymbolAddress((void**)&wkv, g_wkv);
    cudaGetSymbolAddress((void**)&wo, g_wo);
    cudaGetSymbolAddress((void**)&wg, g_wg);
    cudaGetSymbolAddress((void**)&wd, g_wd);

    // 0. weight prep
    half_concat_big<<<(FUSN * Hc + 255) / 256, 256>>>(in_proj_w, q_w, k_w, v_w);
    half_concat_kv<<<(KVSLD * Hc + 255) / 256, 256>>>(k_w, v_w);
    half_permute_gate<<<(GATEN * Hc + 255) / 256, 256>>>(gate_w);
    half_copy<<<(PROJW * Ic + 255) / 256, 256>>>(wxp, x_proj_w, PROJW * Ic);
    half_copy<<<(Ic * Rc + 255) / 256, 256>>>(wdt, dt_proj_w, Ic * Rc);
    half_copy<<<(Hc * Ic + 255) / 256, 256>>>(wop, out_proj_w, Hc * Ic);
    half_copy<<<(Hc * NHc * HDc + 255) / 256, 256>>>(wo, o_w, Hc * NHc * HDc);
    half_copy<<<(Hc * IMc + 255) / 256, 256>>>(wd, down_w, Hc * IMc);

    // 1. pre-norm (half out)
    resid_rms<<<Mrows, 256>>>(hidden, nullptr, pre_norm_w, nullptr, hs);
    // 2. fused xz|q|k|v (2048 x 5632, K=1024) -> fp32
    gemm_h<128, OP_NONE, false><<<dim3(FUSN / 128, Mrows / BM), 128, smem128>>>(
        hs, wbig, xzq, nullptr, FUSN, Hc, Hc, Hc);
    // 3. conv + silu (fp32 + half out)
    conv_silu<<<(Mrows * Ic) / 256, 256>>>(conv_w, conv_b);
    // 4. x_proj (2048 x 96, K=2048) -> half
    gemm_h<64, OP_HALF, true><<<dim3(2, Mrows / BM), 128, smem64>>>(
        xsh, wxp, proj_h, nullptr, PROJW, Ic, Ic, Ic);
    // 5. dt = softplus(proj @ dt_w^T + bias)  (2048 x 2048, K=64) -> fp32
    gemm_h<128, OP_SPLUS, false><<<dim3(Ic / 128, Mrows / BM), 128, smem128>>>(
        proj_h, wdt, dt, dt_proj_b, Ic, Rc, PROJW, Rc);
    // 6. selective scan -> y (half)
    scan_kernel<<<(Bc * Ic) / 16, 256>>>(A_log, Dp);
    // 7. out_proj (2048 x 1024, K=2048) -> fp32; residual + norm
    gemm_h<64, OP_NONE, false><<<dim3(Hc / 64, Mrows / BM), 128, smem64>>>(
        y, wop, tmp, nullptr, Hc, Ic, Ic, Ic);
    resid_rms<<<Mrows, 256>>>(tmp, hidden, ssm_norm_w, ssmres, ssmst);
    // 8. kv_ssm (2048 x 512, K=1024) -> fp32
    gemm_h<64, OP_NONE, false><<<dim3(KVSLD / 64, Mrows / BM), 128, smem64>>>(
        ssmst, wkv, kvssm, nullptr, KVSLD, Hc, Hc, Hc);
    // 9. rotary
    rotary_kernel<<<(Mrows * NHc * 32) / 256, 256>>>(xzq, FUSN, 4096, NHc);
    rotary_kernel<<<(Mrows * NKVc * 32) / 256, 256>>>(xzq, FUSN, 5120, NKVc);
    rotary_kernel<<<(Mrows * NKVc * 32) / 256, 256>>>(kvssm, KVSLD, 0, NKVc);
    // 10. attention -> o (half)
    attn2<<<dim3(Sc / 8, NHc, Bc), 256>>>();
    // 11. o proj (2048 x 1024, K=1024) -> fp32; residual + norm
    gemm_h<64, OP_NONE, false><<<dim3(Hc / 64, Mrows / BM), 128, smem64>>>(
        oh, wo, tmp, nullptr, Hc, NHc * HDc, NHc * HDc, NHc * HDc);
    resid_rms<<<Mrows, 256>>>(tmp, ssmres, mlp_norm_w, mlpres, x2);
    // 12. MLP: gate GEMM + fused swiglu -> hm (half); down GEMM + fused residual -> out
    gemm_h<128, OP_SWIGLU, false><<<dim3(GATEN / 128, Mrows / BM), 128, smem128>>>(
        x2, wg, hm, nullptr, GATEN, Hc, Hc, Hc);
    gemm_h<64, OP_ADDC, false><<<dim3(Hc / 64, Mrows / BM), 128, smem64>>>(
        hm, wd, out, mlpres, Hc, IMc, IMc, IMc);
}

// round 9
// speedup vs baseline: 1.2466x; 1.0237x over previous
#include <cuda_runtime.h>
#include <cuda_fp16.h>
#include <math.h>
#include <stdint.h>

// ---------------- problem constants ----------------
#define Bc   2
#define Sc   1024
#define Hc   1024
#define Ic   2048
#define Nst  16
#define Rc   64
#define Kcv  4
#define NHc  16
#define NKVc 4
#define HDc  64
#define WATT 512
#define WSSM 128
#define IMc  2816
#define Mrows (Bc*Sc)        // 2048
#define EPSc  1e-6f
#define PROJW (Rc + 2*Nst)   // 96
#define FUSN  5632           // xz(4096)|q(1024)|katt(256)|vatt(256)
#define KVSLD 512            // kssm(256)|vssm(256)
#define GATEN 5632           // interleaved gate|val pairs

// ---------------- scratch ----------------
__device__ __half g_hs[Mrows*Hc];
__device__ float  g_xzq[Mrows*FUSN];
__device__ float  g_xs[Mrows*Ic];
__device__ __half g_xsh[Mrows*Ic];
__device__ __half g_proj_h[Mrows*PROJW];
__device__ float  g_dt[Mrows*Ic];
__device__ __half g_y[Mrows*Ic];
__device__ float  g_tmp[Mrows*Hc];
__device__ float  g_ssmres[Mrows*Hc];
__device__ __half g_ssmst[Mrows*Hc];
__device__ float  g_kvssm[Mrows*KVSLD];
__device__ __half g_oh[Mrows*NHc*HDc];
__device__ float  g_mlpres[Mrows*Hc];
__device__ __half g_x2[Mrows*Hc];
__device__ __half g_hm[Mrows*IMc];
// compact half attention operands
__device__ __half g_qh[Mrows*NHc*HDc];      // rotated q
__device__ __half g_kah[Mrows*NKVc*HDc];    // rotated k_att
__device__ __half g_ksh[Mrows*NKVc*HDc];    // rotated k_ssm
__device__ __half g_vah[Mrows*NKVc*HDc];    // v_att
__device__ __half g_vsh[Mrows*NKVc*HDc];    // v_ssm
// half weights
__device__ __half g_wbig[FUSN*Hc];
__device__ __half g_wxp[PROJW*Ic];
__device__ __half g_wdt[Ic*Rc];
__device__ __half g_wop[Hc*Ic];
__device__ __half g_wkv[KVSLD*Hc];
__device__ __half g_wo[Hc*NHc*HDc];
__device__ __half g_wg[GATEN*Hc];
__device__ __half g_wd[Hc*IMc];

__device__ __forceinline__ float sigmoidf_(float x) { return 1.f / (1.f + expf(-x)); }

// ---------------- fp16 MMA GEMM (unchanged from R8) ----------------
#define BM 128
#define BK 32
#define PADH 40
#define STAGES 4

#define OP_NONE   0
#define OP_HALF   1
#define OP_SPLUS  2
#define OP_SWIGLU 3
#define OP_ADDC   4

__device__ __forceinline__ void cp16(uint32_t dst, const void* src, int ssize) {
    asm volatile("cp.async.cg.shared.global [%0], [%1], 16, %2;\n"
                 :: "r"(dst), "l"(src), "r"(ssize));
}
__device__ __forceinline__ void mma_f16(float* c, const uint32_t* a, uint32_t b0, uint32_t b1) {
    asm volatile("mma.sync.aligned.m16n8k16.row.col.f32.f16.f16.f32 "
                 "{%0,%1,%2,%3}, {%4,%5,%6,%7}, {%8,%9}, {%0,%1,%2,%3};\n"
                 : "+f"(c[0]), "+f"(c[1]), "+f"(c[2]), "+f"(c[3])
                 : "r"(a[0]), "r"(a[1]), "r"(a[2]), "r"(a[3]), "r"(b0), "r"(b1));
}

template<int BNT, int OP, bool NG>
__global__ __launch_bounds__(128, 2)
void gemm_h(const __half* __restrict__ A, const __half* __restrict__ Bw,
            void* __restrict__ Cv, const float* __restrict__ aux,
            int Ndim, int Kdim, int lda, int ldb) {
    constexpr int NI  = BNT / 16;
    constexpr int ASZ = BM * PADH;
    constexpr int BSZ = BNT * PADH;
    constexpr int STG = ASZ + BSZ;
    extern __shared__ __half smh[];
    const int t    = threadIdx.x;
    const int bm   = blockIdx.y * BM;
    const int bn   = blockIdx.x * BNT;
    const int warp = t >> 5, lane = t & 31;
    const int wm   = (warp & 1) * 64;
    const int wn   = (warp >> 1) * (BNT / 2);
    const int gid  = lane >> 2;
    const int tig  = lane & 3;
    const uint32_t smem_base = (uint32_t)__cvta_generic_to_shared(smh);

    float acc[4][NI][4];
#pragma unroll
    for (int mi = 0; mi < 4; mi++)
#pragma unroll
        for (int ni = 0; ni < NI; ni++)
#pragma unroll
            for (int j = 0; j < 4; j++) acc[mi][ni][j] = 0.f;

    const int niters = Kdim / BK;

    auto load_tile = [&](int slot, int k0) {
        uint32_t aOff = smem_base + slot * STG * 2;
        uint32_t bOff = aOff + ASZ * 2;
#pragma unroll
        for (int i = 0; i < 4; i++) {
            int id = t + i * 128;
            int r  = id >> 2;
            int kq = (id & 3) * 8;
            cp16(aOff + (r * PADH + kq) * 2, A + (size_t)(bm + r) * lda + k0 + kq, 16);
        }
#pragma unroll
        for (int i = 0; i < BNT / 32; i++) {
            int id = t + i * 128;
            int r  = id >> 2;
            int kq = (id & 3) * 8;
            int ok = 1;
            int br = bn + r;
            if (NG) ok = (br < Ndim);
            cp16(bOff + (r * PADH + kq) * 2,
                 Bw + (size_t)(NG ? (ok ? br : 0) : br) * ldb + k0 + kq, ok ? 16 : 0);
        }
    };

#pragma unroll
    for (int s = 0; s < STAGES - 1; s++) {
        if (s < niters) load_tile(s, s * BK);
        asm volatile("cp.async.commit_group;\n");
    }

    int cslot = 0, nslot = STAGES - 1;
    for (int it = 0; it < niters; it++) {
        asm volatile("cp.async.wait_group %0;\n" :: "n"(STAGES - 2));
        __syncthreads();
        int nk = it + STAGES - 1;
        if (nk < niters) load_tile(nslot, nk * BK);
        asm volatile("cp.async.commit_group;\n");
        if (++nslot == STAGES) nslot = 0;

        const __half* Ab = smh + cslot * STG;
        const __half* Bb = Ab + ASZ;
        if (++cslot == STAGES) cslot = 0;
#pragma unroll
        for (int kk = 0; kk < 2; kk++) {
            int kb = kk * 16;
            uint32_t afr[4][4];
#pragma unroll
            for (int mi = 0; mi < 4; mi++) {
                const __half* ab = Ab + (wm + mi * 16 + gid) * PADH + kb + tig * 2;
                afr[mi][0] = *(const uint32_t*)(ab);
                afr[mi][1] = *(const uint32_t*)(ab + 8 * PADH);
                afr[mi][2] = *(const uint32_t*)(ab + 8);
                afr[mi][3] = *(const uint32_t*)(ab + 8 * PADH + 8);
            }
#pragma unroll
            for (int ni = 0; ni < NI; ni++) {
                const __half* bb = Bb + (wn + ni * 8 + gid) * PADH + kb + tig * 2;
                uint32_t b0 = *(const uint32_t*)(bb);
                uint32_t b1 = *(const uint32_t*)(bb + 8);
#pragma unroll
                for (int mi = 0; mi < 4; mi++)
                    mma_f16(acc[mi][ni], afr[mi], b0, b1);
            }
        }
    }

    float*  Cf = (float*)Cv;
    __half* Ch = (__half*)Cv;
#pragma unroll
    for (int mi = 0; mi < 4; mi++) {
        int rbase = bm + wm + mi * 16 + gid;
#pragma unroll
        for (int ni = 0; ni < NI; ni++) {
            int c0 = bn + wn + ni * 8 + tig * 2;
            if (NG && c0 >= Ndim) continue;
#pragma unroll
            for (int half_ = 0; half_ < 2; half_++) {
                int r0 = rbase + half_ * 8;
                float a0 = acc[mi][ni][half_ * 2 + 0];
                float a1 = acc[mi][ni][half_ * 2 + 1];
                if (OP == OP_NONE) {
                    *(float2*)(Cf + (size_t)r0 * Ndim + c0) = make_float2(a0, a1);
                } else if (OP == OP_HALF) {
                    *(__half2*)(Ch + (size_t)r0 * Ndim + c0) = __floats2half2_rn(a0, a1);
                } else if (OP == OP_SPLUS) {
                    float x0 = a0 + aux[c0], x1 = a1 + aux[c0 + 1];
                    x0 = (x0 > 20.f) ? x0 : log1pf(expf(x0));
                    x1 = (x1 > 20.f) ? x1 : log1pf(expf(x1));
                    *(float2*)(Cf + (size_t)r0 * Ndim + c0) = make_float2(x0, x1);
                } else if (OP == OP_SWIGLU) {
                    float sv = a0 * sigmoidf_(a0) * a1;
                    Ch[(size_t)r0 * IMc + (c0 >> 1)] = __float2half_rn(sv);
                } else if (OP == OP_ADDC) {
                    float2 r = *(const float2*)(aux + (size_t)r0 * Ndim + c0);
                    *(float2*)(Cf + (size_t)r0 * Ndim + c0) =
                        make_float2(a0 + r.x, a1 + r.y);
                }
            }
        }
    }
}

// ---------------- fused weight prep (single kernel) ----------------
#define W0 (FUSN*Hc)                 // wbig
#define W1 (W0 + KVSLD*Hc)           // wkv
#define W2 (W1 + GATEN*Hc)           // wg
#define W3 (W2 + PROJW*Ic)           // wxp
#define W4 (W3 + Ic*Rc)              // wdt
#define W5 (W4 + Hc*Ic)              // wop
#define W6 (W5 + Hc*NHc*HDc)         // wo
#define W7 (W6 + Hc*IMc)             // wd
__global__ void prep_weights(const float* __restrict__ ipw, const float* __restrict__ qw,
                             const float* __restrict__ kw, const float* __restrict__ vw,
                             const float* __restrict__ gw, const float* __restrict__ xpw,
                             const float* __restrict__ dtw, const float* __restrict__ opw,
                             const float* __restrict__ ow, const float* __restrict__ dw) {
    int idx = blockIdx.x * 256 + threadIdx.x;
    if (idx >= W7) return;
    if (idx < W0) {
        int row = idx >> 10, col = idx & 1023;
        float v;
        if (row < 4096)      v = ipw[idx];
        else if (row < 5120) v = qw[(row - 4096) * Hc + col];
        else if (row < 5376) v = kw[(row - 5120) * Hc + col];
        else                 v = vw[(row - 5376) * Hc + col];
        g_wbig[idx] = __float2half_rn(v);
    } else if (idx < W1) {
        int i = idx - W0;
        int row = i >> 10, col = i & 1023;
        float v = (row < 256) ? kw[row * Hc + col] : vw[(row - 256) * Hc + col];
        g_wkv[i] = __float2half_rn(v);
    } else if (idx < W2) {
        int i = idx - W1;
        int row = i >> 10, col = i & 1023;
        int f = row >> 1;
        int src = (row & 1) ? (IMc + f) : f;
        g_wg[i] = __float2half_rn(gw[src * Hc + col]);
    } else if (idx < W3) {
        int i = idx - W2; g_wxp[i] = __float2half_rn(xpw[i]);
    } else if (idx < W4) {
        int i = idx - W3; g_wdt[i] = __float2half_rn(dtw[i]);
    } else if (idx < W5) {
        int i = idx - W4; g_wop[i] = __float2half_rn(opw[i]);
    } else if (idx < W6) {
        int i = idx - W5; g_wo[i] = __float2half_rn(ow[i]);
    } else {
        int i = idx - W6; g_wd[i] = __float2half_rn(dw[i]);
    }
}

// ---------------- RMSNorm (+optional residual); nrm output half ----------------
__global__ void resid_rms(const float* __restrict__ a, const float* __restrict__ r,
                          const float* __restrict__ w, float* __restrict__ res_out,
                          __half* __restrict__ nrm_out) {
    int row = blockIdx.x;
    int t   = threadIdx.x;
    const float* ap = a + (size_t)row * Hc;
    const float* rp = r ? r + (size_t)row * Hc : nullptr;
    float v[4];
    float ss = 0.f;
#pragma unroll
    for (int i = 0; i < 4; i++) {
        int c = t + i * 256;
        float x = ap[c] + (rp ? rp[c] : 0.f);
        v[i] = x;
        ss += x * x;
    }
#pragma unroll
    for (int off = 16; off; off >>= 1) ss += __shfl_xor_sync(0xffffffffu, ss, off);
    __shared__ float sred[8];
    __shared__ float sscale;
    if ((t & 31) == 0) sred[t >> 5] = ss;
    __syncthreads();
    if (t == 0) {
        float tot = 0.f;
        for (int i = 0; i < 8; i++) tot += sred[i];
        sscale = rsqrtf(tot * (1.f / Hc) + EPSc);
    }
    __syncthreads();
    float scale = sscale;
    float* ro = res_out ? res_out + (size_t)row * Hc : nullptr;
    __half* no = nrm_out + (size_t)row * Hc;
#pragma unroll
    for (int i = 0; i < 4; i++) {
        int c = t + i * 256;
        if (ro) ro[c] = v[i];
        no[c] = __float2half_rn(v[i] * scale * w[c]);
    }
}

// ---------------- causal depthwise conv (K=4) + SiLU ----------------
__global__ void conv_silu(const float* __restrict__ cw, const float* __restrict__ cb) {
    int idx = blockIdx.x * blockDim.x + threadIdx.x;
    if (idx >= Mrows * Ic) return;
    int row = idx / Ic;
    int i   = idx - row * Ic;
    int b   = row / Sc;
    int s   = row - b * Sc;
    float acc = cb[i];
#pragma unroll
    for (int k = 0; k < Kcv; k++) {
        int sp = s + k - (Kcv - 1);
        if (sp >= 0)
            acc += cw[i * Kcv + k] * g_xzq[(size_t)(b * Sc + sp) * FUSN + i];
    }
    float r = acc * sigmoidf_(acc);
    g_xs[idx]  = r;
    g_xsh[idx] = __float2half_rn(r);
}

// ---------------- selective scan ----------------
__global__ void scan_kernel(const float* __restrict__ A_log, const float* __restrict__ Dp) {
    int t  = threadIdx.x;
    int c  = t >> 4;
    int n  = t & 15;
    int gi = blockIdx.x * 16 + c;
    int b  = gi / Ic;
    int i  = gi - b * Ic;
    float An = -expf(A_log[i * Nst + n]);
    float Dv = Dp[i];
    float h  = 0.f;
    for (int s = 0; s < Sc; s++) {
        int row = b * Sc + s;
        float dt = g_dt[(size_t)row * Ic + i];
        float xs = g_xs[(size_t)row * Ic + i];
        float Bn = __half2float(g_proj_h[row * PROJW + Rc + n]);
        float Cn = __half2float(g_proj_h[row * PROJW + Rc + Nst + n]);
        h = h * expf(dt * An) + dt * Bn * xs;
        float v = h * Cn;
        v += __shfl_xor_sync(0xffffffffu, v, 8);
        v += __shfl_xor_sync(0xffffffffu, v, 4);
        v += __shfl_xor_sync(0xffffffffu, v, 2);
        v += __shfl_xor_sync(0xffffffffu, v, 1);
        if (n == 0) {
            float z  = g_xzq[(size_t)row * FUSN + Ic + i];
            float yv = (v + Dv * xs) * (z * sigmoidf_(z));
            g_y[(size_t)row * Ic + i] = __float2half_rn(yv);
        }
    }
}

// ---------------- rotary: fp32 strided src -> compact half dst ----------------
__global__ void rotary_half(const float* __restrict__ src, int ld, int coloff,
                            __half* __restrict__ dst, int nheads) {
    int idx = blockIdx.x * blockDim.x + threadIdx.x;
    int tot = Mrows * nheads * 32;
    if (idx >= tot) return;
    int r    = idx / (nheads * 32);
    int rem  = idx - r * (nheads * 32);
    int head = rem >> 5;
    int j    = rem & 31;
    int s    = r % Sc;
    float inv = expf(-((float)(2 * j) / (float)HDc) * logf(10000.0f));
    float f = (float)s * inv;
    float sn, cs;
    sincosf(f, &sn, &cs);
    const float* bi = src + (size_t)r * ld + coloff + head * HDc;
    __half* bo = dst + (size_t)r * nheads * HDc + head * HDc;
    float x1 = bi[j], x2 = bi[j + 32];
    bo[j]      = __float2half_rn(x1 * cs - x2 * sn);
    bo[j + 32] = __float2half_rn(x2 * cs + x1 * sn);
}

// ---------------- v copy: fp32 -> compact half (both v_att and v_ssm) ----------------
__global__ void copy_vh() {
    int idx = blockIdx.x * blockDim.x + threadIdx.x;
    if (idx >= Mrows * 512) return;
    int r   = idx >> 9;
    int col = idx & 511;
    if (col < 256)
        g_vah[r * 256 + col] = __float2half_rn(g_xzq[(size_t)r * FUSN + 5376 + col]);
    else
        g_vsh[r * 256 + (col - 256)] = __float2half_rn(g_kvssm[(size_t)r * KVSLD + 256 + (col - 256)]);
}

// ---------------- dual-window attention v3: 16 q/block, half compact operands ----------------
// dynamic smem: sc[16][640] | tile[64][65] | qs[16][64]
#define ATT_SC   (16 * (WATT + WSSM))      // 10240 floats
#define ATT_TILE (64 * 65)                 // 4160 floats
#define ATT_QS   (16 * 64)                 // 1024 floats
#define ATT_SMEM ((ATT_SC + ATT_TILE + ATT_QS) * 4)

__global__ __launch_bounds__(512) void attn3() {
    extern __shared__ float dyn[];
    float* sc   = dyn;                       // [16][640]
    float* tile = dyn + ATT_SC;              // [64][65]
    float* qs   = dyn + ATT_SC + ATT_TILE;   // [16][64]
    int t    = threadIdx.x;
    int w    = t >> 5;
    int lane = t & 31;
    int q0   = blockIdx.x * 16;
    int h    = blockIdx.y;
    int b    = blockIdx.z;
    int rowb = b * Sc;
    int qi   = q0 + w;
    int hk   = h >> 2;

    {
        const __half* qp = g_qh + (size_t)(rowb + qi) * (NHc * HDc) + h * HDc;
        qs[w * 64 + lane]      = __half2float(qp[lane]);
        qs[w * 64 + lane + 32] = __half2float(qp[lane + 32]);
    }

    int ka = max(0, qi - (WATT - 1)), na = qi - ka + 1;
    int ks = max(0, qi - (WSSM - 1)), ns = qi - ks + 1;
    int caStart = max(0, q0 - (WATT - 1)) & ~63;
    int csStart = max(0, q0 - (WSSM - 1)) & ~63;
    int qe = q0 + 15;

    // load a 64-key tile from compact half buffer; transposed (QK) or row (PV)
    auto load_tile_T = [&](const __half* base) {
        int r  = t >> 3;            // key in tile
        int d8 = (t & 7) * 8;       // dim group
        int key = r;                // caller adds c via pointer
        (void)key;
#pragma unroll
        for (int j = 0; j < 8; j++) { } // (placeholder removed below)
    };
    (void)load_tile_T;

    // ---- QK passes ----
    for (int pass = 0; pass < 2; pass++) {
        const __half* kbuf = pass == 0 ? g_kah : g_ksh;
        int cs  = pass == 0 ? caStart : csStart;
        int kb0 = pass == 0 ? ka : ks;
        int off = pass == 0 ? 0 : WATT;
        int kql = pass == 0 ? qi : qi;
        for (int c = cs; c <= qe; c += 64) {
            __syncthreads();
            {
                int r  = t >> 3;
                int d8 = (t & 7) * 8;
                int key = c + r;
                if (key < Sc) {
                    const __half* kp = kbuf + (size_t)(rowb + key) * (NKVc * HDc) + hk * HDc + d8;
                    uint4 u = *(const uint4*)kp;
                    const __half2* h2 = (const __half2*)&u;
#pragma unroll
                    for (int j = 0; j < 4; j++) {
                        float2 f2 = __half22float2(h2[j]);
                        tile[(d8 + 2 * j) * 65 + r]     = f2.x;
                        tile[(d8 + 2 * j + 1) * 65 + r] = f2.y;
                    }
                } else {
#pragma unroll
                    for (int j = 0; j < 8; j++) tile[(d8 + j) * 65 + r] = 0.f;
                }
            }
            __syncthreads();
            float a0 = 0.f, a1 = 0.f;
#pragma unroll 8
            for (int d = 0; d < 64; d++) {
                float qd = qs[w * 64 + d];
                a0 = fmaf(qd, tile[d * 65 + lane], a0);
                a1 = fmaf(qd, tile[d * 65 + lane + 32], a1);
            }
            int k0 = c + lane, k1 = c + lane + 32;
            if (k0 >= kb0 && k0 <= kql) sc[w * (WATT + WSSM) + off + k0 - kb0] = a0 * 0.125f;
            if (k1 >= kb0 && k1 <= kql) sc[w * (WATT + WSSM) + off + k1 - kb0] = a1 * 0.125f;
        }
    }
    __syncwarp();

    // ---- softmax (warp-local) ----
    float* scw = sc + w * (WATT + WSSM);
    float mx = -1e30f;
    for (int j = lane; j < na; j += 32) mx = fmaxf(mx, scw[j]);
    for (int j = lane; j < ns; j += 32) mx = fmaxf(mx, scw[WATT + j]);
#pragma unroll
    for (int off = 16; off; off >>= 1) mx = fmaxf(mx, __shfl_xor_sync(0xffffffffu, mx, off));
    float sum = 0.f;
    for (int j = lane; j < na; j += 32) { float e = expf(scw[j] - mx); scw[j] = e; sum += e; }
    for (int j = lane; j < ns; j += 32) { float e = expf(scw[WATT + j] - mx); scw[WATT + j] = e; sum += e; }
#pragma unroll
    for (int off = 16; off; off >>= 1) sum += __shfl_xor_sync(0xffffffffu, sum, off);
    float invs = 1.f / sum;
    __syncwarp();

    // ---- PV passes ----
    float o0 = 0.f, o1 = 0.f;
    for (int pass = 0; pass < 2; pass++) {
        const __half* vbuf = pass == 0 ? g_vah : g_vsh;
        int cs  = pass == 0 ? caStart : csStart;
        int kb0 = pass == 0 ? ka : ks;
        int off = pass == 0 ? 0 : WATT;
        for (int c = cs; c <= qe; c += 64) {
            __syncthreads();
            {
                int r  = t >> 3;
                int d8 = (t & 7) * 8;
                int key = c + r;
                if (key < Sc) {
                    const __half* vp = vbuf + (size_t)(rowb + key) * (NKVc * HDc) + hk * HDc + d8;
                    uint4 u = *(const uint4*)vp;
                    const __half2* h2 = (const __half2*)&u;
#pragma unroll
                    for (int j = 0; j < 4; j++) {
                        float2 f2 = __half22float2(h2[j]);
                        tile[r * 65 + d8 + 2 * j]     = f2.x;
                        tile[r * 65 + d8 + 2 * j + 1] = f2.y;
                    }
                } else {
#pragma unroll
                    for (int j = 0; j < 8; j++) tile[r * 65 + d8 + j] = 0.f;
                }
            }
            __syncthreads();
#pragma unroll 4
            for (int j = 0; j < 64; j++) {
                int key = c + j;
                float p = (key >= kb0 && key <= qi) ? scw[off + key - kb0] : 0.f;
                o0 = fmaf(p, tile[j * 65 + lane], o0);
                o1 = fmaf(p, tile[j * 65 + lane + 32], o1);
            }
        }
    }

    __half* op = g_oh + (size_t)(rowb + qi) * NHc * HDc + h * HDc;
    op[lane]      = __float2half_rn(o0 * invs);
    op[lane + 32] = __float2half_rn(o1 * invs);
}

// ---------------- host launcher ----------------
extern "C" void kernel_launch(void* const* d_in, const int* in_sizes, int n_in,
                              void* d_out, int out_size) {
    const float* hidden      = (const float*)d_in[0];
    const float* pre_norm_w  = (const float*)d_in[1];
    const float* in_proj_w   = (const float*)d_in[2];
    const float* conv_w      = (const float*)d_in[3];
    const float* conv_b      = (const float*)d_in[4];
    const float* x_proj_w    = (const float*)d_in[5];
    const float* dt_proj_w   = (const float*)d_in[6];
    const float* dt_proj_b   = (const float*)d_in[7];
    const float* A_log       = (const float*)d_in[8];
    const float* Dp          = (const float*)d_in[9];
    const float* out_proj_w  = (const float*)d_in[10];
    const float* ssm_norm_w  = (const float*)d_in[11];
    const float* q_w         = (const float*)d_in[12];
    const float* k_w         = (const float*)d_in[13];
    const float* v_w         = (const float*)d_in[14];
    const float* o_w         = (const float*)d_in[15];
    const float* mlp_norm_w  = (const float*)d_in[16];
    const float* gate_w      = (const float*)d_in[17];
    const float* down_w      = (const float*)d_in[18];
    float* out = (float*)d_out;

    const int smem128 = (BM * PADH + 128 * PADH) * STAGES * 2;  // 81920
    const int smem64  = (BM * PADH + 64 * PADH) * STAGES * 2;   // 61440
    cudaFuncSetAttribute(gemm_h<128, OP_NONE,  false>, cudaFuncAttributeMaxDynamicSharedMemorySize, smem128);
    cudaFuncSetAttribute(gemm_h<128, OP_SPLUS, false>, cudaFuncAttributeMaxDynamicSharedMemorySize, smem128);
    cudaFuncSetAttribute(gemm_h<128, OP_SWIGLU,false>, cudaFuncAttributeMaxDynamicSharedMemorySize, smem128);
    cudaFuncSetAttribute(gemm_h<64,  OP_HALF,  true >, cudaFuncAttributeMaxDynamicSharedMemorySize, smem64);
    cudaFuncSetAttribute(gemm_h<64,  OP_NONE,  false>, cudaFuncAttributeMaxDynamicSharedMemorySize, smem64);
    cudaFuncSetAttribute(gemm_h<64,  OP_ADDC,  false>, cudaFuncAttributeMaxDynamicSharedMemorySize, smem64);
    cudaFuncSetAttribute(attn3, cudaFuncAttributeMaxDynamicSharedMemorySize, ATT_SMEM);

    __half *hs, *xsh, *proj_h, *y, *ssmst, *oh, *x2, *hm;
    __half *wbig, *wxp, *wdt, *wop, *wkv, *wo, *wg, *wd;
    float *xzq, *xs, *dt, *tmp, *ssmres, *kvssm, *mlpres;
    cudaGetSymbolAddress((void**)&hs, g_hs);
    cudaGetSymbolAddress((void**)&xzq, g_xzq);
    cudaGetSymbolAddress((void**)&xs, g_xs);
    cudaGetSymbolAddress((void**)&xsh, g_xsh);
    cudaGetSymbolAddress((void**)&proj_h, g_proj_h);
    cudaGetSymbolAddress((void**)&dt, g_dt);
    cudaGetSymbolAddress((void**)&y, g_y);
    cudaGetSymbolAddress((void**)&tmp, g_tmp);
    cudaGetSymbolAddress((void**)&ssmres, g_ssmres);
    cudaGetSymbolAddress((void**)&ssmst, g_ssmst);
    cudaGetSymbolAddress((void**)&kvssm, g_kvssm);
    cudaGetSymbolAddress((void**)&oh, g_oh);
    cudaGetSymbolAddress((void**)&mlpres, g_mlpres);
    cudaGetSymbolAddress((void**)&x2, g_x2);
    cudaGetSymbolAddress((void**)&hm, g_hm);
    cudaGetSymbolAddress((void**)&wbig, g_wbig);
    cudaGetSymbolAddress((void**)&wxp, g_wxp);
    cudaGetSymbolAddress((void**)&wdt, g_wdt);
    cudaGetSymbolAddress((void**)&wop, g_wop);
    cudaGetSymbolAddress((void**)&wkv, g_wkv);
    cudaGetSymbolAddress((void**)&wo, g_wo);
    cudaGetSymbolAddress((void**)&wg, g_wg);
    cudaGetSymbolAddress((void**)&wd, g_wd);
    __half *qh, *kah, *ksh;
    cudaGetSymbolAddress((void**)&qh, g_qh);
    cudaGetSymbolAddress((void**)&kah, g_kah);
    cudaGetSymbolAddress((void**)&ksh, g_ksh);

    // 0. fused weight prep
    prep_weights<<<(W7 + 255) / 256, 256>>>(in_proj_w, q_w, k_w, v_w, gate_w,
                                            x_proj_w, dt_proj_w, out_proj_w, o_w, down_w);
    // 1. pre-norm
    resid_rms<<<Mrows, 256>>>(hidden, nullptr, pre_norm_w, nullptr, hs);
    // 2. fused xz|q|k|v (2048 x 5632, K=1024)
    gemm_h<128, OP_NONE, false><<<dim3(FUSN / 128, Mrows / BM), 128, smem128>>>(
        hs, wbig, xzq, nullptr, FUSN, Hc, Hc, Hc);
    // 3. conv + silu
    conv_silu<<<(Mrows * Ic) / 256, 256>>>(conv_w, conv_b);
    // 4. x_proj (2048 x 96, K=2048) -> half
    gemm_h<64, OP_HALF, true><<<dim3(2, Mrows / BM), 128, smem64>>>(
        xsh, wxp, proj_h, nullptr, PROJW, Ic, Ic, Ic);
    // 5. dt GEMM (profiled by ncu -s 5)
    gemm_h<128, OP_SPLUS, false><<<dim3(Ic / 128, Mrows / BM), 128, smem128>>>(
        proj_h, wdt, dt, dt_proj_b, Ic, Rc, PROJW, Rc);
    // 6. selective scan
    scan_kernel<<<(Bc * Ic) / 16, 256>>>(A_log, Dp);
    // 7. out_proj; residual + norm
    gemm_h<64, OP_NONE, false><<<dim3(Hc / 64, Mrows / BM), 128, smem64>>>(
        y, wop, tmp, nullptr, Hc, Ic, Ic, Ic);
    resid_rms<<<Mrows, 256>>>(tmp, hidden, ssm_norm_w, ssmres, ssmst);
    // 8. kv_ssm
    gemm_h<64, OP_NONE, false><<<dim3(KVSLD / 64, Mrows / BM), 128, smem64>>>(
        ssmst, wkv, kvssm, nullptr, KVSLD, Hc, Hc, Hc);
    // 9. rotary -> compact half; v copies
    rotary_half<<<(Mrows * NHc * 32) / 256, 256>>>(xzq, FUSN, 4096, qh, NHc);
    rotary_half<<<(Mrows * NKVc * 32) / 256, 256>>>(xzq, FUSN, 5120, kah, NKVc);
    rotary_half<<<(Mrows * NKVc * 32) / 256, 256>>>(kvssm, KVSLD, 0, ksh, NKVc);
    copy_vh<<<(Mrows * 512) / 256, 256>>>();
    // 10. attention (16 q/block)
    attn3<<<dim3(Sc / 16, NHc, Bc), 512, ATT_SMEM>>>();
    // 11. o proj; residual + norm
    gemm_h<64, OP_NONE, false><<<dim3(Hc / 64, Mrows / BM), 128, smem64>>>(
        oh, wo, tmp, nullptr, Hc, NHc * HDc, NHc * HDc, NHc * HDc);
    resid_rms<<<Mrows, 256>>>(tmp, ssmres, mlp_norm_w, mlpres, x2);
    // 12. MLP
    gemm_h<128, OP_SWIGLU, false><<<dim3(GATEN / 128, Mrows / BM), 128, smem128>>>(
        x2, wg, hm, nullptr, GATEN, Hc, Hc, Hc);
    gemm_h<64, OP_ADDC, false><<<dim3(Hc / 64, Mrows / BM), 128, smem64>>>(
        hm, wd, out, mlpres, Hc, IMc, IMc, IMc);
}

// round 10
// speedup vs baseline: 1.6481x; 1.3221x over previous
#include <cuda_runtime.h>
#include <cuda_fp16.h>
#include <math.h>
#include <stdint.h>

// ---------------- problem constants ----------------
#define Bc   2
#define Sc   1024
#define Hc   1024
#define Ic   2048
#define Nst  16
#define Rc   64
#define Kcv  4
#define NHc  16
#define NKVc 4
#define HDc  64
#define WATT 512
#define WSSM 128
#define IMc  2816
#define Mrows (Bc*Sc)
#define EPSc  1e-6f
#define PROJW (Rc + 2*Nst)   // 96
#define FUSN  5632
#define KVSLD 512
#define GATEN 5632

// ---------------- scratch ----------------
__device__ __half g_hs[Mrows*Hc];
__device__ float  g_xzq[Mrows*FUSN];
__device__ float  g_xs[Mrows*Ic];
__device__ __half g_xsh[Mrows*Ic];
__device__ __half g_proj_h[Mrows*PROJW];
__device__ float  g_dt[Mrows*Ic];
__device__ __half g_y[Mrows*Ic];
__device__ float  g_tmp[Mrows*Hc];
__device__ float  g_ssmres[Mrows*Hc];
__device__ __half g_ssmst[Mrows*Hc];
__device__ float  g_kvssm[Mrows*KVSLD];
__device__ __half g_oh[Mrows*NHc*HDc];
__device__ float  g_mlpres[Mrows*Hc];
__device__ __half g_x2[Mrows*Hc];
__device__ __half g_hm[Mrows*IMc];
// compact half attention operands
__device__ __half g_qh[Mrows*NHc*HDc];
__device__ __half g_kah[Mrows*NKVc*HDc];
__device__ __half g_ksh[Mrows*NKVc*HDc];
__device__ __half g_vah[Mrows*NKVc*HDc];
__device__ __half g_vsh[Mrows*NKVc*HDc];
// half weights
__device__ __half g_wbig[FUSN*Hc];
__device__ __half g_wxp[PROJW*Ic];
__device__ __half g_wdt[Ic*Rc];
__device__ __half g_wop[Hc*Ic];
__device__ __half g_wkv[KVSLD*Hc];
__device__ __half g_wo[Hc*NHc*HDc];
__device__ __half g_wg[GATEN*Hc];
__device__ __half g_wd[Hc*IMc];

__device__ __forceinline__ float sigmoidf_(float x) { return 1.f / (1.f + expf(-x)); }

// ---------------- fp16 MMA primitives ----------------
#define BM 128
#define BK 32
#define PADH 40
#define STAGES 4

#define OP_NONE   0
#define OP_HALF   1
#define OP_SPLUS  2
#define OP_SWIGLU 3
#define OP_ADDC   4

__device__ __forceinline__ void cp16(uint32_t dst, const void* src, int ssize) {
    asm volatile("cp.async.cg.shared.global [%0], [%1], 16, %2;\n"
                 :: "r"(dst), "l"(src), "r"(ssize));
}
__device__ __forceinline__ void mma_f16(float* c, const uint32_t* a, uint32_t b0, uint32_t b1) {
    asm volatile("mma.sync.aligned.m16n8k16.row.col.f32.f16.f16.f32 "
                 "{%0,%1,%2,%3}, {%4,%5,%6,%7}, {%8,%9}, {%0,%1,%2,%3};\n"
                 : "+f"(c[0]), "+f"(c[1]), "+f"(c[2]), "+f"(c[3])
                 : "r"(a[0]), "r"(a[1]), "r"(a[2]), "r"(a[3]), "r"(b0), "r"(b1));
}

template<int BNT, int OP, bool NG>
__global__ __launch_bounds__(128, 2)
void gemm_h(const __half* __restrict__ A, const __half* __restrict__ Bw,
            void* __restrict__ Cv, const float* __restrict__ aux,
            int Ndim, int Kdim, int lda, int ldb) {
    constexpr int NI  = BNT / 16;
    constexpr int ASZ = BM * PADH;
    constexpr int BSZ = BNT * PADH;
    constexpr int STG = ASZ + BSZ;
    extern __shared__ __half smh[];
    const int t    = threadIdx.x;
    const int bm   = blockIdx.y * BM;
    const int bn   = blockIdx.x * BNT;
    const int warp = t >> 5, lane = t & 31;
    const int wm   = (warp & 1) * 64;
    const int wn   = (warp >> 1) * (BNT / 2);
    const int gid  = lane >> 2;
    const int tig  = lane & 3;
    const uint32_t smem_base = (uint32_t)__cvta_generic_to_shared(smh);

    float acc[4][NI][4];
#pragma unroll
    for (int mi = 0; mi < 4; mi++)
#pragma unroll
        for (int ni = 0; ni < NI; ni++)
#pragma unroll
            for (int j = 0; j < 4; j++) acc[mi][ni][j] = 0.f;

    const int niters = Kdim / BK;

    auto load_tile = [&](int slot, int k0) {
        uint32_t aOff = smem_base + slot * STG * 2;
        uint32_t bOff = aOff + ASZ * 2;
#pragma unroll
        for (int i = 0; i < 4; i++) {
            int id = t + i * 128;
            int r  = id >> 2;
            int kq = (id & 3) * 8;
            cp16(aOff + (r * PADH + kq) * 2, A + (size_t)(bm + r) * lda + k0 + kq, 16);
        }
#pragma unroll
        for (int i = 0; i < BNT / 32; i++) {
            int id = t + i * 128;
            int r  = id >> 2;
            int kq = (id & 3) * 8;
            int ok = 1;
            int br = bn + r;
            if (NG) ok = (br < Ndim);
            cp16(bOff + (r * PADH + kq) * 2,
                 Bw + (size_t)(NG ? (ok ? br : 0) : br) * ldb + k0 + kq, ok ? 16 : 0);
        }
    };

#pragma unroll
    for (int s = 0; s < STAGES - 1; s++) {
        if (s < niters) load_tile(s, s * BK);
        asm volatile("cp.async.commit_group;\n");
    }

    int cslot = 0, nslot = STAGES - 1;
    for (int it = 0; it < niters; it++) {
        asm volatile("cp.async.wait_group %0;\n" :: "n"(STAGES - 2));
        __syncthreads();
        int nk = it + STAGES - 1;
        if (nk < niters) load_tile(nslot, nk * BK);
        asm volatile("cp.async.commit_group;\n");
        if (++nslot == STAGES) nslot = 0;

        const __half* Ab = smh + cslot * STG;
        const __half* Bb = Ab + ASZ;
        if (++cslot == STAGES) cslot = 0;
#pragma unroll
        for (int kk = 0; kk < 2; kk++) {
            int kb = kk * 16;
            uint32_t afr[4][4];
#pragma unroll
            for (int mi = 0; mi < 4; mi++) {
                const __half* ab = Ab + (wm + mi * 16 + gid) * PADH + kb + tig * 2;
                afr[mi][0] = *(const uint32_t*)(ab);
                afr[mi][1] = *(const uint32_t*)(ab + 8 * PADH);
                afr[mi][2] = *(const uint32_t*)(ab + 8);
                afr[mi][3] = *(const uint32_t*)(ab + 8 * PADH + 8);
            }
#pragma unroll
            for (int ni = 0; ni < NI; ni++) {
                const __half* bb = Bb + (wn + ni * 8 + gid) * PADH + kb + tig * 2;
                uint32_t b0 = *(const uint32_t*)(bb);
                uint32_t b1 = *(const uint32_t*)(bb + 8);
#pragma unroll
                for (int mi = 0; mi < 4; mi++)
                    mma_f16(acc[mi][ni], afr[mi], b0, b1);
            }
        }
    }

    float*  Cf = (float*)Cv;
    __half* Ch = (__half*)Cv;
#pragma unroll
    for (int mi = 0; mi < 4; mi++) {
        int rbase = bm + wm + mi * 16 + gid;
#pragma unroll
        for (int ni = 0; ni < NI; ni++) {
            int c0 = bn + wn + ni * 8 + tig * 2;
            if (NG && c0 >= Ndim) continue;
#pragma unroll
            for (int half_ = 0; half_ < 2; half_++) {
                int r0 = rbase + half_ * 8;
                float a0 = acc[mi][ni][half_ * 2 + 0];
                float a1 = acc[mi][ni][half_ * 2 + 1];
                if (OP == OP_NONE) {
                    *(float2*)(Cf + (size_t)r0 * Ndim + c0) = make_float2(a0, a1);
                } else if (OP == OP_HALF) {
                    *(__half2*)(Ch + (size_t)r0 * Ndim + c0) = __floats2half2_rn(a0, a1);
                } else if (OP == OP_SPLUS) {
                    float x0 = a0 + aux[c0], x1 = a1 + aux[c0 + 1];
                    x0 = (x0 > 20.f) ? x0 : log1pf(expf(x0));
                    x1 = (x1 > 20.f) ? x1 : log1pf(expf(x1));
                    *(float2*)(Cf + (size_t)r0 * Ndim + c0) = make_float2(x0, x1);
                } else if (OP == OP_SWIGLU) {
                    float sv = a0 * sigmoidf_(a0) * a1;
                    Ch[(size_t)r0 * IMc + (c0 >> 1)] = __float2half_rn(sv);
                } else if (OP == OP_ADDC) {
                    float2 r = *(const float2*)(aux + (size_t)r0 * Ndim + c0);
                    *(float2*)(Cf + (size_t)r0 * Ndim + c0) =
                        make_float2(a0 + r.x, a1 + r.y);
                }
            }
        }
    }
}

// ---------------- fused weight prep ----------------
#define W0 (FUSN*Hc)
#define W1 (W0 + KVSLD*Hc)
#define W2 (W1 + GATEN*Hc)
#define W3 (W2 + PROJW*Ic)
#define W4 (W3 + Ic*Rc)
#define W5 (W4 + Hc*Ic)
#define W6 (W5 + Hc*NHc*HDc)
#define W7 (W6 + Hc*IMc)
__global__ void prep_weights(const float* __restrict__ ipw, const float* __restrict__ qw,
                             const float* __restrict__ kw, const float* __restrict__ vw,
                             const float* __restrict__ gw, const float* __restrict__ xpw,
                             const float* __restrict__ dtw, const float* __restrict__ opw,
                             const float* __restrict__ ow, const float* __restrict__ dw) {
    int idx = blockIdx.x * 256 + threadIdx.x;
    if (idx >= W7) return;
    if (idx < W0) {
        int row = idx >> 10, col = idx & 1023;
        float v;
        if (row < 4096)      v = ipw[idx];
        else if (row < 5120) v = qw[(row - 4096) * Hc + col];
        else if (row < 5376) v = kw[(row - 5120) * Hc + col];
        else                 v = vw[(row - 5376) * Hc + col];
        g_wbig[idx] = __float2half_rn(v);
    } else if (idx < W1) {
        int i = idx - W0;
        int row = i >> 10, col = i & 1023;
        float v = (row < 256) ? kw[row * Hc + col] : vw[(row - 256) * Hc + col];
        g_wkv[i] = __float2half_rn(v);
    } else if (idx < W2) {
        int i = idx - W1;
        int row = i >> 10, col = i & 1023;
        int f = row >> 1;
        int src = (row & 1) ? (IMc + f) : f;
        g_wg[i] = __float2half_rn(gw[src * Hc + col]);
    } else if (idx < W3) {
        int i = idx - W2; g_wxp[i] = __float2half_rn(xpw[i]);
    } else if (idx < W4) {
        int i = idx - W3; g_wdt[i] = __float2half_rn(dtw[i]);
    } else if (idx < W5) {
        int i = idx - W4; g_wop[i] = __float2half_rn(opw[i]);
    } else if (idx < W6) {
        int i = idx - W5; g_wo[i] = __float2half_rn(ow[i]);
    } else {
        int i = idx - W6; g_wd[i] = __float2half_rn(dw[i]);
    }
}

// ---------------- RMSNorm ----------------
__global__ void resid_rms(const float* __restrict__ a, const float* __restrict__ r,
                          const float* __restrict__ w, float* __restrict__ res_out,
                          __half* __restrict__ nrm_out) {
    int row = blockIdx.x;
    int t   = threadIdx.x;
    const float* ap = a + (size_t)row * Hc;
    const float* rp = r ? r + (size_t)row * Hc : nullptr;
    float v[4];
    float ss = 0.f;
#pragma unroll
    for (int i = 0; i < 4; i++) {
        int c = t + i * 256;
        float x = ap[c] + (rp ? rp[c] : 0.f);
        v[i] = x;
        ss += x * x;
    }
#pragma unroll
    for (int off = 16; off; off >>= 1) ss += __shfl_xor_sync(0xffffffffu, ss, off);
    __shared__ float sred[8];
    __shared__ float sscale;
    if ((t & 31) == 0) sred[t >> 5] = ss;
    __syncthreads();
    if (t == 0) {
        float tot = 0.f;
        for (int i = 0; i < 8; i++) tot += sred[i];
        sscale = rsqrtf(tot * (1.f / Hc) + EPSc);
    }
    __syncthreads();
    float scale = sscale;
    float* ro = res_out ? res_out + (size_t)row * Hc : nullptr;
    __half* no = nrm_out + (size_t)row * Hc;
#pragma unroll
    for (int i = 0; i < 4; i++) {
        int c = t + i * 256;
        if (ro) ro[c] = v[i];
        no[c] = __float2half_rn(v[i] * scale * w[c]);
    }
}

// ---------------- causal depthwise conv (K=4) + SiLU ----------------
__global__ void conv_silu(const float* __restrict__ cw, const float* __restrict__ cb) {
    int idx = blockIdx.x * blockDim.x + threadIdx.x;
    if (idx >= Mrows * Ic) return;
    int row = idx / Ic;
    int i   = idx - row * Ic;
    int b   = row / Sc;
    int s   = row - b * Sc;
    float acc = cb[i];
#pragma unroll
    for (int k = 0; k < Kcv; k++) {
        int sp = s + k - (Kcv - 1);
        if (sp >= 0)
            acc += cw[i * Kcv + k] * g_xzq[(size_t)(b * Sc + sp) * FUSN + i];
    }
    float r = acc * sigmoidf_(acc);
    g_xs[idx]  = r;
    g_xsh[idx] = __float2half_rn(r);
}

// ---------------- selective scan ----------------
__global__ void scan_kernel(const float* __restrict__ A_log, const float* __restrict__ Dp) {
    int t  = threadIdx.x;
    int c  = t >> 4;
    int n  = t & 15;
    int gi = blockIdx.x * 16 + c;
    int b  = gi / Ic;
    int i  = gi - b * Ic;
    float An = -expf(A_log[i * Nst + n]);
    float Dv = Dp[i];
    float h  = 0.f;
    for (int s = 0; s < Sc; s++) {
        int row = b * Sc + s;
        float dt = g_dt[(size_t)row * Ic + i];
        float xs = g_xs[(size_t)row * Ic + i];
        float Bn = __half2float(g_proj_h[row * PROJW + Rc + n]);
        float Cn = __half2float(g_proj_h[row * PROJW + Rc + Nst + n]);
        h = h * expf(dt * An) + dt * Bn * xs;
        float v = h * Cn;
        v += __shfl_xor_sync(0xffffffffu, v, 8);
        v += __shfl_xor_sync(0xffffffffu, v, 4);
        v += __shfl_xor_sync(0xffffffffu, v, 2);
        v += __shfl_xor_sync(0xffffffffu, v, 1);
        if (n == 0) {
            float z  = g_xzq[(size_t)row * FUSN + Ic + i];
            float yv = (v + Dv * xs) * (z * sigmoidf_(z));
            g_y[(size_t)row * Ic + i] = __float2half_rn(yv);
        }
    }
}

// ---------------- rotary: fp32 strided src -> compact half dst ----------------
__global__ void rotary_half(const float* __restrict__ src, int ld, int coloff,
                            __half* __restrict__ dst, int nheads) {
    int idx = blockIdx.x * blockDim.x + threadIdx.x;
    int tot = Mrows * nheads * 32;
    if (idx >= tot) return;
    int r    = idx / (nheads * 32);
    int rem  = idx - r * (nheads * 32);
    int head = rem >> 5;
    int j    = rem & 31;
    int s    = r % Sc;
    float inv = expf(-((float)(2 * j) / (float)HDc) * logf(10000.0f));
    float f = (float)s * inv;
    float sn, cs;
    sincosf(f, &sn, &cs);
    const float* bi = src + (size_t)r * ld + coloff + head * HDc;
    __half* bo = dst + (size_t)r * nheads * HDc + head * HDc;
    float x1 = bi[j], x2 = bi[j + 32];
    bo[j]      = __float2half_rn(x1 * cs - x2 * sn);
    bo[j + 32] = __float2half_rn(x2 * cs + x1 * sn);
}

// ---------------- v copy: fp32 -> compact half ----------------
__global__ void copy_vh() {
    int idx = blockIdx.x * blockDim.x + threadIdx.x;
    if (idx >= Mrows * 512) return;
    int r   = idx >> 9;
    int col = idx & 511;
    if (col < 256)
        g_vah[r * 256 + col] = __float2half_rn(g_xzq[(size_t)r * FUSN + 5376 + col]);
    else
        g_vsh[r * 256 + (col - 256)] = __float2half_rn(g_kvssm[(size_t)r * KVSLD + 256 + (col - 256)]);
}

// ---------------- attn4: FA2-style MMA attention ----------------
// block = 64 queries x 1 head; 128 threads (4 warps x 16-q m-tiles).
// Joint online softmax over att(W=512) + ssm(W=128) windows; key tiles descend
// from c=q0 so the first tile is fully valid for every row.
__global__ __launch_bounds__(128) void attn4() {
    __shared__ __half Kt[64][72];
    __shared__ __half Vt[64][72];
    int t = threadIdx.x, w = t >> 5, lane = t & 31;
    int g = lane >> 2, tig = lane & 3;
    int q0 = blockIdx.x * 64, h = blockIdx.y, b = blockIdx.z;
    int rowb = b * Sc, hk = h >> 2;
    int qr0 = q0 + w * 16 + g;
    int qr1 = qr0 + 8;

    // Q fragments (scaled later), loaded once
    uint32_t qf[4][4];
    {
        const __half* qb = g_qh + (size_t)rowb * 1024 + h * HDc;
#pragma unroll
        for (int kk = 0; kk < 4; kk++) {
            const __half* r0 = qb + (size_t)qr0 * 1024 + kk * 16 + tig * 2;
            const __half* r1 = qb + (size_t)qr1 * 1024 + kk * 16 + tig * 2;
            qf[kk][0] = *(const uint32_t*)(r0);
            qf[kk][1] = *(const uint32_t*)(r1);
            qf[kk][2] = *(const uint32_t*)(r0 + 8);
            qf[kk][3] = *(const uint32_t*)(r1 + 8);
        }
    }

    float O[8][4];
#pragma unroll
    for (int nt = 0; nt < 8; nt++)
#pragma unroll
        for (int e = 0; e < 4; e++) O[nt][e] = 0.f;
    float m0 = -1e30f, m1 = -1e30f, l0 = 0.f, l1 = 0.f;

    for (int pass = 0; pass < 2; pass++) {
        const __half* kb = pass ? g_ksh : g_kah;
        const __half* vb = pass ? g_vsh : g_vah;
        int W  = pass ? WSSM : WATT;
        int cs = max(0, q0 - (W - 1)) & ~63;
        for (int c = q0; c >= cs; c -= 64) {
            __syncthreads();
            // load K tile (key-major) and V tile transposed (dim-major)
#pragma unroll
            for (int i = 0; i < 4; i++) {
                int id = t + i * 128;
                int r  = id >> 3;
                int c8 = (id & 7) * 8;
                size_t src = (size_t)(rowb + c + r) * 256 + hk * HDc + c8;
                *(uint4*)&Kt[r][c8] = *(const uint4*)(kb + src);
                uint4 vv = *(const uint4*)(vb + src);
                const __half* hv = (const __half*)&vv;
#pragma unroll
                for (int j = 0; j < 8; j++) Vt[c8 + j][r] = hv[j];
            }
            __syncthreads();

            // S = Q K^T  (16 x 64 per warp)
            float S[8][4];
#pragma unroll
            for (int nt = 0; nt < 8; nt++)
#pragma unroll
                for (int e = 0; e < 4; e++) S[nt][e] = 0.f;
#pragma unroll
            for (int kk = 0; kk < 4; kk++)
#pragma unroll
                for (int nt = 0; nt < 8; nt++) {
                    const __half* kp = &Kt[nt * 8 + g][kk * 16 + tig * 2];
                    uint32_t b0 = *(const uint32_t*)kp;
                    uint32_t b1 = *(const uint32_t*)(kp + 8);
                    mma_f16(S[nt], qf[kk], b0, b1);
                }

            // mask + scale; tile-local row max
            float mt0 = -1e30f, mt1 = -1e30f;
#pragma unroll
            for (int nt = 0; nt < 8; nt++) {
                int key = c + nt * 8 + tig * 2;
                float s0 = (key     <= qr0 && key     > qr0 - W) ? S[nt][0] * 0.125f : -1e30f;
                float s1 = (key + 1 <= qr0 && key + 1 > qr0 - W) ? S[nt][1] * 0.125f : -1e30f;
                float s2 = (key     <= qr1 && key     > qr1 - W) ? S[nt][2] * 0.125f : -1e30f;
                float s3 = (key + 1 <= qr1 && key + 1 > qr1 - W) ? S[nt][3] * 0.125f : -1e30f;
                S[nt][0] = s0; S[nt][1] = s1; S[nt][2] = s2; S[nt][3] = s3;
                mt0 = fmaxf(mt0, fmaxf(s0, s1));
                mt1 = fmaxf(mt1, fmaxf(s2, s3));
            }
            mt0 = fmaxf(mt0, __shfl_xor_sync(0xffffffffu, mt0, 1));
            mt0 = fmaxf(mt0, __shfl_xor_sync(0xffffffffu, mt0, 2));
            mt1 = fmaxf(mt1, __shfl_xor_sync(0xffffffffu, mt1, 1));
            mt1 = fmaxf(mt1, __shfl_xor_sync(0xffffffffu, mt1, 2));

            float nm0 = fmaxf(m0, mt0), nm1 = fmaxf(m1, mt1);
            float cr0 = __expf(m0 - nm0), cr1 = __expf(m1 - nm1);
            m0 = nm0; m1 = nm1;

            float ps0 = 0.f, ps1 = 0.f;
#pragma unroll
            for (int nt = 0; nt < 8; nt++) {
                S[nt][0] = __expf(S[nt][0] - nm0);
                S[nt][1] = __expf(S[nt][1] - nm0);
                S[nt][2] = __expf(S[nt][2] - nm1);
                S[nt][3] = __expf(S[nt][3] - nm1);
                ps0 += S[nt][0] + S[nt][1];
                ps1 += S[nt][2] + S[nt][3];
            }
            ps0 += __shfl_xor_sync(0xffffffffu, ps0, 1);
            ps0 += __shfl_xor_sync(0xffffffffu, ps0, 2);
            ps1 += __shfl_xor_sync(0xffffffffu, ps1, 1);
            ps1 += __shfl_xor_sync(0xffffffffu, ps1, 2);
            l0 = l0 * cr0 + ps0;
            l1 = l1 * cr1 + ps1;

#pragma unroll
            for (int nt = 0; nt < 8; nt++) {
                O[nt][0] *= cr0; O[nt][1] *= cr0;
                O[nt][2] *= cr1; O[nt][3] *= cr1;
            }

            // O += P V   (P from S fragments)
#pragma unroll
            for (int kk = 0; kk < 4; kk++) {
                uint32_t pf[4];
                __half2 h0 = __floats2half2_rn(S[2 * kk][0],     S[2 * kk][1]);
                __half2 h1 = __floats2half2_rn(S[2 * kk][2],     S[2 * kk][3]);
                __half2 h2 = __floats2half2_rn(S[2 * kk + 1][0], S[2 * kk + 1][1]);
                __half2 h3 = __floats2half2_rn(S[2 * kk + 1][2], S[2 * kk + 1][3]);
                pf[0] = *(uint32_t*)&h0; pf[1] = *(uint32_t*)&h1;
                pf[2] = *(uint32_t*)&h2; pf[3] = *(uint32_t*)&h3;
#pragma unroll
                for (int nt = 0; nt < 8; nt++) {
                    const __half* vp = &Vt[nt * 8 + g][kk * 16 + tig * 2];
                    uint32_t b0 = *(const uint32_t*)vp;
                    uint32_t b1 = *(const uint32_t*)(vp + 8);
                    mma_f16(O[nt], pf, b0, b1);
                }
            }
        }
    }

    float i0 = 1.f / l0, i1 = 1.f / l1;
    __half* ob = g_oh + (size_t)rowb * 1024 + h * HDc;
#pragma unroll
    for (int nt = 0; nt < 8; nt++) {
        *(__half2*)(ob + (size_t)qr0 * 1024 + nt * 8 + tig * 2) =
            __floats2half2_rn(O[nt][0] * i0, O[nt][1] * i0);
        *(__half2*)(ob + (size_t)qr1 * 1024 + nt * 8 + tig * 2) =
            __floats2half2_rn(O[nt][2] * i1, O[nt][3] * i1);
    }
}

// ---------------- host launcher ----------------
extern "C" void kernel_launch(void* const* d_in, const int* in_sizes, int n_in,
                              void* d_out, int out_size) {
    const float* hidden      = (const float*)d_in[0];
    const float* pre_norm_w  = (const float*)d_in[1];
    const float* in_proj_w   = (const float*)d_in[2];
    const float* conv_w      = (const float*)d_in[3];
    const float* conv_b      = (const float*)d_in[4];
    const float* x_proj_w    = (const float*)d_in[5];
    const float* dt_proj_w   = (const float*)d_in[6];
    const float* dt_proj_b   = (const float*)d_in[7];
    const float* A_log       = (const float*)d_in[8];
    const float* Dp          = (const float*)d_in[9];
    const float* out_proj_w  = (const float*)d_in[10];
    const float* ssm_norm_w  = (const float*)d_in[11];
    const float* q_w         = (const float*)d_in[12];
    const float* k_w         = (const float*)d_in[13];
    const float* v_w         = (const float*)d_in[14];
    const float* o_w         = (const float*)d_in[15];
    const float* mlp_norm_w  = (const float*)d_in[16];
    const float* gate_w      = (const float*)d_in[17];
    const float* down_w      = (const float*)d_in[18];
    float* out = (float*)d_out;

    const int smem128 = (BM * PADH + 128 * PADH) * STAGES * 2;
    const int smem64  = (BM * PADH + 64 * PADH) * STAGES * 2;
    cudaFuncSetAttribute(gemm_h<128, OP_NONE,  false>, cudaFuncAttributeMaxDynamicSharedMemorySize, smem128);
    cudaFuncSetAttribute(gemm_h<128, OP_SPLUS, false>, cudaFuncAttributeMaxDynamicSharedMemorySize, smem128);
    cudaFuncSetAttribute(gemm_h<128, OP_SWIGLU,false>, cudaFuncAttributeMaxDynamicSharedMemorySize, smem128);
    cudaFuncSetAttribute(gemm_h<64,  OP_HALF,  true >, cudaFuncAttributeMaxDynamicSharedMemorySize, smem64);
    cudaFuncSetAttribute(gemm_h<64,  OP_NONE,  false>, cudaFuncAttributeMaxDynamicSharedMemorySize, smem64);
    cudaFuncSetAttribute(gemm_h<64,  OP_ADDC,  false>, cudaFuncAttributeMaxDynamicSharedMemorySize, smem64);

    __half *hs, *xsh, *proj_h, *y, *ssmst, *oh, *x2, *hm;
    __half *wbig, *wxp, *wdt, *wop, *wkv, *wo, *wg, *wd;
    float *xzq, *xs, *dt, *tmp, *ssmres, *kvssm, *mlpres;
    cudaGetSymbolAddress((void**)&hs, g_hs);
    cudaGetSymbolAddress((void**)&xzq, g_xzq);
    cudaGetSymbolAddress((void**)&xs, g_xs);
    cudaGetSymbolAddress((void**)&xsh, g_xsh);
    cudaGetSymbolAddress((void**)&proj_h, g_proj_h);
    cudaGetSymbolAddress((void**)&dt, g_dt);
    cudaGetSymbolAddress((void**)&y, g_y);
    cudaGetSymbolAddress((void**)&tmp, g_tmp);
    cudaGetSymbolAddress((void**)&ssmres, g_ssmres);
    cudaGetSymbolAddress((void**)&ssmst, g_ssmst);
    cudaGetSymbolAddress((void**)&kvssm, g_kvssm);
    cudaGetSymbolAddress((void**)&oh, g_oh);
    cudaGetSymbolAddress((void**)&mlpres, g_mlpres);
    cudaGetSymbolAddress((void**)&x2, g_x2);
    cudaGetSymbolAddress((void**)&hm, g_hm);
    cudaGetSymbolAddress((void**)&wbig, g_wbig);
    cudaGetSymbolAddress((void**)&wxp, g_wxp);
    cudaGetSymbolAddress((void**)&wdt, g_wdt);
    cudaGetSymbolAddress((void**)&wop, g_wop);
    cudaGetSymbolAddress((void**)&wkv, g_wkv);
    cudaGetSymbolAddress((void**)&wo, g_wo);
    cudaGetSymbolAddress((void**)&wg, g_wg);
    cudaGetSymbolAddress((void**)&wd, g_wd);
    __half *qh, *kah, *ksh;
    cudaGetSymbolAddress((void**)&qh, g_qh);
    cudaGetSymbolAddress((void**)&kah, g_kah);
    cudaGetSymbolAddress((void**)&ksh, g_ksh);

    // 0. fused weight prep
    prep_weights<<<(W7 + 255) / 256, 256>>>(in_proj_w, q_w, k_w, v_w, gate_w,
                                            x_proj_w, dt_proj_w, out_proj_w, o_w, down_w);
    // 1. pre-norm
    resid_rms<<<Mrows, 256>>>(hidden, nullptr, pre_norm_w, nullptr, hs);
    // 2. fused xz|q|k|v (2048 x 5632, K=1024)
    gemm_h<128, OP_NONE, false><<<dim3(FUSN / 128, Mrows / BM), 128, smem128>>>(
        hs, wbig, xzq, nullptr, FUSN, Hc, Hc, Hc);
    // 3. conv + silu
    conv_silu<<<(Mrows * Ic) / 256, 256>>>(conv_w, conv_b);
    // 4. x_proj (2048 x 96, K=2048) -> half
    gemm_h<64, OP_HALF, true><<<dim3(2, Mrows / BM), 128, smem64>>>(
        xsh, wxp, proj_h, nullptr, PROJW, Ic, Ic, Ic);
    // 5. dt GEMM with fused bias+softplus
    gemm_h<128, OP_SPLUS, false><<<dim3(Ic / 128, Mrows / BM), 128, smem128>>>(
        proj_h, wdt, dt, dt_proj_b, Ic, Rc, PROJW, Rc);
    // 6. selective scan
    scan_kernel<<<(Bc * Ic) / 16, 256>>>(A_log, Dp);
    // 7. out_proj; residual + norm
    gemm_h<64, OP_NONE, false><<<dim3(Hc / 64, Mrows / BM), 128, smem64>>>(
        y, wop, tmp, nullptr, Hc, Ic, Ic, Ic);
    resid_rms<<<Mrows, 256>>>(tmp, hidden, ssm_norm_w, ssmres, ssmst);
    // 8. kv_ssm
    gemm_h<64, OP_NONE, false><<<dim3(KVSLD / 64, Mrows / BM), 128, smem64>>>(
        ssmst, wkv, kvssm, nullptr, KVSLD, Hc, Hc, Hc);
    // 9. rotary -> compact half; v copies
    rotary_half<<<(Mrows * NHc * 32) / 256, 256>>>(xzq, FUSN, 4096, qh, NHc);
    rotary_half<<<(Mrows * NKVc * 32) / 256, 256>>>(xzq, FUSN, 5120, kah, NKVc);
    rotary_half<<<(Mrows * NKVc * 32) / 256, 256>>>(kvssm, KVSLD, 0, ksh, NKVc);
    copy_vh<<<(Mrows * 512) / 256, 256>>>();
    // 10. attention (MMA, 64 q/block)
    attn4<<<dim3(Sc / 64, NHc, Bc), 128>>>();
    // 11. o proj; residual + norm
    gemm_h<64, OP_NONE, false><<<dim3(Hc / 64, Mrows / BM), 128, smem64>>>(
        oh, wo, tmp, nullptr, Hc, NHc * HDc, NHc * HDc, NHc * HDc);
    resid_rms<<<Mrows, 256>>>(tmp, ssmres, mlp_norm_w, mlpres, x2);
    // 12. MLP
    gemm_h<128, OP_SWIGLU, false><<<dim3(GATEN / 128, Mrows / BM), 128, smem128>>>(
        x2, wg, hm, nullptr, GATEN, Hc, Hc, Hc);
    gemm_h<64, OP_ADDC, false><<<dim3(Hc / 64, Mrows / BM), 128, smem64>>>(
        hm, wd, out, mlpres, Hc, IMc, IMc, IMc);
}

// round 12
// speedup vs baseline: 3.1220x; 1.8943x over previous
#include <cuda_runtime.h>
#include <cuda_fp16.h>
#include <math.h>
#include <stdint.h>

// ---------------- problem constants ----------------
#define Bc   2
#define Sc   1024
#define Hc   1024
#define Ic   2048
#define Nst  16
#define Rc   64
#define Kcv  4
#define NHc  16
#define NKVc 4
#define HDc  64
#define WATT 512
#define WSSM 128
#define IMc  2816
#define Mrows (Bc*Sc)
#define EPSc  1e-6f
#define PROJW (Rc + 2*Nst)   // 96
#define FUSN  5632
#define KVSLD 512
#define GATEN 5632

// ---------------- scratch ----------------
__device__ __half g_hs[Mrows*Hc];
__device__ float  g_xzq[Mrows*FUSN];
__device__ float  g_xs[Mrows*Ic];
__device__ __half g_xsh[Mrows*Ic];
__device__ __half g_proj_h[Mrows*PROJW];
__device__ float  g_dt[Mrows*Ic];
__device__ __half g_y[Mrows*Ic];
__device__ float  g_tmp[Mrows*Hc];
__device__ float  g_ssmres[Mrows*Hc];
__device__ __half g_ssmst[Mrows*Hc];
__device__ float  g_kvssm[Mrows*KVSLD];
__device__ __half g_oh[Mrows*NHc*HDc];
__device__ float  g_mlpres[Mrows*Hc];
__device__ __half g_x2[Mrows*Hc];
__device__ __half g_hm[Mrows*IMc];
// compact half attention operands
__device__ __half g_qh[Mrows*NHc*HDc];
__device__ __half g_kah[Mrows*NKVc*HDc];
__device__ __half g_ksh[Mrows*NKVc*HDc];
__device__ __half g_vah[Mrows*NKVc*HDc];
__device__ __half g_vsh[Mrows*NKVc*HDc];
// half weights
__device__ __half g_wbig[FUSN*Hc];
__device__ __half g_wxp[PROJW*Ic];
__device__ __half g_wdt[Ic*Rc];
__device__ __half g_wop[Hc*Ic];
__device__ __half g_wkv[KVSLD*Hc];
__device__ __half g_wo[Hc*NHc*HDc];
__device__ __half g_wg[GATEN*Hc];
__device__ __half g_wd[Hc*IMc];

__device__ __forceinline__ float fsig(float x) { return 1.f / (1.f + __expf(-x)); }

// ---------------- fp16 MMA primitives ----------------
#define BM 128
#define BK 32
#define PADH 40
#define STAGES 4

#define OP_NONE   0
#define OP_HALF   1
#define OP_SPLUS  2
#define OP_SWIGLU 3
#define OP_ADDC   4

__device__ __forceinline__ void cp16(uint32_t dst, const void* src, int ssize) {
    asm volatile("cp.async.cg.shared.global [%0], [%1], 16, %2;\n"
                 :: "r"(dst), "l"(src), "r"(ssize));
}
__device__ __forceinline__ void mma_f16(float* c, const uint32_t* a, uint32_t b0, uint32_t b1) {
    asm volatile("mma.sync.aligned.m16n8k16.row.col.f32.f16.f16.f32 "
                 "{%0,%1,%2,%3}, {%4,%5,%6,%7}, {%8,%9}, {%0,%1,%2,%3};\n"
                 : "+f"(c[0]), "+f"(c[1]), "+f"(c[2]), "+f"(c[3])
                 : "r"(a[0]), "r"(a[1]), "r"(a[2]), "r"(a[3]), "r"(b0), "r"(b1));
}

template<int BNT, int OP, bool NG>
__global__ __launch_bounds__(128, 2)
void gemm_h(const __half* __restrict__ A, const __half* __restrict__ Bw,
            void* __restrict__ Cv, const float* __restrict__ aux,
            int Ndim, int Kdim, int lda, int ldb) {
    constexpr int NI  = BNT / 16;
    constexpr int ASZ = BM * PADH;
    constexpr int BSZ = BNT * PADH;
    constexpr int STG = ASZ + BSZ;
    extern __shared__ __half smh[];
    const int t    = threadIdx.x;
    const int bm   = blockIdx.y * BM;
    const int bn   = blockIdx.x * BNT;
    const int warp = t >> 5, lane = t & 31;
    const int wm   = (warp & 1) * 64;
    const int wn   = (warp >> 1) * (BNT / 2);
    const int gid  = lane >> 2;
    const int tig  = lane & 3;
    const uint32_t smem_base = (uint32_t)__cvta_generic_to_shared(smh);

    float acc[4][NI][4];
#pragma unroll
    for (int mi = 0; mi < 4; mi++)
#pragma unroll
        for (int ni = 0; ni < NI; ni++)
#pragma unroll
            for (int j = 0; j < 4; j++) acc[mi][ni][j] = 0.f;

    const int niters = Kdim / BK;

    auto load_tile = [&](int slot, int k0) {
        uint32_t aOff = smem_base + slot * STG * 2;
        uint32_t bOff = aOff + ASZ * 2;
#pragma unroll
        for (int i = 0; i < 4; i++) {
            int id = t + i * 128;
            int r  = id >> 2;
            int kq = (id & 3) * 8;
            cp16(aOff + (r * PADH + kq) * 2, A + (size_t)(bm + r) * lda + k0 + kq, 16);
        }
#pragma unroll
        for (int i = 0; i < BNT / 32; i++) {
            int id = t + i * 128;
            int r  = id >> 2;
            int kq = (id & 3) * 8;
            int ok = 1;
            int br = bn + r;
            if (NG) ok = (br < Ndim);
            cp16(bOff + (r * PADH + kq) * 2,
                 Bw + (size_t)(NG ? (ok ? br : 0) : br) * ldb + k0 + kq, ok ? 16 : 0);
        }
    };

#pragma unroll
    for (int s = 0; s < STAGES - 1; s++) {
        if (s < niters) load_tile(s, s * BK);
        asm volatile("cp.async.commit_group;\n");
    }

    int cslot = 0, nslot = STAGES - 1;
    for (int it = 0; it < niters; it++) {
        asm volatile("cp.async.wait_group %0;\n" :: "n"(STAGES - 2));
        __syncthreads();
        int nk = it + STAGES - 1;
        if (nk < niters) load_tile(nslot, nk * BK);
        asm volatile("cp.async.commit_group;\n");
        if (++nslot == STAGES) nslot = 0;

        const __half* Ab = smh + cslot * STG;
        const __half* Bb = Ab + ASZ;
        if (++cslot == STAGES) cslot = 0;
#pragma unroll
        for (int kk = 0; kk < 2; kk++) {
            int kb = kk * 16;
            uint32_t afr[4][4];
#pragma unroll
            for (int mi = 0; mi < 4; mi++) {
                const __half* ab = Ab + (wm + mi * 16 + gid) * PADH + kb + tig * 2;
                afr[mi][0] = *(const uint32_t*)(ab);
                afr[mi][1] = *(const uint32_t*)(ab + 8 * PADH);
                afr[mi][2] = *(const uint32_t*)(ab + 8);
                afr[mi][3] = *(const uint32_t*)(ab + 8 * PADH + 8);
            }
#pragma unroll
            for (int ni = 0; ni < NI; ni++) {
                const __half* bb = Bb + (wn + ni * 8 + gid) * PADH + kb + tig * 2;
                uint32_t b0 = *(const uint32_t*)(bb);
                uint32_t b1 = *(const uint32_t*)(bb + 8);
#pragma unroll
                for (int mi = 0; mi < 4; mi++)
                    mma_f16(acc[mi][ni], afr[mi], b0, b1);
            }
        }
    }

    float*  Cf = (float*)Cv;
    __half* Ch = (__half*)Cv;
#pragma unroll
    for (int mi = 0; mi < 4; mi++) {
        int rbase = bm + wm + mi * 16 + gid;
#pragma unroll
        for (int ni = 0; ni < NI; ni++) {
            int c0 = bn + wn + ni * 8 + tig * 2;
            if (NG && c0 >= Ndim) continue;
#pragma unroll
            for (int half_ = 0; half_ < 2; half_++) {
                int r0 = rbase + half_ * 8;
                float a0 = acc[mi][ni][half_ * 2 + 0];
                float a1 = acc[mi][ni][half_ * 2 + 1];
                if (OP == OP_NONE) {
                    *(float2*)(Cf + (size_t)r0 * Ndim + c0) = make_float2(a0, a1);
                } else if (OP == OP_HALF) {
                    *(__half2*)(Ch + (size_t)r0 * Ndim + c0) = __floats2half2_rn(a0, a1);
                } else if (OP == OP_SPLUS) {
                    float x0 = a0 + aux[c0], x1 = a1 + aux[c0 + 1];
                    x0 = (x0 > 20.f) ? x0 : __logf(1.f + __expf(x0));
                    x1 = (x1 > 20.f) ? x1 : __logf(1.f + __expf(x1));
                    *(float2*)(Cf + (size_t)r0 * Ndim + c0) = make_float2(x0, x1);
                } else if (OP == OP_SWIGLU) {
                    float sv = a0 * fsig(a0) * a1;
                    Ch[(size_t)r0 * IMc + (c0 >> 1)] = __float2half_rn(sv);
                } else if (OP == OP_ADDC) {
                    float2 r = *(const float2*)(aux + (size_t)r0 * Ndim + c0);
                    *(float2*)(Cf + (size_t)r0 * Ndim + c0) =
                        make_float2(a0 + r.x, a1 + r.y);
                }
            }
        }
    }
}

// ---------------- weight prep (split: wbig first, rest second) ----------------
#define W0 (FUSN*Hc)
#define R1 (KVSLD*Hc)
#define R2 (R1 + GATEN*Hc)
#define R3 (R2 + PROJW*Ic)
#define R4 (R3 + Ic*Rc)
#define R5 (R4 + Hc*Ic)
#define R6 (R5 + Hc*NHc*HDc)
#define R7 (R6 + Hc*IMc)
__global__ void prep_wbig(const float* __restrict__ ipw, const float* __restrict__ qw,
                          const float* __restrict__ kw, const float* __restrict__ vw) {
    int idx = blockIdx.x * 256 + threadIdx.x;
    if (idx >= W0) return;
    int row = idx >> 10, col = idx & 1023;
    float v;
    if (row < 4096)      v = ipw[idx];
    else if (row < 5120) v = qw[(row - 4096) * Hc + col];
    else if (row < 5376) v = kw[(row - 5120) * Hc + col];
    else                 v = vw[(row - 5376) * Hc + col];
    g_wbig[idx] = __float2half_rn(v);
}
__global__ void prep_rest(const float* __restrict__ kw, const float* __restrict__ vw,
                          const float* __restrict__ gw, const float* __restrict__ xpw,
                          const float* __restrict__ dtw, const float* __restrict__ opw,
                          const float* __restrict__ ow, const float* __restrict__ dw) {
    int idx = blockIdx.x * 256 + threadIdx.x;
    if (idx >= R7) return;
    if (idx < R1) {
        int row = idx >> 10, col = idx & 1023;
        float v = (row < 256) ? kw[row * Hc + col] : vw[(row - 256) * Hc + col];
        g_wkv[idx] = __float2half_rn(v);
    } else if (idx < R2) {
        int i = idx - R1;
        int row = i >> 10, col = i & 1023;
        int f = row >> 1;
        int src = (row & 1) ? (IMc + f) : f;
        g_wg[i] = __float2half_rn(gw[src * Hc + col]);
    } else if (idx < R3) {
        int i = idx - R2; g_wxp[i] = __float2half_rn(xpw[i]);
    } else if (idx < R4) {
        int i = idx - R3; g_wdt[i] = __float2half_rn(dtw[i]);
    } else if (idx < R5) {
        int i = idx - R4; g_wop[i] = __float2half_rn(opw[i]);
    } else if (idx < R6) {
        int i = idx - R5; g_wo[i] = __float2half_rn(ow[i]);
    } else {
        int i = idx - R6; g_wd[i] = __float2half_rn(dw[i]);
    }
}

// ---------------- RMSNorm ----------------
__global__ void resid_rms(const float* __restrict__ a, const float* __restrict__ r,
                          const float* __restrict__ w, float* __restrict__ res_out,
                          __half* __restrict__ nrm_out) {
    int row = blockIdx.x;
    int t   = threadIdx.x;
    const float* ap = a + (size_t)row * Hc;
    const float* rp = r ? r + (size_t)row * Hc : nullptr;
    float v[4];
    float ss = 0.f;
#pragma unroll
    for (int i = 0; i < 4; i++) {
        int c = t + i * 256;
        float x = ap[c] + (rp ? rp[c] : 0.f);
        v[i] = x;
        ss += x * x;
    }
#pragma unroll
    for (int off = 16; off; off >>= 1) ss += __shfl_xor_sync(0xffffffffu, ss, off);
    __shared__ float sred[8];
    __shared__ float sscale;
    if ((t & 31) == 0) sred[t >> 5] = ss;
    __syncthreads();
    if (t == 0) {
        float tot = 0.f;
        for (int i = 0; i < 8; i++) tot += sred[i];
        sscale = rsqrtf(tot * (1.f / Hc) + EPSc);
    }
    __syncthreads();
    float scale = sscale;
    float* ro = res_out ? res_out + (size_t)row * Hc : nullptr;
    __half* no = nrm_out + (size_t)row * Hc;
#pragma unroll
    for (int i = 0; i < 4; i++) {
        int c = t + i * 256;
        if (ro) ro[c] = v[i];
        no[c] = __float2half_rn(v[i] * scale * w[c]);
    }
}

// ---------------- causal depthwise conv (K=4) + SiLU ----------------
__global__ void conv_silu(const float* __restrict__ cw, const float* __restrict__ cb) {
    int idx = blockIdx.x * blockDim.x + threadIdx.x;
    if (idx >= Mrows * Ic) return;
    int row = idx / Ic;
    int i   = idx - row * Ic;
    int b   = row / Sc;
    int s   = row - b * Sc;
    float acc = cb[i];
#pragma unroll
    for (int k = 0; k < Kcv; k++) {
        int sp = s + k - (Kcv - 1);
        if (sp >= 0)
            acc += cw[i * Kcv + k] * g_xzq[(size_t)(b * Sc + sp) * FUSN + i];
    }
    float r = acc * fsig(acc);
    g_xs[idx]  = r;
    g_xsh[idx] = __float2half_rn(r);
}

// ---------------- selective scan v2: cp.async staged, fast exp ----------------
#define SCH 64
__global__ __launch_bounds__(256) void scan2(const float* __restrict__ A_log,
                                             const float* __restrict__ Dp) {
    __shared__ float  sdt[2][SCH][16];
    __shared__ float  sxs[2][SCH][16];
    __shared__ float  szz[2][SCH][16];
    __shared__ __half sbc[2][SCH][32];
    __shared__ __half sy[SCH][16];
    int t  = threadIdx.x;
    int gi0 = blockIdx.x * 16;
    int b   = gi0 / Ic;
    int i0  = gi0 - b * Ic;
    int rowb = b * Sc;
    int c = t >> 4, n = t & 15;
    int i = i0 + c;
    float An = -__expf(A_log[i * Nst + n]);
    float Dv = Dp[i];

    int lrow = t >> 2, lq = t & 3;
    auto load_chunk = [&](int buf, int s0) {
        size_t gr = (size_t)(rowb + s0 + lrow);
        cp16((uint32_t)__cvta_generic_to_shared(&sdt[buf][lrow][lq * 4]),
             g_dt + gr * Ic + i0 + lq * 4, 16);
        cp16((uint32_t)__cvta_generic_to_shared(&sxs[buf][lrow][lq * 4]),
             g_xs + gr * Ic + i0 + lq * 4, 16);
        cp16((uint32_t)__cvta_generic_to_shared(&szz[buf][lrow][lq * 4]),
             g_xzq + gr * FUSN + Ic + i0 + lq * 4, 16);
        cp16((uint32_t)__cvta_generic_to_shared(&sbc[buf][lrow][lq * 8]),
             g_proj_h + gr * PROJW + Rc + lq * 8, 16);
    };

    load_chunk(0, 0);
    asm volatile("cp.async.commit_group;\n");

    float h = 0.f;
    for (int ch = 0; ch < Sc / SCH; ch++) {
        int buf = ch & 1;
        if (ch + 1 < Sc / SCH) {
            load_chunk(buf ^ 1, (ch + 1) * SCH);
            asm volatile("cp.async.commit_group;\n");
            asm volatile("cp.async.wait_group 1;\n");
        } else {
            asm volatile("cp.async.wait_group 0;\n");
        }
        __syncthreads();
#pragma unroll 4
        for (int s = 0; s < SCH; s++) {
            float dtv = sdt[buf][s][c];
            float xsv = sxs[buf][s][c];
            float Bn  = __half2float(sbc[buf][s][n]);
            float Cn  = __half2float(sbc[buf][s][16 + n]);
            h = h * __expf(dtv * An) + dtv * Bn * xsv;
            float v = h * Cn;
            v += __shfl_xor_sync(0xffffffffu, v, 8);
            v += __shfl_xor_sync(0xffffffffu, v, 4);
            v += __shfl_xor_sync(0xffffffffu, v, 2);
            v += __shfl_xor_sync(0xffffffffu, v, 1);
            if (n == 0) {
                float z = szz[buf][s][c];
                sy[s][c] = __float2half_rn((v + Dv * xsv) * (z * fsig(z)));
            }
        }
        __syncthreads();
        if (t < 128) {
            int row = t >> 1, part = (t & 1) * 8;
            *(uint4*)(g_y + (size_t)(rowb + ch * SCH + row) * Ic + i0 + part) =
                *(const uint4*)&sy[row][part];
        }
    }
}

// ---------------- rotary: fp32 strided src -> compact half dst ----------------
__global__ void rotary_half(const float* __restrict__ src, int ld, int coloff,
                            __half* __restrict__ dst, int nheads) {
    int idx = blockIdx.x * blockDim.x + threadIdx.x;
    int tot = Mrows * nheads * 32;
    if (idx >= tot) return;
    int r    = idx / (nheads * 32);
    int rem  = idx - r * (nheads * 32);
    int head = rem >> 5;
    int j    = rem & 31;
    int s    = r % Sc;
    float inv = __expf(-((float)(2 * j) / (float)HDc) * __logf(10000.0f));
    float f = (float)s * inv;
    float sn, cs;
    __sincosf(f, &sn, &cs);
    const float* bi = src + (size_t)r * ld + coloff + head * HDc;
    __half* bo = dst + (size_t)r * nheads * HDc + head * HDc;
    float x1 = bi[j], x2 = bi[j + 32];
    bo[j]      = __float2half_rn(x1 * cs - x2 * sn);
    bo[j + 32] = __float2half_rn(x2 * cs + x1 * sn);
}

// ---------------- v copy: fp32 -> compact half ----------------
__global__ void copy_vh() {
    int idx = blockIdx.x * blockDim.x + threadIdx.x;
    if (idx >= Mrows * 512) return;
    int r   = idx >> 9;
    int col = idx & 511;
    if (col < 256)
        g_vah[r * 256 + col] = __float2half_rn(g_xzq[(size_t)r * FUSN + 5376 + col]);
    else
        g_vsh[r * 256 + (col - 256)] = __float2half_rn(g_kvssm[(size_t)r * KVSLD + 256 + (col - 256)]);
}

// ---------------- attn4: FA2-style MMA attention ----------------
__global__ __launch_bounds__(128) void attn4() {
    __shared__ __half Kt[64][72];
    __shared__ __half Vt[64][72];
    int t = threadIdx.x, w = t >> 5, lane = t & 31;
    int g = lane >> 2, tig = lane & 3;
    int q0 = blockIdx.x * 64, h = blockIdx.y, b = blockIdx.z;
    int rowb = b * Sc, hk = h >> 2;
    int qr0 = q0 + w * 16 + g;
    int qr1 = qr0 + 8;

    uint32_t qf[4][4];
    {
        const __half* qb = g_qh + (size_t)rowb * 1024 + h * HDc;
#pragma unroll
        for (int kk = 0; kk < 4; kk++) {
            const __half* r0 = qb + (size_t)qr0 * 1024 + kk * 16 + tig * 2;
            const __half* r1 = qb + (size_t)qr1 * 1024 + kk * 16 + tig * 2;
            qf[kk][0] = *(const uint32_t*)(r0);
            qf[kk][1] = *(const uint32_t*)(r1);
            qf[kk][2] = *(const uint32_t*)(r0 + 8);
            qf[kk][3] = *(const uint32_t*)(r1 + 8);
        }
    }

    float O[8][4];
#pragma unroll
    for (int nt = 0; nt < 8; nt++)
#pragma unroll
        for (int e = 0; e < 4; e++) O[nt][e] = 0.f;
    float m0 = -1e30f, m1 = -1e30f, l0 = 0.f, l1 = 0.f;

    for (int pass = 0; pass < 2; pass++) {
        const __half* kb = pass ? g_ksh : g_kah;
        const __half* vb = pass ? g_vsh : g_vah;
        int W  = pass ? WSSM : WATT;
        int cs = max(0, q0 - (W - 1)) & ~63;
        for (int c = q0; c >= cs; c -= 64) {
            __syncthreads();
#pragma unroll
            for (int i = 0; i < 4; i++) {
                int id = t + i * 128;
                int r  = id >> 3;
                int c8 = (id & 7) * 8;
                size_t src = (size_t)(rowb + c + r) * 256 + hk * HDc + c8;
                *(uint4*)&Kt[r][c8] = *(const uint4*)(kb + src);
                uint4 vv = *(const uint4*)(vb + src);
                const __half* hv = (const __half*)&vv;
#pragma unroll
                for (int j = 0; j < 8; j++) Vt[c8 + j][r] = hv[j];
            }
            __syncthreads();

            float S[8][4];
#pragma unroll
            for (int nt = 0; nt < 8; nt++)
#pragma unroll
                for (int e = 0; e < 4; e++) S[nt][e] = 0.f;
#pragma unroll
            for (int kk = 0; kk < 4; kk++)
#pragma unroll
                for (int nt = 0; nt < 8; nt++) {
                    const __half* kp = &Kt[nt * 8 + g][kk * 16 + tig * 2];
                    uint32_t b0 = *(const uint32_t*)kp;
                    uint32_t b1 = *(const uint32_t*)(kp + 8);
                    mma_f16(S[nt], qf[kk], b0, b1);
                }

            float mt0 = -1e30f, mt1 = -1e30f;
#pragma unroll
            for (int nt = 0; nt < 8; nt++) {
                int key = c + nt * 8 + tig * 2;
                float s0 = (key     <= qr0 && key     > qr0 - W) ? S[nt][0] * 0.125f : -1e30f;
                float s1 = (key + 1 <= qr0 && key + 1 > qr0 - W) ? S[nt][1] * 0.125f : -1e30f;
                float s2 = (key     <= qr1 && key     > qr1 - W) ? S[nt][2] * 0.125f : -1e30f;
                float s3 = (key + 1 <= qr1 && key + 1 > qr1 - W) ? S[nt][3] * 0.125f : -1e30f;
                S[nt][0] = s0; S[nt][1] = s1; S[nt][2] = s2; S[nt][3] = s3;
                mt0 = fmaxf(mt0, fmaxf(s0, s1));
                mt1 = fmaxf(mt1, fmaxf(s2, s3));
            }
            mt0 = fmaxf(mt0, __shfl_xor_sync(0xffffffffu, mt0, 1));
            mt0 = fmaxf(mt0, __shfl_xor_sync(0xffffffffu, mt0, 2));
            mt1 = fmaxf(mt1, __shfl_xor_sync(0xffffffffu, mt1, 1));
            mt1 = fmaxf(mt1, __shfl_xor_sync(0xffffffffu, mt1, 2));

            float nm0 = fmaxf(m0, mt0), nm1 = fmaxf(m1, mt1);
            float cr0 = __expf(m0 - nm0), cr1 = __expf(m1 - nm1);
            m0 = nm0; m1 = nm1;

            float ps0 = 0.f, ps1 = 0.f;
#pragma unroll
            for (int nt = 0; nt < 8; nt++) {
                S[nt][0] = __expf(S[nt][0] - nm0);
                S[nt][1] = __expf(S[nt][1] - nm0);
                S[nt][2] = __expf(S[nt][2] - nm1);
                S[nt][3] = __expf(S[nt][3] - nm1);
                ps0 += S[nt][0] + S[nt][1];
                ps1 += S[nt][2] + S[nt][3];
            }
            ps0 += __shfl_xor_sync(0xffffffffu, ps0, 1);
            ps0 += __shfl_xor_sync(0xffffffffu, ps0, 2);
            ps1 += __shfl_xor_sync(0xffffffffu, ps1, 1);
            ps1 += __shfl_xor_sync(0xffffffffu, ps1, 2);
            l0 = l0 * cr0 + ps0;
            l1 = l1 * cr1 + ps1;

#pragma unroll
            for (int nt = 0; nt < 8; nt++) {
                O[nt][0] *= cr0; O[nt][1] *= cr0;
                O[nt][2] *= cr1; O[nt][3] *= cr1;
            }

#pragma unroll
            for (int kk = 0; kk < 4; kk++) {
                uint32_t pf[4];
                __half2 h0 = __floats2half2_rn(S[2 * kk][0],     S[2 * kk][1]);
                __half2 h1 = __floats2half2_rn(S[2 * kk][2],     S[2 * kk][3]);
                __half2 h2 = __floats2half2_rn(S[2 * kk + 1][0], S[2 * kk + 1][1]);
                __half2 h3 = __floats2half2_rn(S[2 * kk + 1][2], S[2 * kk + 1][3]);
                pf[0] = *(uint32_t*)&h0; pf[1] = *(uint32_t*)&h1;
                pf[2] = *(uint32_t*)&h2; pf[3] = *(uint32_t*)&h3;
#pragma unroll
                for (int nt = 0; nt < 8; nt++) {
                    const __half* vp = &Vt[nt * 8 + g][kk * 16 + tig * 2];
                    uint32_t b0 = *(const uint32_t*)vp;
                    uint32_t b1 = *(const uint32_t*)(vp + 8);
                    mma_f16(O[nt], pf, b0, b1);
                }
            }
        }
    }

    float i0 = 1.f / l0, i1 = 1.f / l1;
    __half* ob = g_oh + (size_t)rowb * 1024 + h * HDc;
#pragma unroll
    for (int nt = 0; nt < 8; nt++) {
        *(__half2*)(ob + (size_t)qr0 * 1024 + nt * 8 + tig * 2) =
            __floats2half2_rn(O[nt][0] * i0, O[nt][1] * i0);
        *(__half2*)(ob + (size_t)qr1 * 1024 + nt * 8 + tig * 2) =
            __floats2half2_rn(O[nt][2] * i1, O[nt][3] * i1);
    }
}

// ---------------- host launcher ----------------
extern "C" void kernel_launch(void* const* d_in, const int* in_sizes, int n_in,
                              void* d_out, int out_size) {
    const float* hidden      = (const float*)d_in[0];
    const float* pre_norm_w  = (const float*)d_in[1];
    const float* in_proj_w   = (const float*)d_in[2];
    const float* conv_w      = (const float*)d_in[3];
    const float* conv_b      = (const float*)d_in[4];
    const float* x_proj_w    = (const float*)d_in[5];
    const float* dt_proj_w   = (const float*)d_in[6];
    const float* dt_proj_b   = (const float*)d_in[7];
    const float* A_log       = (const float*)d_in[8];
    const float* Dp          = (const float*)d_in[9];
    const float* out_proj_w  = (const float*)d_in[10];
    const float* ssm_norm_w  = (const float*)d_in[11];
    const float* q_w         = (const float*)d_in[12];
    const float* k_w         = (const float*)d_in[13];
    const float* v_w         = (const float*)d_in[14];
    const float* o_w         = (const float*)d_in[15];
    const float* mlp_norm_w  = (const float*)d_in[16];
    const float* gate_w      = (const float*)d_in[17];
    const float* down_w      = (const float*)d_in[18];
    float* out = (float*)d_out;

    const int smem128 = (BM * PADH + 128 * PADH) * STAGES * 2;
    const int smem64  = (BM * PADH + 64 * PADH) * STAGES * 2;
    cudaFuncSetAttribute(gemm_h<128, OP_NONE,  false>, cudaFuncAttributeMaxDynamicSharedMemorySize, smem128);
    cudaFuncSetAttribute(gemm_h<128, OP_SPLUS, false>, cudaFuncAttributeMaxDynamicSharedMemorySize, smem128);
    cudaFuncSetAttribute(gemm_h<128, OP_SWIGLU,false>, cudaFuncAttributeMaxDynamicSharedMemorySize, smem128);
    cudaFuncSetAttribute(gemm_h<64,  OP_HALF,  true >, cudaFuncAttributeMaxDynamicSharedMemorySize, smem64);
    cudaFuncSetAttribute(gemm_h<64,  OP_NONE,  false>, cudaFuncAttributeMaxDynamicSharedMemorySize, smem64);
    cudaFuncSetAttribute(gemm_h<64,  OP_ADDC,  false>, cudaFuncAttributeMaxDynamicSharedMemorySize, smem64);

    __half *hs, *xsh, *proj_h, *y, *ssmst, *oh, *x2, *hm;
    __half *wbig, *wxp, *wdt, *wop, *wkv, *wo, *wg, *wd;
    float *xzq, *xs, *dt, *tmp, *ssmres, *kvssm, *mlpres;
    cudaGetSymbolAddress((void**)&hs, g_hs);
    cudaGetSymbolAddress((void**)&xzq, g_xzq);
    cudaGetSymbolAddress((void**)&xs, g_xs);
    cudaGetSymbolAddress((void**)&xsh, g_xsh);
    cudaGetSymbolAddress((void**)&proj_h, g_proj_h);
    cudaGetSymbolAddress((void**)&dt, g_dt);
    cudaGetSymbolAddress((void**)&y, g_y);
    cudaGetSymbolAddress((void**)&tmp, g_tmp);
    cudaGetSymbolAddress((void**)&ssmres, g_ssmres);
    cudaGetSymbolAddress((void**)&ssmst, g_ssmst);
    cudaGetSymbolAddress((void**)&kvssm, g_kvssm);
    cudaGetSymbolAddress((void**)&oh, g_oh);
    cudaGetSymbolAddress((void**)&mlpres, g_mlpres);
    cudaGetSymbolAddress((void**)&x2, g_x2);
    cudaGetSymbolAddress((void**)&hm, g_hm);
    cudaGetSymbolAddress((void**)&wbig, g_wbig);
    cudaGetSymbolAddress((void**)&wxp, g_wxp);
    cudaGetSymbolAddress((void**)&wdt, g_wdt);
    cudaGetSymbolAddress((void**)&wop, g_wop);
    cudaGetSymbolAddress((void**)&wkv, g_wkv);
    cudaGetSymbolAddress((void**)&wo, g_wo);
    cudaGetSymbolAddress((void**)&wg, g_wg);
    cudaGetSymbolAddress((void**)&wd, g_wd);
    __half *qh, *kah, *ksh;
    cudaGetSymbolAddress((void**)&qh, g_qh);
    cudaGetSymbolAddress((void**)&kah, g_kah);
    cudaGetSymbolAddress((void**)&ksh, g_ksh);

    // 1-2. weight prep (split so the big GEMM is launch #4 for ncu)
    prep_wbig<<<(W0 + 255) / 256, 256>>>(in_proj_w, q_w, k_w, v_w);
    prep_rest<<<(R7 + 255) / 256, 256>>>(k_w, v_w, gate_w, x_proj_w, dt_proj_w,
                                         out_proj_w, o_w, down_w);
    // 3. pre-norm
    resid_rms<<<Mrows, 256>>>(hidden, nullptr, pre_norm_w, nullptr, hs);
    // 4. fused xz|q|k|v (2048 x 5632, K=1024)  <-- ncu captures this
    gemm_h<128, OP_NONE, false><<<dim3(FUSN / 128, Mrows / BM), 128, smem128>>>(
        hs, wbig, xzq, nullptr, FUSN, Hc, Hc, Hc);
    // 5. conv + silu
    conv_silu<<<(Mrows * Ic) / 256, 256>>>(conv_w, conv_b);
    // 6. x_proj -> half
    gemm_h<64, OP_HALF, true><<<dim3(2, Mrows / BM), 128, smem64>>>(
        xsh, wxp, proj_h, nullptr, PROJW, Ic, Ic, Ic);
    // 7. dt GEMM with fused bias+softplus
    gemm_h<128, OP_SPLUS, false><<<dim3(Ic / 128, Mrows / BM), 128, smem128>>>(
        proj_h, wdt, dt, dt_proj_b, Ic, Rc, PROJW, Rc);
    // 8. selective scan (staged)
    scan2<<<(Bc * Ic) / 16, 256>>>(A_log, Dp);
    // 9. out_proj; residual + norm
    gemm_h<64, OP_NONE, false><<<dim3(Hc / 64, Mrows / BM), 128, smem64>>>(
        y, wop, tmp, nullptr, Hc, Ic, Ic, Ic);
    resid_rms<<<Mrows, 256>>>(tmp, hidden, ssm_norm_w, ssmres, ssmst);
    // 10. kv_ssm
    gemm_h<64, OP_NONE, false><<<dim3(KVSLD / 64, Mrows / BM), 128, smem64>>>(
        ssmst, wkv, kvssm, nullptr, KVSLD, Hc, Hc, Hc);
    // 11. rotary -> compact half; v copies
    rotary_half<<<(Mrows * NHc * 32) / 256, 256>>>(xzq, FUSN, 4096, qh, NHc);
    rotary_half<<<(Mrows * NKVc * 32) / 256, 256>>>(xzq, FUSN, 5120, kah, NKVc);
    rotary_half<<<(Mrows * NKVc * 32) / 256, 256>>>(kvssm, KVSLD, 0, ksh, NKVc);
    copy_vh<<<(Mrows * 512) / 256, 256>>>();
    // 12. attention (MMA)
    attn4<<<dim3(Sc / 64, NHc, Bc), 128>>>();
    // 13. o proj; residual + norm
    gemm_h<64, OP_NONE, false><<<dim3(Hc / 64, Mrows / BM), 128, smem64>>>(
        oh, wo, tmp, nullptr, Hc, NHc * HDc, NHc * HDc, NHc * HDc);
    resid_rms<<<Mrows, 256>>>(tmp, ssmres, mlp_norm_w, mlpres, x2);
    // 14. MLP
    gemm_h<128, OP_SWIGLU, false><<<dim3(GATEN / 128, Mrows / BM), 128, smem128>>>(
        x2, wg, hm, nullptr, GATEN, Hc, Hc, Hc);
    gemm_h<64, OP_ADDC, false><<<dim3(Hc / 64, Mrows / BM), 128, smem64>>>(
        hm, wd, out, mlpres, Hc, IMc, IMc, IMc);
}

// round 13
// speedup vs baseline: 3.1344x; 1.0039x over previous
#include <cuda_runtime.h>
#include <cuda_fp16.h>
#include <math.h>
#include <stdint.h>

// ---------------- problem constants ----------------
#define Bc   2
#define Sc   1024
#define Hc   1024
#define Ic   2048
#define Nst  16
#define Rc   64
#define Kcv  4
#define NHc  16
#define NKVc 4
#define HDc  64
#define WATT 512
#define WSSM 128
#define IMc  2816
#define Mrows (Bc*Sc)
#define EPSc  1e-6f
#define PROJW (Rc + 2*Nst)   // 96
#define FUSN  5632
#define KVSLD 512
#define GATEN 5632

// ---------------- scratch ----------------
__device__ __half g_hs[Mrows*Hc];
__device__ float  g_xzq[Mrows*FUSN];
__device__ float  g_xs[Mrows*Ic];
__device__ __half g_xsh[Mrows*Ic];
__device__ __half g_proj_h[Mrows*PROJW];
__device__ float  g_dt[Mrows*Ic];
__device__ __half g_y[Mrows*Ic];
__device__ float  g_tmp[Mrows*Hc];
__device__ float  g_ssmres[Mrows*Hc];
__device__ __half g_ssmst[Mrows*Hc];
__device__ float  g_kvssm[Mrows*KVSLD];
__device__ __half g_oh[Mrows*NHc*HDc];
__device__ float  g_mlpres[Mrows*Hc];
__device__ __half g_x2[Mrows*Hc];
__device__ __half g_hm[Mrows*IMc];
// compact half attention operands
__device__ __half g_qh[Mrows*NHc*HDc];
__device__ __half g_kah[Mrows*NKVc*HDc];
__device__ __half g_ksh[Mrows*NKVc*HDc];
__device__ __half g_vah[Mrows*NKVc*HDc];
__device__ __half g_vsh[Mrows*NKVc*HDc];
// half weights
__device__ __half g_wbig[FUSN*Hc];
__device__ __half g_wxp[PROJW*Ic];
__device__ __half g_wdt[Ic*Rc];
__device__ __half g_wop[Hc*Ic];
__device__ __half g_wkv[KVSLD*Hc];
__device__ __half g_wo[Hc*NHc*HDc];
__device__ __half g_wg[GATEN*Hc];
__device__ __half g_wd[Hc*IMc];

__device__ __forceinline__ float fsig(float x) { return 1.f / (1.f + __expf(-x)); }

// ---------------- fp16 MMA primitives ----------------
#define BM 128
#define BK 32
#define PADH 40
#define STAGES 4

#define OP_NONE   0
#define OP_HALF   1
#define OP_SPLUS  2
#define OP_SWIGLU 3
#define OP_ADDC   4

__device__ __forceinline__ void cp16(uint32_t dst, const void* src, int ssize) {
    asm volatile("cp.async.cg.shared.global [%0], [%1], 16, %2;\n"
                 :: "r"(dst), "l"(src), "r"(ssize));
}
__device__ __forceinline__ void mma_f16(float* c, const uint32_t* a, uint32_t b0, uint32_t b1) {
    asm volatile("mma.sync.aligned.m16n8k16.row.col.f32.f16.f16.f32 "
                 "{%0,%1,%2,%3}, {%4,%5,%6,%7}, {%8,%9}, {%0,%1,%2,%3};\n"
                 : "+f"(c[0]), "+f"(c[1]), "+f"(c[2]), "+f"(c[3])
                 : "r"(a[0]), "r"(a[1]), "r"(a[2]), "r"(a[3]), "r"(b0), "r"(b1));
}

// warp tile 64x32; BNT=128 -> 256 thr (2x4 warps), BNT=64 -> 128 thr (2x2 warps)
template<int BNT, int OP, bool NG>
__global__ __launch_bounds__(BNT * 2, 2)
void gemm_h(const __half* __restrict__ A, const __half* __restrict__ Bw,
            void* __restrict__ Cv, const float* __restrict__ aux,
            int Ndim, int Kdim, int lda, int ldb) {
    constexpr int NT  = BNT * 2;
    constexpr int ASZ = BM * PADH;
    constexpr int BSZ = BNT * PADH;
    constexpr int STG = ASZ + BSZ;
    constexpr int AITER = 512 / NT;          // A chunk loads per thread
    constexpr int BITER = (BNT * 4) / NT;    // B chunk loads per thread (=2)
    extern __shared__ __half smh[];
    const int t    = threadIdx.x;
    const int bm   = blockIdx.y * BM;
    const int bn   = blockIdx.x * BNT;
    const int warp = t >> 5, lane = t & 31;
    const int wm   = (warp & 1) * 64;
    const int wn   = (warp >> 1) * 32;
    const int gid  = lane >> 2;
    const int tig  = lane & 3;
    const uint32_t smem_base = (uint32_t)__cvta_generic_to_shared(smh);

    float acc[4][4][4];
#pragma unroll
    for (int mi = 0; mi < 4; mi++)
#pragma unroll
        for (int nj = 0; nj < 4; nj++)
#pragma unroll
            for (int j = 0; j < 4; j++) acc[mi][nj][j] = 0.f;

    const int niters = Kdim / BK;

    auto load_tile = [&](int slot, int k0) {
        uint32_t aOff = smem_base + slot * STG * 2;
        uint32_t bOff = aOff + ASZ * 2;
#pragma unroll
        for (int i = 0; i < AITER; i++) {
            int id = t + i * NT;
            int r  = id >> 2;
            int kq = (id & 3) * 8;
            cp16(aOff + (r * PADH + kq) * 2, A + (size_t)(bm + r) * lda + k0 + kq, 16);
        }
#pragma unroll
        for (int i = 0; i < BITER; i++) {
            int id = t + i * NT;
            int r  = id >> 2;
            int kq = (id & 3) * 8;
            int ok = 1;
            int br = bn + r;
            if (NG) ok = (br < Ndim);
            cp16(bOff + (r * PADH + kq) * 2,
                 Bw + (size_t)(NG ? (ok ? br : 0) : br) * ldb + k0 + kq, ok ? 16 : 0);
        }
    };

#pragma unroll
    for (int s = 0; s < STAGES - 1; s++) {
        if (s < niters) load_tile(s, s * BK);
        asm volatile("cp.async.commit_group;\n");
    }

    int cslot = 0, nslot = STAGES - 1;
    for (int it = 0; it < niters; it++) {
        asm volatile("cp.async.wait_group %0;\n" :: "n"(STAGES - 2));
        __syncthreads();
        int nk = it + STAGES - 1;
        if (nk < niters) load_tile(nslot, nk * BK);
        asm volatile("cp.async.commit_group;\n");
        if (++nslot == STAGES) nslot = 0;

        const __half* Ab = smh + cslot * STG;
        const __half* Bb = Ab + ASZ;
        if (++cslot == STAGES) cslot = 0;
#pragma unroll
        for (int kk = 0; kk < 2; kk++) {
            int kb = kk * 16;
            uint32_t afr[4][4];
#pragma unroll
            for (int mi = 0; mi < 4; mi++) {
                const __half* ab = Ab + (wm + mi * 16 + gid) * PADH + kb + tig * 2;
                afr[mi][0] = *(const uint32_t*)(ab);
                afr[mi][1] = *(const uint32_t*)(ab + 8 * PADH);
                afr[mi][2] = *(const uint32_t*)(ab + 8);
                afr[mi][3] = *(const uint32_t*)(ab + 8 * PADH + 8);
            }
#pragma unroll
            for (int nj = 0; nj < 4; nj++) {
                const __half* bb = Bb + (wn + nj * 8 + gid) * PADH + kb + tig * 2;
                uint32_t b0 = *(const uint32_t*)(bb);
                uint32_t b1 = *(const uint32_t*)(bb + 8);
#pragma unroll
                for (int mi = 0; mi < 4; mi++)
                    mma_f16(acc[mi][nj], afr[mi], b0, b1);
            }
        }
    }

    float*  Cf = (float*)Cv;
    __half* Ch = (__half*)Cv;
#pragma unroll
    for (int mi = 0; mi < 4; mi++) {
        int rbase = bm + wm + mi * 16 + gid;
#pragma unroll
        for (int nj = 0; nj < 4; nj++) {
            int c0 = bn + wn + nj * 8 + tig * 2;
            if (NG && c0 >= Ndim) continue;
#pragma unroll
            for (int half_ = 0; half_ < 2; half_++) {
                int r0 = rbase + half_ * 8;
                float a0 = acc[mi][nj][half_ * 2 + 0];
                float a1 = acc[mi][nj][half_ * 2 + 1];
                if (OP == OP_NONE) {
                    *(float2*)(Cf + (size_t)r0 * Ndim + c0) = make_float2(a0, a1);
                } else if (OP == OP_HALF) {
                    *(__half2*)(Ch + (size_t)r0 * Ndim + c0) = __floats2half2_rn(a0, a1);
                } else if (OP == OP_SPLUS) {
                    float x0 = a0 + aux[c0], x1 = a1 + aux[c0 + 1];
                    x0 = (x0 > 20.f) ? x0 : __logf(1.f + __expf(x0));
                    x1 = (x1 > 20.f) ? x1 : __logf(1.f + __expf(x1));
                    *(float2*)(Cf + (size_t)r0 * Ndim + c0) = make_float2(x0, x1);
                } else if (OP == OP_SWIGLU) {
                    float sv = a0 * fsig(a0) * a1;
                    Ch[(size_t)r0 * IMc + (c0 >> 1)] = __float2half_rn(sv);
                } else if (OP == OP_ADDC) {
                    float2 r = *(const float2*)(aux + (size_t)r0 * Ndim + c0);
                    *(float2*)(Cf + (size_t)r0 * Ndim + c0) =
                        make_float2(a0 + r.x, a1 + r.y);
                }
            }
        }
    }
}

// ---------------- weight prep (split: wbig first, rest second) ----------------
#define W0 (FUSN*Hc)
#define R1 (KVSLD*Hc)
#define R2 (R1 + GATEN*Hc)
#define R3 (R2 + PROJW*Ic)
#define R4 (R3 + Ic*Rc)
#define R5 (R4 + Hc*Ic)
#define R6 (R5 + Hc*NHc*HDc)
#define R7 (R6 + Hc*IMc)
__global__ void prep_wbig(const float* __restrict__ ipw, const float* __restrict__ qw,
                          const float* __restrict__ kw, const float* __restrict__ vw) {
    int idx = blockIdx.x * 256 + threadIdx.x;
    if (idx >= W0) return;
    int row = idx >> 10, col = idx & 1023;
    float v;
    if (row < 4096)      v = ipw[idx];
    else if (row < 5120) v = qw[(row - 4096) * Hc + col];
    else if (row < 5376) v = kw[(row - 5120) * Hc + col];
    else                 v = vw[(row - 5376) * Hc + col];
    g_wbig[idx] = __float2half_rn(v);
}
__global__ void prep_rest(const float* __restrict__ kw, const float* __restrict__ vw,
                          const float* __restrict__ gw, const float* __restrict__ xpw,
                          const float* __restrict__ dtw, const float* __restrict__ opw,
                          const float* __restrict__ ow, const float* __restrict__ dw) {
    int idx = blockIdx.x * 256 + threadIdx.x;
    if (idx >= R7) return;
    if (idx < R1) {
        int row = idx >> 10, col = idx & 1023;
        float v = (row < 256) ? kw[row * Hc + col] : vw[(row - 256) * Hc + col];
        g_wkv[idx] = __float2half_rn(v);
    } else if (idx < R2) {
        int i = idx - R1;
        int row = i >> 10, col = i & 1023;
        int f = row >> 1;
        int src = (row & 1) ? (IMc + f) : f;
        g_wg[i] = __float2half_rn(gw[src * Hc + col]);
    } else if (idx < R3) {
        int i = idx - R2; g_wxp[i] = __float2half_rn(xpw[i]);
    } else if (idx < R4) {
        int i = idx - R3; g_wdt[i] = __float2half_rn(dtw[i]);
    } else if (idx < R5) {
        int i = idx - R4; g_wop[i] = __float2half_rn(opw[i]);
    } else if (idx < R6) {
        int i = idx - R5; g_wo[i] = __float2half_rn(ow[i]);
    } else {
        int i = idx - R6; g_wd[i] = __float2half_rn(dw[i]);
    }
}

// ---------------- RMSNorm ----------------
__global__ void resid_rms(const float* __restrict__ a, const float* __restrict__ r,
                          const float* __restrict__ w, float* __restrict__ res_out,
                          __half* __restrict__ nrm_out) {
    int row = blockIdx.x;
    int t   = threadIdx.x;
    const float* ap = a + (size_t)row * Hc;
    const float* rp = r ? r + (size_t)row * Hc : nullptr;
    float v[4];
    float ss = 0.f;
#pragma unroll
    for (int i = 0; i < 4; i++) {
        int c = t + i * 256;
        float x = ap[c] + (rp ? rp[c] : 0.f);
        v[i] = x;
        ss += x * x;
    }
#pragma unroll
    for (int off = 16; off; off >>= 1) ss += __shfl_xor_sync(0xffffffffu, ss, off);
    __shared__ float sred[8];
    __shared__ float sscale;
    if ((t & 31) == 0) sred[t >> 5] = ss;
    __syncthreads();
    if (t == 0) {
        float tot = 0.f;
        for (int i = 0; i < 8; i++) tot += sred[i];
        sscale = rsqrtf(tot * (1.f / Hc) + EPSc);
    }
    __syncthreads();
    float scale = sscale;
    float* ro = res_out ? res_out + (size_t)row * Hc : nullptr;
    __half* no = nrm_out + (size_t)row * Hc;
#pragma unroll
    for (int i = 0; i < 4; i++) {
        int c = t + i * 256;
        if (ro) ro[c] = v[i];
        no[c] = __float2half_rn(v[i] * scale * w[c]);
    }
}

// ---------------- causal depthwise conv (K=4) + SiLU ----------------
__global__ void conv_silu(const float* __restrict__ cw, const float* __restrict__ cb) {
    int idx = blockIdx.x * blockDim.x + threadIdx.x;
    if (idx >= Mrows * Ic) return;
    int row = idx / Ic;
    int i   = idx - row * Ic;
    int b   = row / Sc;
    int s   = row - b * Sc;
    float acc = cb[i];
#pragma unroll
    for (int k = 0; k < Kcv; k++) {
        int sp = s + k - (Kcv - 1);
        if (sp >= 0)
            acc += cw[i * Kcv + k] * g_xzq[(size_t)(b * Sc + sp) * FUSN + i];
    }
    float r = acc * fsig(acc);
    g_xs[idx]  = r;
    g_xsh[idx] = __float2half_rn(r);
}

// ---------------- selective scan v2: cp.async staged, fast exp ----------------
#define SCH 64
__global__ __launch_bounds__(256) void scan2(const float* __restrict__ A_log,
                                             const float* __restrict__ Dp) {
    __shared__ float  sdt[2][SCH][16];
    __shared__ float  sxs[2][SCH][16];
    __shared__ float  szz[2][SCH][16];
    __shared__ __half sbc[2][SCH][32];
    __shared__ __half sy[SCH][16];
    int t  = threadIdx.x;
    int gi0 = blockIdx.x * 16;
    int b   = gi0 / Ic;
    int i0  = gi0 - b * Ic;
    int rowb = b * Sc;
    int c = t >> 4, n = t & 15;
    int i = i0 + c;
    float An = -__expf(A_log[i * Nst + n]);
    float Dv = Dp[i];

    int lrow = t >> 2, lq = t & 3;
    auto load_chunk = [&](int buf, int s0) {
        size_t gr = (size_t)(rowb + s0 + lrow);
        cp16((uint32_t)__cvta_generic_to_shared(&sdt[buf][lrow][lq * 4]),
             g_dt + gr * Ic + i0 + lq * 4, 16);
        cp16((uint32_t)__cvta_generic_to_shared(&sxs[buf][lrow][lq * 4]),
             g_xs + gr * Ic + i0 + lq * 4, 16);
        cp16((uint32_t)__cvta_generic_to_shared(&szz[buf][lrow][lq * 4]),
             g_xzq + gr * FUSN + Ic + i0 + lq * 4, 16);
        cp16((uint32_t)__cvta_generic_to_shared(&sbc[buf][lrow][lq * 8]),
             g_proj_h + gr * PROJW + Rc + lq * 8, 16);
    };

    load_chunk(0, 0);
    asm volatile("cp.async.commit_group;\n");

    float h = 0.f;
    for (int ch = 0; ch < Sc / SCH; ch++) {
        int buf = ch & 1;
        if (ch + 1 < Sc / SCH) {
            load_chunk(buf ^ 1, (ch + 1) * SCH);
            asm volatile("cp.async.commit_group;\n");
            asm volatile("cp.async.wait_group 1;\n");
        } else {
            asm volatile("cp.async.wait_group 0;\n");
        }
        __syncthreads();
#pragma unroll 4
        for (int s = 0; s < SCH; s++) {
            float dtv = sdt[buf][s][c];
            float xsv = sxs[buf][s][c];
            float Bn  = __half2float(sbc[buf][s][n]);
            float Cn  = __half2float(sbc[buf][s][16 + n]);
            h = h * __expf(dtv * An) + dtv * Bn * xsv;
            float v = h * Cn;
            v += __shfl_xor_sync(0xffffffffu, v, 8);
            v += __shfl_xor_sync(0xffffffffu, v, 4);
            v += __shfl_xor_sync(0xffffffffu, v, 2);
            v += __shfl_xor_sync(0xffffffffu, v, 1);
            if (n == 0) {
                float z = szz[buf][s][c];
                sy[s][c] = __float2half_rn((v + Dv * xsv) * (z * fsig(z)));
            }
        }
        __syncthreads();
        if (t < 128) {
            int row = t >> 1, part = (t & 1) * 8;
            *(uint4*)(g_y + (size_t)(rowb + ch * SCH + row) * Ic + i0 + part) =
                *(const uint4*)&sy[row][part];
        }
    }
}

// ---------------- fused postproc: rotary q/k_att/k_ssm + v copies ----------------
// segments (per row): q 512 thr (16h*32), k_att 128, k_ssm 128, v copies 512 (fp32->half)
#define PPW (512 + 128 + 128 + 512)   // 1280 per row
__global__ void postproc() {
    int idx = blockIdx.x * 256 + threadIdx.x;
    if (idx >= Mrows * PPW) return;
    int r   = idx / PPW;
    int rem = idx - r * PPW;
    int s   = r % Sc;
    if (rem < 512) {            // rotary q
        int head = rem >> 5, j = rem & 31;
        float inv = __expf(-((float)(2 * j) / 64.f) * __logf(10000.0f));
        float sn, cs; __sincosf((float)s * inv, &sn, &cs);
        const float* bi = g_xzq + (size_t)r * FUSN + 4096 + head * HDc;
        __half* bo = g_qh + (size_t)r * 1024 + head * HDc;
        float x1 = bi[j], x2 = bi[j + 32];
        bo[j]      = __float2half_rn(x1 * cs - x2 * sn);
        bo[j + 32] = __float2half_rn(x2 * cs + x1 * sn);
    } else if (rem < 640) {     // rotary k_att
        int q = rem - 512;
        int head = q >> 5, j = q & 31;
        float inv = __expf(-((float)(2 * j) / 64.f) * __logf(10000.0f));
        float sn, cs; __sincosf((float)s * inv, &sn, &cs);
        const float* bi = g_xzq + (size_t)r * FUSN + 5120 + head * HDc;
        __half* bo = g_kah + (size_t)r * 256 + head * HDc;
        float x1 = bi[j], x2 = bi[j + 32];
        bo[j]      = __float2half_rn(x1 * cs - x2 * sn);
        bo[j + 32] = __float2half_rn(x2 * cs + x1 * sn);
    } else if (rem < 768) {     // rotary k_ssm
        int q = rem - 640;
        int head = q >> 5, j = q & 31;
        float inv = __expf(-((float)(2 * j) / 64.f) * __logf(10000.0f));
        float sn, cs; __sincosf((float)s * inv, &sn, &cs);
        const float* bi = g_kvssm + (size_t)r * KVSLD + head * HDc;
        __half* bo = g_ksh + (size_t)r * 256 + head * HDc;
        float x1 = bi[j], x2 = bi[j + 32];
        bo[j]      = __float2half_rn(x1 * cs - x2 * sn);
        bo[j + 32] = __float2half_rn(x2 * cs + x1 * sn);
    } else {                    // v copies
        int col = rem - 768;
        if (col < 256)
            g_vah[r * 256 + col] = __float2half_rn(g_xzq[(size_t)r * FUSN + 5376 + col]);
        else
            g_vsh[r * 256 + (col - 256)] =
                __float2half_rn(g_kvssm[(size_t)r * KVSLD + 256 + (col - 256)]);
    }
}

// ---------------- attn4: FA2-style MMA attention ----------------
__global__ __launch_bounds__(128) void attn4() {
    __shared__ __half Kt[64][72];
    __shared__ __half Vt[64][72];
    int t = threadIdx.x, w = t >> 5, lane = t & 31;
    int g = lane >> 2, tig = lane & 3;
    int q0 = blockIdx.x * 64, h = blockIdx.y, b = blockIdx.z;
    int rowb = b * Sc, hk = h >> 2;
    int qr0 = q0 + w * 16 + g;
    int qr1 = qr0 + 8;

    uint32_t qf[4][4];
    {
        const __half* qb = g_qh + (size_t)rowb * 1024 + h * HDc;
#pragma unroll
        for (int kk = 0; kk < 4; kk++) {
            const __half* r0 = qb + (size_t)qr0 * 1024 + kk * 16 + tig * 2;
            const __half* r1 = qb + (size_t)qr1 * 1024 + kk * 16 + tig * 2;
            qf[kk][0] = *(const uint32_t*)(r0);
            qf[kk][1] = *(const uint32_t*)(r1);
            qf[kk][2] = *(const uint32_t*)(r0 + 8);
            qf[kk][3] = *(const uint32_t*)(r1 + 8);
        }
    }

    float O[8][4];
#pragma unroll
    for (int nt = 0; nt < 8; nt++)
#pragma unroll
        for (int e = 0; e < 4; e++) O[nt][e] = 0.f;
    float m0 = -1e30f, m1 = -1e30f, l0 = 0.f, l1 = 0.f;

    for (int pass = 0; pass < 2; pass++) {
        const __half* kb = pass ? g_ksh : g_kah;
        const __half* vb = pass ? g_vsh : g_vah;
        int W  = pass ? WSSM : WATT;
        int cs = max(0, q0 - (W - 1)) & ~63;
        for (int c = q0; c >= cs; c -= 64) {
            __syncthreads();
#pragma unroll
            for (int i = 0; i < 4; i++) {
                int id = t + i * 128;
                int r  = id >> 3;
                int c8 = (id & 7) * 8;
                size_t src = (size_t)(rowb + c + r) * 256 + hk * HDc + c8;
                *(uint4*)&Kt[r][c8] = *(const uint4*)(kb + src);
                uint4 vv = *(const uint4*)(vb + src);
                const __half* hv = (const __half*)&vv;
#pragma unroll
                for (int j = 0; j < 8; j++) Vt[c8 + j][r] = hv[j];
            }
            __syncthreads();

            float S[8][4];
#pragma unroll
            for (int nt = 0; nt < 8; nt++)
#pragma unroll
                for (int e = 0; e < 4; e++) S[nt][e] = 0.f;
#pragma unroll
            for (int kk = 0; kk < 4; kk++)
#pragma unroll
                for (int nt = 0; nt < 8; nt++) {
                    const __half* kp = &Kt[nt * 8 + g][kk * 16 + tig * 2];
                    uint32_t b0 = *(const uint32_t*)kp;
                    uint32_t b1 = *(const uint32_t*)(kp + 8);
                    mma_f16(S[nt], qf[kk], b0, b1);
                }

            float mt0 = -1e30f, mt1 = -1e30f;
#pragma unroll
            for (int nt = 0; nt < 8; nt++) {
                int key = c + nt * 8 + tig * 2;
                float s0 = (key     <= qr0 && key     > qr0 - W) ? S[nt][0] * 0.125f : -1e30f;
                float s1 = (key + 1 <= qr0 && key + 1 > qr0 - W) ? S[nt][1] * 0.125f : -1e30f;
                float s2 = (key     <= qr1 && key     > qr1 - W) ? S[nt][2] * 0.125f : -1e30f;
                float s3 = (key + 1 <= qr1 && key + 1 > qr1 - W) ? S[nt][3] * 0.125f : -1e30f;
                S[nt][0] = s0; S[nt][1] = s1; S[nt][2] = s2; S[nt][3] = s3;
                mt0 = fmaxf(mt0, fmaxf(s0, s1));
                mt1 = fmaxf(mt1, fmaxf(s2, s3));
            }
            mt0 = fmaxf(mt0, __shfl_xor_sync(0xffffffffu, mt0, 1));
            mt0 = fmaxf(mt0, __shfl_xor_sync(0xffffffffu, mt0, 2));
            mt1 = fmaxf(mt1, __shfl_xor_sync(0xffffffffu, mt1, 1));
            mt1 = fmaxf(mt1, __shfl_xor_sync(0xffffffffu, mt1, 2));

            float nm0 = fmaxf(m0, mt0), nm1 = fmaxf(m1, mt1);
            float cr0 = __expf(m0 - nm0), cr1 = __expf(m1 - nm1);
            m0 = nm0; m1 = nm1;

            float ps0 = 0.f, ps1 = 0.f;
#pragma unroll
            for (int nt = 0; nt < 8; nt++) {
                S[nt][0] = __expf(S[nt][0] - nm0);
                S[nt][1] = __expf(S[nt][1] - nm0);
                S[nt][2] = __expf(S[nt][2] - nm1);
                S[nt][3] = __expf(S[nt][3] - nm1);
                ps0 += S[nt][0] + S[nt][1];
                ps1 += S[nt][2] + S[nt][3];
            }
            ps0 += __shfl_xor_sync(0xffffffffu, ps0, 1);
            ps0 += __shfl_xor_sync(0xffffffffu, ps0, 2);
            ps1 += __shfl_xor_sync(0xffffffffu, ps1, 1);
            ps1 += __shfl_xor_sync(0xffffffffu, ps1, 2);
            l0 = l0 * cr0 + ps0;
            l1 = l1 * cr1 + ps1;

#pragma unroll
            for (int nt = 0; nt < 8; nt++) {
                O[nt][0] *= cr0; O[nt][1] *= cr0;
                O[nt][2] *= cr1; O[nt][3] *= cr1;
            }

#pragma unroll
            for (int kk = 0; kk < 4; kk++) {
                uint32_t pf[4];
                __half2 h0 = __floats2half2_rn(S[2 * kk][0],     S[2 * kk][1]);
                __half2 h1 = __floats2half2_rn(S[2 * kk][2],     S[2 * kk][3]);
                __half2 h2 = __floats2half2_rn(S[2 * kk + 1][0], S[2 * kk + 1][1]);
                __half2 h3 = __floats2half2_rn(S[2 * kk + 1][2], S[2 * kk + 1][3]);
                pf[0] = *(uint32_t*)&h0; pf[1] = *(uint32_t*)&h1;
                pf[2] = *(uint32_t*)&h2; pf[3] = *(uint32_t*)&h3;
#pragma unroll
                for (int nt = 0; nt < 8; nt++) {
                    const __half* vp = &Vt[nt * 8 + g][kk * 16 + tig * 2];
                    uint32_t b0 = *(const uint32_t*)vp;
                    uint32_t b1 = *(const uint32_t*)(vp + 8);
                    mma_f16(O[nt], pf, b0, b1);
                }
            }
        }
    }

    float i0 = 1.f / l0, i1 = 1.f / l1;
    __half* ob = g_oh + (size_t)rowb * 1024 + h * HDc;
#pragma unroll
    for (int nt = 0; nt < 8; nt++) {
        *(__half2*)(ob + (size_t)qr0 * 1024 + nt * 8 + tig * 2) =
            __floats2half2_rn(O[nt][0] * i0, O[nt][1] * i0);
        *(__half2*)(ob + (size_t)qr1 * 1024 + nt * 8 + tig * 2) =
            __floats2half2_rn(O[nt][2] * i1, O[nt][3] * i1);
    }
}

// ---------------- host launcher ----------------
extern "C" void kernel_launch(void* const* d_in, const int* in_sizes, int n_in,
                              void* d_out, int out_size) {
    const float* hidden      = (const float*)d_in[0];
    const float* pre_norm_w  = (const float*)d_in[1];
    const float* in_proj_w   = (const float*)d_in[2];
    const float* conv_w      = (const float*)d_in[3];
    const float* conv_b      = (const float*)d_in[4];
    const float* x_proj_w    = (const float*)d_in[5];
    const float* dt_proj_w   = (const float*)d_in[6];
    const float* dt_proj_b   = (const float*)d_in[7];
    const float* A_log       = (const float*)d_in[8];
    const float* Dp          = (const float*)d_in[9];
    const float* out_proj_w  = (const float*)d_in[10];
    const float* ssm_norm_w  = (const float*)d_in[11];
    const float* q_w         = (const float*)d_in[12];
    const float* k_w         = (const float*)d_in[13];
    const float* v_w         = (const float*)d_in[14];
    const float* o_w         = (const float*)d_in[15];
    const float* mlp_norm_w  = (const float*)d_in[16];
    const float* gate_w      = (const float*)d_in[17];
    const float* down_w      = (const float*)d_in[18];
    float* out = (float*)d_out;

    const int smem128 = (BM * PADH + 128 * PADH) * STAGES * 2;
    const int smem64  = (BM * PADH + 64 * PADH) * STAGES * 2;
    cudaFuncSetAttribute(gemm_h<128, OP_NONE,  false>, cudaFuncAttributeMaxDynamicSharedMemorySize, smem128);
    cudaFuncSetAttribute(gemm_h<128, OP_SPLUS, false>, cudaFuncAttributeMaxDynamicSharedMemorySize, smem128);
    cudaFuncSetAttribute(gemm_h<128, OP_SWIGLU,false>, cudaFuncAttributeMaxDynamicSharedMemorySize, smem128);
    cudaFuncSetAttribute(gemm_h<64,  OP_HALF,  true >, cudaFuncAttributeMaxDynamicSharedMemorySize, smem64);
    cudaFuncSetAttribute(gemm_h<64,  OP_NONE,  false>, cudaFuncAttributeMaxDynamicSharedMemorySize, smem64);
    cudaFuncSetAttribute(gemm_h<64,  OP_ADDC,  false>, cudaFuncAttributeMaxDynamicSharedMemorySize, smem64);

    __half *hs, *xsh, *proj_h, *y, *ssmst, *oh, *x2, *hm;
    __half *wbig, *wxp, *wdt, *wop, *wkv, *wo, *wg, *wd;
    float *xzq, *xs, *dt, *tmp, *ssmres, *kvssm, *mlpres;
    cudaGetSymbolAddress((void**)&hs, g_hs);
    cudaGetSymbolAddress((void**)&xzq, g_xzq);
    cudaGetSymbolAddress((void**)&xs, g_xs);
    cudaGetSymbolAddress((void**)&xsh, g_xsh);
    cudaGetSymbolAddress((void**)&proj_h, g_proj_h);
    cudaGetSymbolAddress((void**)&dt, g_dt);
    cudaGetSymbolAddress((void**)&y, g_y);
    cudaGetSymbolAddress((void**)&tmp, g_tmp);
    cudaGetSymbolAddress((void**)&ssmres, g_ssmres);
    cudaGetSymbolAddress((void**)&ssmst, g_ssmst);
    cudaGetSymbolAddress((void**)&kvssm, g_kvssm);
    cudaGetSymbolAddress((void**)&oh, g_oh);
    cudaGetSymbolAddress((void**)&mlpres, g_mlpres);
    cudaGetSymbolAddress((void**)&x2, g_x2);
    cudaGetSymbolAddress((void**)&hm, g_hm);
    cudaGetSymbolAddress((void**)&wbig, g_wbig);
    cudaGetSymbolAddress((void**)&wxp, g_wxp);
    cudaGetSymbolAddress((void**)&wdt, g_wdt);
    cudaGetSymbolAddress((void**)&wop, g_wop);
    cudaGetSymbolAddress((void**)&wkv, g_wkv);
    cudaGetSymbolAddress((void**)&wo, g_wo);
    cudaGetSymbolAddress((void**)&wg, g_wg);
    cudaGetSymbolAddress((void**)&wd, g_wd);

    // 1-2. weight prep
    prep_wbig<<<(W0 + 255) / 256, 256>>>(in_proj_w, q_w, k_w, v_w);
    prep_rest<<<(R7 + 255) / 256, 256>>>(k_w, v_w, gate_w, x_proj_w, dt_proj_w,
                                         out_proj_w, o_w, down_w);
    // 3. pre-norm
    resid_rms<<<Mrows, 256>>>(hidden, nullptr, pre_norm_w, nullptr, hs);
    // 4. fused xz|q|k|v (2048 x 5632, K=1024)  <-- ncu captures this
    gemm_h<128, OP_NONE, false><<<dim3(FUSN / 128, Mrows / BM), 256, smem128>>>(
        hs, wbig, xzq, nullptr, FUSN, Hc, Hc, Hc);
    // 5. conv + silu
    conv_silu<<<(Mrows * Ic) / 256, 256>>>(conv_w, conv_b);
    // 6. x_proj -> half
    gemm_h<64, OP_HALF, true><<<dim3(2, Mrows / BM), 128, smem64>>>(
        xsh, wxp, proj_h, nullptr, PROJW, Ic, Ic, Ic);
    // 7. dt GEMM with fused bias+softplus
    gemm_h<128, OP_SPLUS, false><<<dim3(Ic / 128, Mrows / BM), 256, smem128>>>(
        proj_h, wdt, dt, dt_proj_b, Ic, Rc, PROJW, Rc);
    // 8. selective scan (staged)
    scan2<<<(Bc * Ic) / 16, 256>>>(A_log, Dp);
    // 9. out_proj; residual + norm
    gemm_h<64, OP_NONE, false><<<dim3(Hc / 64, Mrows / BM), 128, smem64>>>(
        y, wop, tmp, nullptr, Hc, Ic, Ic, Ic);
    resid_rms<<<Mrows, 256>>>(tmp, hidden, ssm_norm_w, ssmres, ssmst);
    // 10. kv_ssm
    gemm_h<64, OP_NONE, false><<<dim3(KVSLD / 64, Mrows / BM), 128, smem64>>>(
        ssmst, wkv, kvssm, nullptr, KVSLD, Hc, Hc, Hc);
    // 11. fused rotary + v copies
    postproc<<<(Mrows * PPW + 255) / 256, 256>>>();
    // 12. attention (MMA)
    attn4<<<dim3(Sc / 64, NHc, Bc), 128>>>();
    // 13. o proj; residual + norm
    gemm_h<64, OP_NONE, false><<<dim3(Hc / 64, Mrows / BM), 128, smem64>>>(
        oh, wo, tmp, nullptr, Hc, NHc * HDc, NHc * HDc, NHc * HDc);
    resid_rms<<<Mrows, 256>>>(tmp, ssmres, mlp_norm_w, mlpres, x2);
    // 14. MLP
    gemm_h<128, OP_SWIGLU, false><<<dim3(GATEN / 128, Mrows / BM), 256, smem128>>>(
        x2, wg, hm, nullptr, GATEN, Hc, Hc, Hc);
    gemm_h<64, OP_ADDC, false><<<dim3(Hc / 64, Mrows / BM), 128, smem64>>>(
        hm, wd, out, mlpres, Hc, IMc, IMc, IMc);
}